// round 1
// baseline (speedup 1.0000x reference)
#include <cuda_runtime.h>
#include <math.h>
#include <stdint.h>

#define NA_N 100000
#define NP_N 100000
#define E_N  400000
#define D_   256
#define H_   8
#define DK_  32

// ---------------- static scratch (module-load allocated; no runtime alloc) ----------------
static __device__ float g_QA[(size_t)NA_N * D_];
static __device__ float g_KA[(size_t)NA_N * D_];
static __device__ float g_VA[(size_t)NA_N * D_];
static __device__ float g_QP[(size_t)NP_N * D_];
static __device__ float g_KP[(size_t)NP_N * D_];
static __device__ float g_VP[(size_t)NP_N * D_];
static __device__ float g_KE[(size_t)NP_N * D_];   // reused per etype; later: author fc tmp
static __device__ float g_VE[(size_t)NP_N * D_];   // reused per etype; later: paper fc tmp
static __device__ float g_AGA[(size_t)NA_N * D_];
static __device__ float g_AGP[(size_t)NP_N * D_];
static __device__ int   g_cnt[NP_N + 1];
static __device__ int   g_off[NP_N + 1];
static __device__ int   g_cur[NP_N];
static __device__ int   g_psrc[E_N];

// ---------------- SGEMM: C[M,256] = scaleA*A[M,256] @ W[256,256] + bias, optional fc-blend epilogue ----------------
// MODE 0: C = scaleA*acc + bias
// MODE 1: C = (scaleA*acc + bias)*sigmoid(res) + Hin*(1-sigmoid(res))
template <int MODE>
__global__ __launch_bounds__(256) void sgemm_k(
    const float* __restrict__ A, const float* __restrict__ W,
    const float* __restrict__ bias, const float* __restrict__ Hin,
    const float* __restrict__ resv, float* __restrict__ C,
    int M, float scaleA)
{
    __shared__ float As[8 * 132];   // [k][row], padded stride 132
    __shared__ float Bs[8 * 128];   // [k][col]

    const int tid = threadIdx.x;
    const int bm = blockIdx.y * 128;
    const int bn = blockIdx.x * 128;

    const int ty = tid >> 4;          // 0..15
    const int tx = tid & 15;          // 0..15

    const int arow = tid >> 1;        // 0..127
    const int acolg = (tid & 1) * 4;  // 0 or 4
    const int brow = tid >> 5;        // 0..7
    const int bcol = (tid & 31) * 4;  // 0..124

    float acc[8][8];
#pragma unroll
    for (int i = 0; i < 8; i++)
#pragma unroll
        for (int j = 0; j < 8; j++) acc[i][j] = 0.f;

    for (int k0 = 0; k0 < 256; k0 += 8) {
        // load A tile (guarded) and transpose into smem
        float4 av = make_float4(0.f, 0.f, 0.f, 0.f);
        int grow = bm + arow;
        if (grow < M) av = *(const float4*)&A[(size_t)grow * 256 + k0 + acolg];
        As[(acolg + 0) * 132 + arow] = av.x;
        As[(acolg + 1) * 132 + arow] = av.y;
        As[(acolg + 2) * 132 + arow] = av.z;
        As[(acolg + 3) * 132 + arow] = av.w;
        // load W tile
        *(float4*)&Bs[brow * 128 + bcol] = *(const float4*)&W[(size_t)(k0 + brow) * 256 + bn + bcol];
        __syncthreads();

#pragma unroll
        for (int kk = 0; kk < 8; kk++) {
            float4 a0 = *(const float4*)&As[kk * 132 + ty * 4];
            float4 a1 = *(const float4*)&As[kk * 132 + 64 + ty * 4];
            float4 b0 = *(const float4*)&Bs[kk * 128 + tx * 4];
            float4 b1 = *(const float4*)&Bs[kk * 128 + 64 + tx * 4];
            float avr[8] = {a0.x, a0.y, a0.z, a0.w, a1.x, a1.y, a1.z, a1.w};
            float bvr[8] = {b0.x, b0.y, b0.z, b0.w, b1.x, b1.y, b1.z, b1.w};
#pragma unroll
            for (int i = 0; i < 8; i++)
#pragma unroll
                for (int j = 0; j < 8; j++) acc[i][j] += avr[i] * bvr[j];
        }
        __syncthreads();
    }

    float alpha = 1.f, beta = 0.f;
    if (MODE == 1) {
        float rv = __ldg(resv);
        alpha = 1.f / (1.f + __expf(-rv));
        beta = 1.f - alpha;
    }

#pragma unroll
    for (int ii = 0; ii < 8; ii++) {
        int row = bm + ((ii < 4) ? (ty * 4 + ii) : (64 + ty * 4 + ii - 4));
        if (row >= M) continue;
#pragma unroll
        for (int jj = 0; jj < 2; jj++) {
            int col = bn + ((jj == 0) ? (tx * 4) : (64 + tx * 4));
            float4 bb = *(const float4*)&bias[col];
            float4 r;
            r.x = acc[ii][jj * 4 + 0] * scaleA + bb.x;
            r.y = acc[ii][jj * 4 + 1] * scaleA + bb.y;
            r.z = acc[ii][jj * 4 + 2] * scaleA + bb.z;
            r.w = acc[ii][jj * 4 + 3] * scaleA + bb.w;
            if (MODE == 1) {
                float4 hv = *(const float4*)&Hin[(size_t)row * 256 + col];
                r.x = r.x * alpha + hv.x * beta;
                r.y = r.y * alpha + hv.y * beta;
                r.z = r.z * alpha + hv.z * beta;
                r.w = r.w * alpha + hv.w * beta;
            }
            *(float4*)&C[(size_t)row * 256 + col] = r;
        }
    }
}

// ---------------- per-head DK x DK transform: Y[n,h,:] = X[n,h,:] @ Wh[h] ----------------
__global__ __launch_bounds__(256) void head_transform_k(
    const float* __restrict__ X, const float* __restrict__ Wh,
    float* __restrict__ Y, int N)
{
    int gw = (blockIdx.x * blockDim.x + threadIdx.x) >> 5;
    if (gw >= N) return;
    int lane = threadIdx.x & 31;
    size_t rb = (size_t)gw * 256;
#pragma unroll
    for (int h = 0; h < 8; h++) {
        float xv = X[rb + h * 32 + lane];
        float acc = 0.f;
#pragma unroll
        for (int d = 0; d < 32; d++) {
            acc += __shfl_sync(0xffffffffu, xv, d) * __ldg(&Wh[(h * 32 + d) * 32 + lane]);
        }
        Y[rb + h * 32 + lane] = acc;
    }
}

// ---------------- CSR build ----------------
__global__ void zero_k(int* __restrict__ p, int n)
{
    for (int i = blockIdx.x * blockDim.x + threadIdx.x; i < n; i += gridDim.x * blockDim.x) p[i] = 0;
}

__global__ void hist_k(const int* __restrict__ dst, int ne, int* __restrict__ cnt)
{
    int i = blockIdx.x * blockDim.x + threadIdx.x;
    if (i < ne) atomicAdd(&cnt[dst[i]], 1);
}

__global__ __launch_bounds__(1024) void scan_k(
    const int* __restrict__ cnt, int n, int* __restrict__ off, int* __restrict__ cur)
{
    __shared__ int sh[1024];
    int t = threadIdx.x;
    int chunk = (n + 1023) >> 10;
    int s0 = t * chunk;
    int s1 = min(s0 + chunk, n);
    int sum = 0;
    for (int i = s0; i < s1; i++) sum += cnt[i];
    sh[t] = sum;
    __syncthreads();
    for (int d = 1; d < 1024; d <<= 1) {
        int v = 0;
        if (t >= d) v = sh[t - d];
        __syncthreads();
        sh[t] += v;
        __syncthreads();
    }
    int run = sh[t] - sum;  // exclusive prefix
    for (int i = s0; i < s1; i++) {
        off[i] = run;
        cur[i] = run;
        run += cnt[i];
    }
    if (t == 1023) off[n] = sh[1023];
}

__global__ void scatter_k(const int* __restrict__ src, const int* __restrict__ dst,
                          int ne, int* __restrict__ cur, int* __restrict__ psrc)
{
    int i = blockIdx.x * blockDim.x + threadIdx.x;
    if (i < ne) {
        int p = atomicAdd(&cur[dst[i]], 1);
        psrc[p] = src[i];
    }
}

// ---------------- warp-per-destination online-softmax aggregation ----------------
// lane layout: head h = lane>>2, 8-dim segment seg = (lane&3)*8
template <int ACCUM>
__global__ __launch_bounds__(256) void agg_k(
    const float* __restrict__ Q, const float* __restrict__ KE, const float* __restrict__ VE,
    const int* __restrict__ off, const int* __restrict__ psrc,
    const float* __restrict__ canon, float* __restrict__ OUT, int n_dst)
{
    int gw = (blockIdx.x * blockDim.x + threadIdx.x) >> 5;
    if (gw >= n_dst) return;
    int lane = threadIdx.x & 31;
    int h = lane >> 2;
    int seg = (lane & 3) << 3;
    size_t base = (size_t)gw * 256 + h * 32 + seg;

    float4 q0 = *(const float4*)(Q + base);
    float4 q1 = *(const float4*)(Q + base + 4);
    float cw = __ldg(&canon[h]) * 0.17677669529663687f;  // 1/sqrt(32)

    int ebeg = __ldg(&off[gw]);
    int eend = __ldg(&off[gw + 1]);

    float m = -3.0e38f, den = 0.f;
    float a0 = 0, a1 = 0, a2 = 0, a3 = 0, a4 = 0, a5 = 0, a6 = 0, a7 = 0;

    for (int i = ebeg; i < eend; i++) {
        int src = __ldg(&psrc[i]);
        size_t sb = (size_t)src * 256 + h * 32 + seg;
        float4 k0 = *(const float4*)(KE + sb);
        float4 k1 = *(const float4*)(KE + sb + 4);
        float4 v0 = *(const float4*)(VE + sb);
        float4 v1 = *(const float4*)(VE + sb + 4);
        float p = q0.x * k0.x + q0.y * k0.y + q0.z * k0.z + q0.w * k0.w +
                  q1.x * k1.x + q1.y * k1.y + q1.z * k1.z + q1.w * k1.w;
        p += __shfl_xor_sync(0xffffffffu, p, 1);
        p += __shfl_xor_sync(0xffffffffu, p, 2);
        float sc = p * cw;
        float mn = fmaxf(m, sc);
        float corr = __expf(m - mn);
        float w = __expf(sc - mn);
        m = mn;
        den = den * corr + w;
        a0 = a0 * corr + w * v0.x;
        a1 = a1 * corr + w * v0.y;
        a2 = a2 * corr + w * v0.z;
        a3 = a3 * corr + w * v0.w;
        a4 = a4 * corr + w * v1.x;
        a5 = a5 * corr + w * v1.y;
        a6 = a6 * corr + w * v1.z;
        a7 = a7 * corr + w * v1.w;
    }

    float r = (den > 0.f) ? (1.f / den) : 0.f;
    float o0 = a0 * r, o1 = a1 * r, o2 = a2 * r, o3 = a3 * r;
    float o4 = a4 * r, o5 = a5 * r, o6 = a6 * r, o7 = a7 * r;
    if (ACCUM) {
        float4 p0 = *(const float4*)(OUT + base);
        float4 p1 = *(const float4*)(OUT + base + 4);
        o0 += p0.x; o1 += p0.y; o2 += p0.z; o3 += p0.w;
        o4 += p1.x; o5 += p1.y; o6 += p1.z; o7 += p1.w;
    }
    *(float4*)(OUT + base) = make_float4(o0, o1, o2, o3);
    *(float4*)(OUT + base + 4) = make_float4(o4, o5, o6, o7);
}

// ---------------- layernorm (warp per row) ----------------
__global__ __launch_bounds__(256) void ln_k(
    const float* __restrict__ HP, const float* __restrict__ g, const float* __restrict__ b,
    float* __restrict__ out, int N)
{
    int gw = (blockIdx.x * blockDim.x + threadIdx.x) >> 5;
    if (gw >= N) return;
    int lane = threadIdx.x & 31;
    size_t base = (size_t)gw * 256 + lane * 8;
    float4 v0 = *(const float4*)&HP[base];
    float4 v1 = *(const float4*)&HP[base + 4];
    float s = v0.x + v0.y + v0.z + v0.w + v1.x + v1.y + v1.z + v1.w;
#pragma unroll
    for (int d = 16; d; d >>= 1) s += __shfl_xor_sync(0xffffffffu, s, d);
    float mu = s * (1.f / 256.f);
    float q = (v0.x - mu) * (v0.x - mu) + (v0.y - mu) * (v0.y - mu) +
              (v0.z - mu) * (v0.z - mu) + (v0.w - mu) * (v0.w - mu) +
              (v1.x - mu) * (v1.x - mu) + (v1.y - mu) * (v1.y - mu) +
              (v1.z - mu) * (v1.z - mu) + (v1.w - mu) * (v1.w - mu);
#pragma unroll
    for (int d = 16; d; d >>= 1) q += __shfl_xor_sync(0xffffffffu, q, d);
    float inv = rsqrtf(q * (1.f / 256.f) + 1e-5f);
    int col = lane * 8;
    float4 g0 = *(const float4*)&g[col];
    float4 g1 = *(const float4*)&g[col + 4];
    float4 b0 = *(const float4*)&b[col];
    float4 b1 = *(const float4*)&b[col + 4];
    float4 r0, r1;
    r0.x = (v0.x - mu) * inv * g0.x + b0.x;
    r0.y = (v0.y - mu) * inv * g0.y + b0.y;
    r0.z = (v0.z - mu) * inv * g0.z + b0.z;
    r0.w = (v0.w - mu) * inv * g0.w + b0.w;
    r1.x = (v1.x - mu) * inv * g1.x + b1.x;
    r1.y = (v1.y - mu) * inv * g1.y + b1.y;
    r1.z = (v1.z - mu) * inv * g1.z + b1.z;
    r1.w = (v1.w - mu) * inv * g1.w + b1.w;
    *(float4*)&out[base] = r0;
    *(float4*)&out[base + 4] = r1;
}

// ---------------- host orchestration ----------------
static void build_csr(const int* src, const int* dst, int n_dst,
                      int* cnt, int* off, int* cur, int* psrc)
{
    zero_k<<<256, 256>>>(cnt, n_dst);
    hist_k<<<(E_N + 255) / 256, 256>>>(dst, E_N, cnt);
    scan_k<<<1, 1024>>>(cnt, n_dst, off, cur);
    scatter_k<<<(E_N + 255) / 256, 256>>>(src, dst, E_N, cur, psrc);
}

extern "C" void kernel_launch(void* const* d_in, const int* in_sizes, int n_in,
                              void* d_out, int out_size)
{
    const float* h_a  = (const float*)d_in[0];
    const float* h_p  = (const float*)d_in[1];
    const int* wsrc   = (const int*)d_in[2];
    const int* wdst   = (const int*)d_in[3];
    const int* wbsrc  = (const int*)d_in[4];
    const int* wbdst  = (const int*)d_in[5];
    const int* csrc   = (const int*)d_in[6];
    const int* cdst   = (const int*)d_in[7];
    const float* Wk   = (const float*)d_in[8];
    const float* bk   = (const float*)d_in[9];
    const float* Wq   = (const float*)d_in[10];
    const float* bq   = (const float*)d_in[11];
    const float* Wv   = (const float*)d_in[12];
    const float* bv   = (const float*)d_in[13];
    const float* Wfc  = (const float*)d_in[14];
    const float* bfc  = (const float*)d_in[15];
    const float* lng  = (const float*)d_in[16];
    const float* lnb  = (const float*)d_in[17];
    const float* attw = (const float*)d_in[18];
    const float* valw = (const float*)d_in[19];
    const float* canon= (const float*)d_in[20];
    const float* res  = (const float*)d_in[21];
    float* out = (float*)d_out;

    float *QA, *KA, *VA, *QP, *KP, *VP, *KE, *VE, *AGA, *AGP;
    int *cnt, *off, *cur, *psrc;
    cudaGetSymbolAddress((void**)&QA, g_QA);
    cudaGetSymbolAddress((void**)&KA, g_KA);
    cudaGetSymbolAddress((void**)&VA, g_VA);
    cudaGetSymbolAddress((void**)&QP, g_QP);
    cudaGetSymbolAddress((void**)&KP, g_KP);
    cudaGetSymbolAddress((void**)&VP, g_VP);
    cudaGetSymbolAddress((void**)&KE, g_KE);
    cudaGetSymbolAddress((void**)&VE, g_VE);
    cudaGetSymbolAddress((void**)&AGA, g_AGA);
    cudaGetSymbolAddress((void**)&AGP, g_AGP);
    cudaGetSymbolAddress((void**)&cnt, g_cnt);
    cudaGetSymbolAddress((void**)&off, g_off);
    cudaGetSymbolAddress((void**)&cur, g_cur);
    cudaGetSymbolAddress((void**)&psrc, g_psrc);

    const dim3 gA(2, (NA_N + 127) / 128), gP(2, (NP_N + 127) / 128);
    const int WPB = 8;  // warps per 256-thread block
    const int gwA = (NA_N + WPB - 1) / WPB, gwP = (NP_N + WPB - 1) / WPB;

    // node projections
    sgemm_k<0><<<gA, 256>>>(h_a, Wq + 0,       bq + 0,   nullptr, nullptr, QA, NA_N, 1.f);
    sgemm_k<0><<<gA, 256>>>(h_a, Wk + 0,       bk + 0,   nullptr, nullptr, KA, NA_N, 1.f);
    sgemm_k<0><<<gA, 256>>>(h_a, Wv + 0,       bv + 0,   nullptr, nullptr, VA, NA_N, 1.f);
    sgemm_k<0><<<gP, 256>>>(h_p, Wq + 65536,   bq + 256, nullptr, nullptr, QP, NP_N, 1.f);
    sgemm_k<0><<<gP, 256>>>(h_p, Wk + 65536,   bk + 256, nullptr, nullptr, KP, NP_N, 1.f);
    sgemm_k<0><<<gP, 256>>>(h_p, Wv + 65536,   bv + 256, nullptr, nullptr, VP, NP_N, 1.f);

    // etype 0: writes (author -> paper), store into AGP
    head_transform_k<<<gwA, 256>>>(KA, attw + 0 * 8192, KE, NA_N);
    head_transform_k<<<gwA, 256>>>(VA, valw + 0 * 8192, VE, NA_N);
    build_csr(wsrc, wdst, NP_N, cnt, off, cur, psrc);
    agg_k<0><<<gwP, 256>>>(QP, KE, VE, off, psrc, canon + 0 * H_, AGP, NP_N);

    // etype 2: cites (paper -> paper), accumulate into AGP
    head_transform_k<<<gwP, 256>>>(KP, attw + 2 * 8192, KE, NP_N);
    head_transform_k<<<gwP, 256>>>(VP, valw + 2 * 8192, VE, NP_N);
    build_csr(csrc, cdst, NP_N, cnt, off, cur, psrc);
    agg_k<1><<<gwP, 256>>>(QP, KE, VE, off, psrc, canon + 2 * H_, AGP, NP_N);

    // etype 1: written-by (paper -> author), store into AGA
    head_transform_k<<<gwP, 256>>>(KP, attw + 1 * 8192, KE, NP_N);
    head_transform_k<<<gwP, 256>>>(VP, valw + 1 * 8192, VE, NP_N);
    build_csr(wbsrc, wbdst, NA_N, cnt, off, cur, psrc);
    agg_k<0><<<gwA, 256>>>(QA, KE, VE, off, psrc, canon + 1 * H_, AGA, NA_N);

    // fc + residual blend (KE/VE reused as temporaries)
    sgemm_k<1><<<gA, 256>>>(AGA, Wfc + 0,     bfc + 0,   h_a, res + 0, KE, NA_N, 1.0f);
    sgemm_k<1><<<gP, 256>>>(AGP, Wfc + 65536, bfc + 256, h_p, res + 1, VE, NP_N, 0.5f);

    // layernorm -> output
    ln_k<<<gwA, 256>>>(KE, lng + 0,   lnb + 0,   out, NA_N);
    ln_k<<<gwP, 256>>>(VE, lng + 256, lnb + 256, out + (size_t)NA_N * D_, NP_N);
}

// round 2
// speedup vs baseline: 2.0858x; 2.0858x over previous
#include <cuda_runtime.h>
#include <math.h>
#include <stdint.h>

#define NA_N 100000
#define NP_N 100000
#define E_N  400000
#define D_   256
#define H_   8
#define DK_  32

// ---------------- static scratch ----------------
static __device__ float g_QA[(size_t)NA_N * D_];
static __device__ float g_QP[(size_t)NP_N * D_];
static __device__ float g_KE[(size_t)NP_N * D_];   // reused per etype; later: author fc tmp
static __device__ float g_VE[(size_t)NP_N * D_];   // reused per etype; later: paper fc tmp
static __device__ float g_AGA[(size_t)NA_N * D_];
static __device__ float g_AGP[(size_t)NP_N * D_];
static __device__ float g_Wc[6 * 256 * 256];       // combined proj@headtransform weights
static __device__ float g_bc[6 * 256];
static __device__ int   g_cnt[NP_N + 1];
static __device__ int   g_off[NP_N + 1];
static __device__ int   g_cur[NP_N];
static __device__ int   g_psrc[E_N];

// ---------------- helpers ----------------
__device__ __forceinline__ unsigned f2tf32(float x) {
    unsigned y;
    asm("cvt.rna.tf32.f32 %0, %1;" : "=r"(y) : "f"(x));
    return y;
}

__device__ __forceinline__ void mma_tf32(float& c0, float& c1, float& c2, float& c3,
                                         unsigned a0, unsigned a1, unsigned a2, unsigned a3,
                                         unsigned b0, unsigned b1) {
    asm volatile(
        "mma.sync.aligned.m16n8k8.row.col.f32.tf32.tf32.f32 "
        "{%0,%1,%2,%3}, {%4,%5,%6,%7}, {%8,%9}, {%0,%1,%2,%3};"
        : "+f"(c0), "+f"(c1), "+f"(c2), "+f"(c3)
        : "r"(a0), "r"(a1), "r"(a2), "r"(a3), "r"(b0), "r"(b1));
}

// ---------------- TF32 tensor-core GEMM: C[M,256] = scaleA*(A[M,256]@W[256,256]) + bias ----------------
// MODE 0: C = scaleA*acc + bias
// MODE 1: C = (scaleA*acc + bias)*sigmoid(res) + Hin*(1-sigmoid(res))
// Block tile 128x128, BK=32, 8 warps (4m x 2n), warp tile 32x64, mma m16n8k8.
template <int MODE>
__global__ __launch_bounds__(256, 2) void mma_gemm_k(
    const float* __restrict__ A, const float* __restrict__ W,
    const float* __restrict__ bias, const float* __restrict__ Hin,
    const float* __restrict__ resv, float* __restrict__ C,
    int M, float scaleA)
{
    __shared__ float As[128 * 36];  // [m][k], stride 36 (pad 4) -> conflict-free frag loads
    __shared__ float Bs[32 * 136];  // [k][n], stride 136 (pad 8)

    const int tid = threadIdx.x;
    const int bm = blockIdx.y * 128;
    const int bn = blockIdx.x * 128;
    const int lane = tid & 31;
    const int wid = tid >> 5;
    const int warp_m = (wid & 3) * 32;
    const int warp_n = (wid >> 2) * 64;
    const int qr = lane >> 2;   // 0..7
    const int qc = lane & 3;    // 0..3

    float acc[2][8][4];
#pragma unroll
    for (int t = 0; t < 2; t++)
#pragma unroll
        for (int j = 0; j < 8; j++)
#pragma unroll
            for (int c = 0; c < 4; c++) acc[t][j][c] = 0.f;

    // A-tile load mapping: 128x32 = 1024 float4, 4 per thread
    const int a_r0 = tid >> 3;          // 0..31 (+32 per iter)
    const int a_c4 = (tid & 7) * 4;     // 0,4,..,28
    // B-tile load mapping: 32x128 = 1024 float4, 4 per thread
    const int b_k0 = tid >> 5;          // 0..7 (+8 per iter)
    const int b_n4 = (tid & 31) * 4;    // 0..124

    for (int k0 = 0; k0 < 256; k0 += 32) {
        // load + tf32-round A tile
#pragma unroll
        for (int it = 0; it < 4; it++) {
            int r = a_r0 + it * 32;
            int grow = bm + r;
            float4 v = make_float4(0.f, 0.f, 0.f, 0.f);
            if (grow < M) v = *(const float4*)&A[(size_t)grow * 256 + k0 + a_c4];
            float4 w;
            w.x = __uint_as_float(f2tf32(v.x));
            w.y = __uint_as_float(f2tf32(v.y));
            w.z = __uint_as_float(f2tf32(v.z));
            w.w = __uint_as_float(f2tf32(v.w));
            *(float4*)&As[r * 36 + a_c4] = w;
        }
        // load + tf32-round B tile
#pragma unroll
        for (int it = 0; it < 4; it++) {
            int k = b_k0 + it * 8;
            float4 v = *(const float4*)&W[(size_t)(k0 + k) * 256 + bn + b_n4];
            float4 w;
            w.x = __uint_as_float(f2tf32(v.x));
            w.y = __uint_as_float(f2tf32(v.y));
            w.z = __uint_as_float(f2tf32(v.z));
            w.w = __uint_as_float(f2tf32(v.w));
            *(float4*)&Bs[k * 136 + b_n4] = w;
        }
        __syncthreads();

#pragma unroll
        for (int ks = 0; ks < 4; ks++) {
            unsigned af[2][4];
#pragma unroll
            for (int t = 0; t < 2; t++) {
                int r = warp_m + t * 16 + qr;
                int kc = ks * 8 + qc;
                af[t][0] = __float_as_uint(As[r * 36 + kc]);
                af[t][1] = __float_as_uint(As[(r + 8) * 36 + kc]);
                af[t][2] = __float_as_uint(As[r * 36 + kc + 4]);
                af[t][3] = __float_as_uint(As[(r + 8) * 36 + kc + 4]);
            }
            unsigned bf[8][2];
#pragma unroll
            for (int j = 0; j < 8; j++) {
                int col = warp_n + j * 8 + qr;
                int kc = ks * 8 + qc;
                bf[j][0] = __float_as_uint(Bs[kc * 136 + col]);
                bf[j][1] = __float_as_uint(Bs[(kc + 4) * 136 + col]);
            }
#pragma unroll
            for (int t = 0; t < 2; t++)
#pragma unroll
                for (int j = 0; j < 8; j++)
                    mma_tf32(acc[t][j][0], acc[t][j][1], acc[t][j][2], acc[t][j][3],
                             af[t][0], af[t][1], af[t][2], af[t][3],
                             bf[j][0], bf[j][1]);
        }
        __syncthreads();
    }

    float alpha = 1.f, beta = 0.f;
    if (MODE == 1) {
        float rv = __ldg(resv);
        alpha = 1.f / (1.f + __expf(-rv));
        beta = 1.f - alpha;
    }

#pragma unroll
    for (int t = 0; t < 2; t++) {
        int r0 = bm + warp_m + t * 16 + qr;
        int r1 = r0 + 8;
#pragma unroll
        for (int j = 0; j < 8; j++) {
            int col = bn + warp_n + j * 8 + 2 * qc;
            float2 bb = *(const float2*)&bias[col];
            float2 v0, v1;
            v0.x = acc[t][j][0] * scaleA + bb.x;
            v0.y = acc[t][j][1] * scaleA + bb.y;
            v1.x = acc[t][j][2] * scaleA + bb.x;
            v1.y = acc[t][j][3] * scaleA + bb.y;
            if (MODE == 1) {
                if (r0 < M) {
                    float2 h0 = *(const float2*)&Hin[(size_t)r0 * 256 + col];
                    v0.x = v0.x * alpha + h0.x * beta;
                    v0.y = v0.y * alpha + h0.y * beta;
                }
                if (r1 < M) {
                    float2 h1 = *(const float2*)&Hin[(size_t)r1 * 256 + col];
                    v1.x = v1.x * alpha + h1.x * beta;
                    v1.y = v1.y * alpha + h1.y * beta;
                }
            }
            if (r0 < M) *(float2*)&C[(size_t)r0 * 256 + col] = v0;
            if (r1 < M) *(float2*)&C[(size_t)r1 * 256 + col] = v1;
        }
    }
}

// ---------------- weight-combine: Wc = W @ blockdiag(hw), bc = b @ blockdiag(hw) ----------------
// W [256,256] (in,out), hw [H,32,32], out Wc [256,256], bc[256]
__global__ __launch_bounds__(256) void prep_w_k(
    const float* __restrict__ W, const float* __restrict__ b,
    const float* __restrict__ hw, float* __restrict__ Wc, float* __restrict__ bc)
{
    __shared__ float s_hw[32 * 32];
    const int h = blockIdx.x;      // head
    const int tid = threadIdx.x;
#pragma unroll
    for (int i = tid; i < 1024; i += 256) s_hw[i] = hw[h * 1024 + i];
    __syncthreads();

    // each thread: one input row d
    const int d = tid;
    float wrow[32];
#pragma unroll
    for (int d2 = 0; d2 < 32; d2++) wrow[d2] = W[(size_t)d * 256 + h * 32 + d2];
#pragma unroll
    for (int j = 0; j < 32; j++) {
        float acc = 0.f;
#pragma unroll
        for (int d2 = 0; d2 < 32; d2++) acc += wrow[d2] * s_hw[d2 * 32 + j];
        Wc[(size_t)d * 256 + h * 32 + j] = acc;
    }
    if (tid < 32) {
        float acc = 0.f;
#pragma unroll
        for (int d2 = 0; d2 < 32; d2++) acc += b[h * 32 + d2] * s_hw[d2 * 32 + tid];
        bc[h * 32 + tid] = acc;
    }
}

// ---------------- CSR build ----------------
__global__ void zero_k(int* __restrict__ p, int n)
{
    for (int i = blockIdx.x * blockDim.x + threadIdx.x; i < n; i += gridDim.x * blockDim.x) p[i] = 0;
}

__global__ void hist_k(const int* __restrict__ dst, int ne, int* __restrict__ cnt)
{
    int i = blockIdx.x * blockDim.x + threadIdx.x;
    if (i < ne) atomicAdd(&cnt[dst[i]], 1);
}

__global__ __launch_bounds__(1024) void scan_k(
    const int* __restrict__ cnt, int n, int* __restrict__ off, int* __restrict__ cur)
{
    __shared__ int sh[1024];
    int t = threadIdx.x;
    int chunk = (n + 1023) >> 10;
    int s0 = t * chunk;
    int s1 = min(s0 + chunk, n);
    int sum = 0;
    for (int i = s0; i < s1; i++) sum += cnt[i];
    sh[t] = sum;
    __syncthreads();
    for (int d = 1; d < 1024; d <<= 1) {
        int v = 0;
        if (t >= d) v = sh[t - d];
        __syncthreads();
        sh[t] += v;
        __syncthreads();
    }
    int run = sh[t] - sum;  // exclusive prefix
    for (int i = s0; i < s1; i++) {
        off[i] = run;
        cur[i] = run;
        run += cnt[i];
    }
    if (t == 1023) off[n] = sh[1023];
}

__global__ void scatter_k(const int* __restrict__ src, const int* __restrict__ dst,
                          int ne, int* __restrict__ cur, int* __restrict__ psrc)
{
    int i = blockIdx.x * blockDim.x + threadIdx.x;
    if (i < ne) {
        int p = atomicAdd(&cur[dst[i]], 1);
        psrc[p] = src[i];
    }
}

// ---------------- warp-per-destination online-softmax aggregation ----------------
template <int ACCUM>
__global__ __launch_bounds__(256) void agg_k(
    const float* __restrict__ Q, const float* __restrict__ KE, const float* __restrict__ VE,
    const int* __restrict__ off, const int* __restrict__ psrc,
    const float* __restrict__ canon, float* __restrict__ OUT, int n_dst)
{
    int gw = (blockIdx.x * blockDim.x + threadIdx.x) >> 5;
    if (gw >= n_dst) return;
    int lane = threadIdx.x & 31;
    int h = lane >> 2;
    int seg = (lane & 3) << 3;
    size_t base = (size_t)gw * 256 + h * 32 + seg;

    float4 q0 = *(const float4*)(Q + base);
    float4 q1 = *(const float4*)(Q + base + 4);
    float cw = __ldg(&canon[h]) * 0.17677669529663687f;  // 1/sqrt(32)

    int ebeg = __ldg(&off[gw]);
    int eend = __ldg(&off[gw + 1]);

    float m = -3.0e38f, den = 0.f;
    float a0 = 0, a1 = 0, a2 = 0, a3 = 0, a4 = 0, a5 = 0, a6 = 0, a7 = 0;

    for (int i = ebeg; i < eend; i++) {
        int src = __ldg(&psrc[i]);
        size_t sb = (size_t)src * 256 + h * 32 + seg;
        float4 k0 = *(const float4*)(KE + sb);
        float4 k1 = *(const float4*)(KE + sb + 4);
        float4 v0 = *(const float4*)(VE + sb);
        float4 v1 = *(const float4*)(VE + sb + 4);
        float p = q0.x * k0.x + q0.y * k0.y + q0.z * k0.z + q0.w * k0.w +
                  q1.x * k1.x + q1.y * k1.y + q1.z * k1.z + q1.w * k1.w;
        p += __shfl_xor_sync(0xffffffffu, p, 1);
        p += __shfl_xor_sync(0xffffffffu, p, 2);
        float sc = p * cw;
        float mn = fmaxf(m, sc);
        float corr = __expf(m - mn);
        float w = __expf(sc - mn);
        m = mn;
        den = den * corr + w;
        a0 = a0 * corr + w * v0.x;
        a1 = a1 * corr + w * v0.y;
        a2 = a2 * corr + w * v0.z;
        a3 = a3 * corr + w * v0.w;
        a4 = a4 * corr + w * v1.x;
        a5 = a5 * corr + w * v1.y;
        a6 = a6 * corr + w * v1.z;
        a7 = a7 * corr + w * v1.w;
    }

    float r = (den > 0.f) ? (1.f / den) : 0.f;
    float o0 = a0 * r, o1 = a1 * r, o2 = a2 * r, o3 = a3 * r;
    float o4 = a4 * r, o5 = a5 * r, o6 = a6 * r, o7 = a7 * r;
    if (ACCUM) {
        float4 p0 = *(const float4*)(OUT + base);
        float4 p1 = *(const float4*)(OUT + base + 4);
        o0 += p0.x; o1 += p0.y; o2 += p0.z; o3 += p0.w;
        o4 += p1.x; o5 += p1.y; o6 += p1.z; o7 += p1.w;
    }
    *(float4*)(OUT + base) = make_float4(o0, o1, o2, o3);
    *(float4*)(OUT + base + 4) = make_float4(o4, o5, o6, o7);
}

// ---------------- layernorm (warp per row) ----------------
__global__ __launch_bounds__(256) void ln_k(
    const float* __restrict__ HP, const float* __restrict__ g, const float* __restrict__ b,
    float* __restrict__ out, int N)
{
    int gw = (blockIdx.x * blockDim.x + threadIdx.x) >> 5;
    if (gw >= N) return;
    int lane = threadIdx.x & 31;
    size_t base = (size_t)gw * 256 + lane * 8;
    float4 v0 = *(const float4*)&HP[base];
    float4 v1 = *(const float4*)&HP[base + 4];
    float s = v0.x + v0.y + v0.z + v0.w + v1.x + v1.y + v1.z + v1.w;
#pragma unroll
    for (int d = 16; d; d >>= 1) s += __shfl_xor_sync(0xffffffffu, s, d);
    float mu = s * (1.f / 256.f);
    float q = (v0.x - mu) * (v0.x - mu) + (v0.y - mu) * (v0.y - mu) +
              (v0.z - mu) * (v0.z - mu) + (v0.w - mu) * (v0.w - mu) +
              (v1.x - mu) * (v1.x - mu) + (v1.y - mu) * (v1.y - mu) +
              (v1.z - mu) * (v1.z - mu) + (v1.w - mu) * (v1.w - mu);
#pragma unroll
    for (int d = 16; d; d >>= 1) q += __shfl_xor_sync(0xffffffffu, q, d);
    float inv = rsqrtf(q * (1.f / 256.f) + 1e-5f);
    int col = lane * 8;
    float4 g0 = *(const float4*)&g[col];
    float4 g1 = *(const float4*)&g[col + 4];
    float4 b0 = *(const float4*)&b[col];
    float4 b1 = *(const float4*)&b[col + 4];
    float4 r0, r1;
    r0.x = (v0.x - mu) * inv * g0.x + b0.x;
    r0.y = (v0.y - mu) * inv * g0.y + b0.y;
    r0.z = (v0.z - mu) * inv * g0.z + b0.z;
    r0.w = (v0.w - mu) * inv * g0.w + b0.w;
    r1.x = (v1.x - mu) * inv * g1.x + b1.x;
    r1.y = (v1.y - mu) * inv * g1.y + b1.y;
    r1.z = (v1.z - mu) * inv * g1.z + b1.z;
    r1.w = (v1.w - mu) * inv * g1.w + b1.w;
    *(float4*)&out[base] = r0;
    *(float4*)&out[base + 4] = r1;
}

// ---------------- host orchestration ----------------
static void build_csr(const int* src, const int* dst, int n_dst,
                      int* cnt, int* off, int* cur, int* psrc)
{
    zero_k<<<256, 256>>>(cnt, n_dst);
    hist_k<<<(E_N + 255) / 256, 256>>>(dst, E_N, cnt);
    scan_k<<<1, 1024>>>(cnt, n_dst, off, cur);
    scatter_k<<<(E_N + 255) / 256, 256>>>(src, dst, E_N, cur, psrc);
}

extern "C" void kernel_launch(void* const* d_in, const int* in_sizes, int n_in,
                              void* d_out, int out_size)
{
    const float* h_a  = (const float*)d_in[0];
    const float* h_p  = (const float*)d_in[1];
    const int* wsrc   = (const int*)d_in[2];
    const int* wdst   = (const int*)d_in[3];
    const int* wbsrc  = (const int*)d_in[4];
    const int* wbdst  = (const int*)d_in[5];
    const int* csrc   = (const int*)d_in[6];
    const int* cdst   = (const int*)d_in[7];
    const float* Wk   = (const float*)d_in[8];
    const float* bk   = (const float*)d_in[9];
    const float* Wq   = (const float*)d_in[10];
    const float* bq   = (const float*)d_in[11];
    const float* Wv   = (const float*)d_in[12];
    const float* bv   = (const float*)d_in[13];
    const float* Wfc  = (const float*)d_in[14];
    const float* bfc  = (const float*)d_in[15];
    const float* lng  = (const float*)d_in[16];
    const float* lnb  = (const float*)d_in[17];
    const float* attw = (const float*)d_in[18];
    const float* valw = (const float*)d_in[19];
    const float* canon= (const float*)d_in[20];
    const float* res  = (const float*)d_in[21];
    float* out = (float*)d_out;

    float *QA, *QP, *KE, *VE, *AGA, *AGP, *Wc, *bc;
    int *cnt, *off, *cur, *psrc;
    cudaGetSymbolAddress((void**)&QA, g_QA);
    cudaGetSymbolAddress((void**)&QP, g_QP);
    cudaGetSymbolAddress((void**)&KE, g_KE);
    cudaGetSymbolAddress((void**)&VE, g_VE);
    cudaGetSymbolAddress((void**)&AGA, g_AGA);
    cudaGetSymbolAddress((void**)&AGP, g_AGP);
    cudaGetSymbolAddress((void**)&Wc, g_Wc);
    cudaGetSymbolAddress((void**)&bc, g_bc);
    cudaGetSymbolAddress((void**)&cnt, g_cnt);
    cudaGetSymbolAddress((void**)&off, g_off);
    cudaGetSymbolAddress((void**)&cur, g_cur);
    cudaGetSymbolAddress((void**)&psrc, g_psrc);

    const dim3 gA(2, (NA_N + 127) / 128), gP(2, (NP_N + 127) / 128);
    const int WPB = 8;
    const int gwA = (NA_N + WPB - 1) / WPB, gwP = (NP_N + WPB - 1) / WPB;
    const size_t WS = 65536;  // 256*256

    // combined weights: slot i of g_Wc/g_bc
    // 0: author K (etype0), 1: author V (etype0)
    // 2: paper  K (etype1), 3: paper  V (etype1)
    // 4: paper  K (etype2), 5: paper  V (etype2)
    prep_w_k<<<8, 256>>>(Wk + 0,  bk + 0,   attw + 0 * 8192, Wc + 0 * WS, bc + 0 * 256);
    prep_w_k<<<8, 256>>>(Wv + 0,  bv + 0,   valw + 0 * 8192, Wc + 1 * WS, bc + 1 * 256);
    prep_w_k<<<8, 256>>>(Wk + WS, bk + 256, attw + 1 * 8192, Wc + 2 * WS, bc + 2 * 256);
    prep_w_k<<<8, 256>>>(Wv + WS, bv + 256, valw + 1 * 8192, Wc + 3 * WS, bc + 3 * 256);
    prep_w_k<<<8, 256>>>(Wk + WS, bk + 256, attw + 2 * 8192, Wc + 4 * WS, bc + 4 * 256);
    prep_w_k<<<8, 256>>>(Wv + WS, bv + 256, valw + 2 * 8192, Wc + 5 * WS, bc + 5 * 256);

    // Q projections
    mma_gemm_k<0><<<gA, 256>>>(h_a, Wq + 0,  bq + 0,   nullptr, nullptr, QA, NA_N, 1.f);
    mma_gemm_k<0><<<gP, 256>>>(h_p, Wq + WS, bq + 256, nullptr, nullptr, QP, NP_N, 1.f);

    // etype 0: writes (author -> paper) -> AGP
    mma_gemm_k<0><<<gA, 256>>>(h_a, Wc + 0 * WS, bc + 0 * 256, nullptr, nullptr, KE, NA_N, 1.f);
    mma_gemm_k<0><<<gA, 256>>>(h_a, Wc + 1 * WS, bc + 1 * 256, nullptr, nullptr, VE, NA_N, 1.f);
    build_csr(wsrc, wdst, NP_N, cnt, off, cur, psrc);
    agg_k<0><<<gwP, 256>>>(QP, KE, VE, off, psrc, canon + 0 * H_, AGP, NP_N);

    // etype 2: cites (paper -> paper), accumulate into AGP
    mma_gemm_k<0><<<gP, 256>>>(h_p, Wc + 4 * WS, bc + 4 * 256, nullptr, nullptr, KE, NP_N, 1.f);
    mma_gemm_k<0><<<gP, 256>>>(h_p, Wc + 5 * WS, bc + 5 * 256, nullptr, nullptr, VE, NP_N, 1.f);
    build_csr(csrc, cdst, NP_N, cnt, off, cur, psrc);
    agg_k<1><<<gwP, 256>>>(QP, KE, VE, off, psrc, canon + 2 * H_, AGP, NP_N);

    // etype 1: written-by (paper -> author) -> AGA
    mma_gemm_k<0><<<gP, 256>>>(h_p, Wc + 2 * WS, bc + 2 * 256, nullptr, nullptr, KE, NP_N, 1.f);
    mma_gemm_k<0><<<gP, 256>>>(h_p, Wc + 3 * WS, bc + 3 * 256, nullptr, nullptr, VE, NP_N, 1.f);
    build_csr(wbsrc, wbdst, NA_N, cnt, off, cur, psrc);
    agg_k<0><<<gwA, 256>>>(QA, KE, VE, off, psrc, canon + 1 * H_, AGA, NA_N);

    // fc + residual blend (KE/VE reused as temporaries)
    mma_gemm_k<1><<<gA, 256>>>(AGA, Wfc + 0,  bfc + 0,   h_a, res + 0, KE, NA_N, 1.0f);
    mma_gemm_k<1><<<gP, 256>>>(AGP, Wfc + WS, bfc + 256, h_p, res + 1, VE, NP_N, 0.5f);

    // layernorm -> output
    ln_k<<<gwA, 256>>>(KE, lng + 0,   lnb + 0,   out, NA_N);
    ln_k<<<gwP, 256>>>(VE, lng + 256, lnb + 256, out + (size_t)NA_N * D_, NP_N);
}

// round 3
// speedup vs baseline: 2.5845x; 1.2391x over previous
#include <cuda_runtime.h>
#include <math.h>
#include <stdint.h>

#define NA_N 100000
#define NP_N 100000
#define E_N  400000
#define D_   256
#define H_   8

#define LDA_P 1280   // paper proj row: Q | K1 | V1 | K2 | V2
#define LDA_A 768    // author proj row: Q | K0 | V0

// ---------------- static scratch ----------------
static __device__ float g_APROJ[(size_t)NA_N * LDA_A];
static __device__ float g_PPROJ[(size_t)NP_N * LDA_P];
static __device__ float g_AGA[(size_t)NA_N * D_];
static __device__ float g_AGP[(size_t)NP_N * D_];
static __device__ float g_T0[(size_t)NA_N * D_];
static __device__ float g_T1[(size_t)NP_N * D_];
static __device__ float g_WcatA[256 * LDA_A];
static __device__ float g_WcatP[256 * LDA_P];
static __device__ float g_bcatA[LDA_A];
static __device__ float g_bcatP[LDA_P];
static __device__ int g_cnt_w[NP_N], g_cnt_c[NP_N], g_cnt_a[NA_N];
static __device__ int g_off_w[NP_N + 1], g_off_c[NP_N + 1], g_off_a[NA_N + 1];
static __device__ int g_cur_w[NP_N], g_cur_c[NP_N], g_cur_a[NA_N];
static __device__ int g_psrc_w[E_N], g_psrc_c[E_N], g_psrc_a[E_N];

// ---------------- helpers ----------------
__device__ __forceinline__ unsigned f2tf32(float x) {
    unsigned y;
    asm("cvt.rna.tf32.f32 %0, %1;" : "=r"(y) : "f"(x));
    return y;
}
__device__ __forceinline__ float4 cvt4(float4 v) {
    float4 w;
    w.x = __uint_as_float(f2tf32(v.x));
    w.y = __uint_as_float(f2tf32(v.y));
    w.z = __uint_as_float(f2tf32(v.z));
    w.w = __uint_as_float(f2tf32(v.w));
    return w;
}
__device__ __forceinline__ void mma_tf32(float& c0, float& c1, float& c2, float& c3,
                                         unsigned a0, unsigned a1, unsigned a2, unsigned a3,
                                         unsigned b0, unsigned b1) {
    asm volatile(
        "mma.sync.aligned.m16n8k8.row.col.f32.tf32.tf32.f32 "
        "{%0,%1,%2,%3}, {%4,%5,%6,%7}, {%8,%9}, {%0,%1,%2,%3};"
        : "+f"(c0), "+f"(c1), "+f"(c2), "+f"(c3)
        : "r"(a0), "r"(a1), "r"(a2), "r"(a3), "r"(b0), "r"(b1));
}

// ---------------- pipelined TF32 GEMM: C[M,N] = scaleA*(A[M,256]@W[256,N]) + bias ----------------
// MODE 0: C = scaleA*acc + bias
// MODE 1: C = (scaleA*acc + bias)*sigmoid(res) + Hin*(1-sigmoid(res))
// Block tile 128x128, BK=32, 2-stage smem double buffer w/ register prefetch.
#define GEMM_SMEM_BYTES ((2 * 4608 + 2 * 4352) * 4)

template <int MODE>
__global__ __launch_bounds__(256) void mma_gemm_k(
    const float* __restrict__ A, const float* __restrict__ W,
    const float* __restrict__ bias, const float* __restrict__ Hin,
    const float* __restrict__ resv, float* __restrict__ C,
    int M, int N, float scaleA)
{
    extern __shared__ float sm[];
    float* As = sm;              // [2][128*36]
    float* Bs = sm + 2 * 4608;   // [2][32*136]

    const int tid = threadIdx.x;
    const int bm = blockIdx.y * 128;
    const int bn = blockIdx.x * 128;
    const int lane = tid & 31, wid = tid >> 5;
    const int warp_m = (wid & 3) * 32, warp_n = (wid >> 2) * 64;
    const int qr = lane >> 2, qc = lane & 3;

    float acc[2][8][4];
#pragma unroll
    for (int t = 0; t < 2; t++)
#pragma unroll
        for (int j = 0; j < 8; j++)
#pragma unroll
            for (int c = 0; c < 4; c++) acc[t][j][c] = 0.f;

    const int a_r0 = tid >> 3, a_c4 = (tid & 7) * 4;
    const int b_k0 = tid >> 5, b_n4 = (tid & 31) * 4;

    float4 pa[4], pb[4];

    // prologue: load k0=0
#pragma unroll
    for (int it = 0; it < 4; it++) {
        int grow = bm + a_r0 + it * 32;
        pa[it] = (grow < M) ? *(const float4*)&A[(size_t)grow * 256 + a_c4]
                            : make_float4(0.f, 0.f, 0.f, 0.f);
        pb[it] = *(const float4*)&W[(size_t)(b_k0 + it * 8) * N + bn + b_n4];
    }
#pragma unroll
    for (int it = 0; it < 4; it++) {
        *(float4*)&As[(a_r0 + it * 32) * 36 + a_c4] = cvt4(pa[it]);
        *(float4*)&Bs[(b_k0 + it * 8) * 136 + b_n4] = cvt4(pb[it]);
    }
    __syncthreads();

    int cur = 0;
#pragma unroll
    for (int it8 = 0; it8 < 8; it8++) {
        // prefetch next tile while computing current
        if (it8 < 7) {
            int k0 = (it8 + 1) * 32;
#pragma unroll
            for (int it = 0; it < 4; it++) {
                int grow = bm + a_r0 + it * 32;
                pa[it] = (grow < M) ? *(const float4*)&A[(size_t)grow * 256 + k0 + a_c4]
                                    : make_float4(0.f, 0.f, 0.f, 0.f);
                pb[it] = *(const float4*)&W[(size_t)(k0 + b_k0 + it * 8) * N + bn + b_n4];
            }
        }

        const float* Ac = As + cur * 4608;
        const float* Bc = Bs + cur * 4352;
#pragma unroll
        for (int ks = 0; ks < 4; ks++) {
            int kc = ks * 8 + qc;
            unsigned af[2][4];
#pragma unroll
            for (int t = 0; t < 2; t++) {
                int r = warp_m + t * 16 + qr;
                af[t][0] = __float_as_uint(Ac[r * 36 + kc]);
                af[t][1] = __float_as_uint(Ac[(r + 8) * 36 + kc]);
                af[t][2] = __float_as_uint(Ac[r * 36 + kc + 4]);
                af[t][3] = __float_as_uint(Ac[(r + 8) * 36 + kc + 4]);
            }
            unsigned bf[8][2];
#pragma unroll
            for (int j = 0; j < 8; j++) {
                int col = warp_n + j * 8 + qr;
                bf[j][0] = __float_as_uint(Bc[kc * 136 + col]);
                bf[j][1] = __float_as_uint(Bc[(kc + 4) * 136 + col]);
            }
#pragma unroll
            for (int t = 0; t < 2; t++)
#pragma unroll
                for (int j = 0; j < 8; j++)
                    mma_tf32(acc[t][j][0], acc[t][j][1], acc[t][j][2], acc[t][j][3],
                             af[t][0], af[t][1], af[t][2], af[t][3],
                             bf[j][0], bf[j][1]);
        }

        if (it8 < 7) {
            int nxt = cur ^ 1;
#pragma unroll
            for (int it = 0; it < 4; it++) {
                *(float4*)&As[nxt * 4608 + (a_r0 + it * 32) * 36 + a_c4] = cvt4(pa[it]);
                *(float4*)&Bs[nxt * 4352 + (b_k0 + it * 8) * 136 + b_n4] = cvt4(pb[it]);
            }
        }
        __syncthreads();
        cur ^= 1;
    }

    float alpha = 1.f, beta = 0.f;
    if (MODE == 1) {
        float rv = __ldg(resv);
        alpha = 1.f / (1.f + __expf(-rv));
        beta = 1.f - alpha;
    }

#pragma unroll
    for (int t = 0; t < 2; t++) {
        int r0 = bm + warp_m + t * 16 + qr;
        int r1 = r0 + 8;
#pragma unroll
        for (int j = 0; j < 8; j++) {
            int col = bn + warp_n + j * 8 + 2 * qc;
            float2 bb = *(const float2*)&bias[col];
            float2 v0, v1;
            v0.x = acc[t][j][0] * scaleA + bb.x;
            v0.y = acc[t][j][1] * scaleA + bb.y;
            v1.x = acc[t][j][2] * scaleA + bb.x;
            v1.y = acc[t][j][3] * scaleA + bb.y;
            if (MODE == 1) {
                if (r0 < M) {
                    float2 h0 = *(const float2*)&Hin[(size_t)r0 * 256 + col];
                    v0.x = v0.x * alpha + h0.x * beta;
                    v0.y = v0.y * alpha + h0.y * beta;
                }
                if (r1 < M) {
                    float2 h1 = *(const float2*)&Hin[(size_t)r1 * 256 + col];
                    v1.x = v1.x * alpha + h1.x * beta;
                    v1.y = v1.y * alpha + h1.y * beta;
                }
            }
            if (r0 < M) *(float2*)&C[(size_t)r0 * N + col] = v0;
            if (r1 < M) *(float2*)&C[(size_t)r1 * N + col] = v1;
        }
    }
}

// ---------------- weight prep ----------------
// grid (8 heads, 6 slots). slot: 0=A/K/e0 1=A/V/e0 2=P/K/e1 3=P/V/e1 4=P/K/e2 5=P/V/e2
__global__ __launch_bounds__(256) void prep_combine_k(
    const float* __restrict__ Wk, const float* __restrict__ bk,
    const float* __restrict__ Wv, const float* __restrict__ bv,
    const float* __restrict__ attw, const float* __restrict__ valw,
    float* __restrict__ WcatA, float* __restrict__ WcatP,
    float* __restrict__ bcatA, float* __restrict__ bcatP)
{
    __shared__ float s_hw[32 * 32];
    const int h = blockIdx.x;
    const int slot = blockIdx.y;
    const int tid = threadIdx.x;

    const bool srcA = (slot < 2);
    const bool isV = (slot & 1);
    const int et = (slot < 2) ? 0 : ((slot < 4) ? 1 : 2);

    const float* Wsrc = (isV ? Wv : Wk) + (srcA ? 0 : 65536);
    const float* bsrc = (isV ? bv : bk) + (srcA ? 0 : 256);
    const float* hw = (isV ? valw : attw) + et * 8192 + h * 1024;
    float* Wout = srcA ? WcatA : WcatP;
    float* bout = srcA ? bcatA : bcatP;
    const int ldn = srcA ? LDA_A : LDA_P;
    const int colbase = 256 + (isV ? 256 : 0) + ((slot >= 4) ? 512 : 0);

#pragma unroll
    for (int i = tid; i < 1024; i += 256) s_hw[i] = hw[i];
    __syncthreads();

    const int d = tid;
    float wrow[32];
#pragma unroll
    for (int d2 = 0; d2 < 32; d2++) wrow[d2] = Wsrc[(size_t)d * 256 + h * 32 + d2];
#pragma unroll
    for (int j = 0; j < 32; j++) {
        float acc = 0.f;
#pragma unroll
        for (int d2 = 0; d2 < 32; d2++) acc += wrow[d2] * s_hw[d2 * 32 + j];
        Wout[(size_t)d * ldn + colbase + h * 32 + j] = acc;
    }
    if (tid < 32) {
        float acc = 0.f;
#pragma unroll
        for (int d2 = 0; d2 < 32; d2++) acc += bsrc[h * 32 + d2] * s_hw[d2 * 32 + tid];
        bout[colbase + h * 32 + tid] = acc;
    }
}

__global__ void copyq_k(const float* __restrict__ Wq, const float* __restrict__ bq,
                        float* __restrict__ WcatA, float* __restrict__ WcatP,
                        float* __restrict__ bcatA, float* __restrict__ bcatP)
{
    int gid = blockIdx.x * blockDim.x + threadIdx.x;
    for (int i = gid; i < 65536; i += gridDim.x * blockDim.x) {
        int r = i >> 8, c = i & 255;
        WcatA[(size_t)r * LDA_A + c] = Wq[i];
        WcatP[(size_t)r * LDA_P + c] = Wq[65536 + i];
    }
    if (gid < 256) {
        bcatA[gid] = bq[gid];
        bcatP[gid] = bq[256 + gid];
    }
}

// ---------------- batched CSR build ----------------
__global__ void zero3_k(int* __restrict__ c0, int* __restrict__ c1, int* __restrict__ c2)
{
    int i = blockIdx.x * blockDim.x + threadIdx.x;
    if (i < NP_N) { c0[i] = 0; c1[i] = 0; }
    if (i < NA_N) c2[i] = 0;
}

__global__ void hist3_k(const int* __restrict__ d0, const int* __restrict__ d1,
                        const int* __restrict__ d2,
                        int* __restrict__ c0, int* __restrict__ c1, int* __restrict__ c2)
{
    int g = blockIdx.y;
    int i = blockIdx.x * blockDim.x + threadIdx.x;
    if (i >= E_N) return;
    const int* d = (g == 0) ? d0 : ((g == 1) ? d1 : d2);
    int* c = (g == 0) ? c0 : ((g == 1) ? c1 : c2);
    atomicAdd(&c[d[i]], 1);
}

__global__ __launch_bounds__(1024) void scan3_k(
    const int* __restrict__ cw, const int* __restrict__ cc, const int* __restrict__ ca,
    int* __restrict__ ow, int* __restrict__ oc, int* __restrict__ oa,
    int* __restrict__ uw, int* __restrict__ uc, int* __restrict__ ua)
{
    __shared__ int sh[1024];
    const int* cnt; int* off; int* cur; int n;
    if (blockIdx.x == 0) { cnt = cw; off = ow; cur = uw; n = NP_N; }
    else if (blockIdx.x == 1) { cnt = cc; off = oc; cur = uc; n = NP_N; }
    else { cnt = ca; off = oa; cur = ua; n = NA_N; }

    int t = threadIdx.x;
    int chunk = (n + 1023) >> 10;
    int s0 = t * chunk;
    int s1 = min(s0 + chunk, n);
    int sum = 0;
    for (int i = s0; i < s1; i++) sum += cnt[i];
    sh[t] = sum;
    __syncthreads();
    for (int d = 1; d < 1024; d <<= 1) {
        int v = 0;
        if (t >= d) v = sh[t - d];
        __syncthreads();
        sh[t] += v;
        __syncthreads();
    }
    int run = sh[t] - sum;
    for (int i = s0; i < s1; i++) {
        off[i] = run;
        cur[i] = run;
        run += cnt[i];
    }
    if (t == 1023) off[n] = sh[1023];
}

__global__ void scatter3_k(
    const int* __restrict__ s0, const int* __restrict__ d0,
    const int* __restrict__ s1, const int* __restrict__ d1,
    const int* __restrict__ s2, const int* __restrict__ d2,
    int* __restrict__ u0, int* __restrict__ u1, int* __restrict__ u2,
    int* __restrict__ p0, int* __restrict__ p1, int* __restrict__ p2)
{
    int g = blockIdx.y;
    int i = blockIdx.x * blockDim.x + threadIdx.x;
    if (i >= E_N) return;
    const int* s = (g == 0) ? s0 : ((g == 1) ? s1 : s2);
    const int* d = (g == 0) ? d0 : ((g == 1) ? d1 : d2);
    int* u = (g == 0) ? u0 : ((g == 1) ? u1 : u2);
    int* p = (g == 0) ? p0 : ((g == 1) ? p1 : p2);
    int pos = atomicAdd(&u[d[i]], 1);
    p[pos] = s[i];
}

// ---------------- aggregation ----------------
// warp layout: head h = lane>>2, 8-dim segment = (lane&3)*8. K at KB[src*ldkv+koff], V at +256.
__device__ __forceinline__ void agg_run(
    float4 q0, float4 q1, float cw,
    const float* __restrict__ KB, int ldkv, int koff,
    const int* __restrict__ psrc, int ebeg, int eend, float* o)
{
    float m = -3.0e38f, den = 0.f;
    float a0 = 0, a1 = 0, a2 = 0, a3 = 0, a4 = 0, a5 = 0, a6 = 0, a7 = 0;
    for (int i = ebeg; i < eend; i++) {
        int src = __ldg(&psrc[i]);
        const float* kp = KB + (size_t)src * ldkv + koff;
        float4 k0 = *(const float4*)kp;
        float4 k1 = *(const float4*)(kp + 4);
        float4 v0 = *(const float4*)(kp + 256);
        float4 v1 = *(const float4*)(kp + 260);
        float p = q0.x * k0.x + q0.y * k0.y + q0.z * k0.z + q0.w * k0.w +
                  q1.x * k1.x + q1.y * k1.y + q1.z * k1.z + q1.w * k1.w;
        p += __shfl_xor_sync(0xffffffffu, p, 1);
        p += __shfl_xor_sync(0xffffffffu, p, 2);
        float sc = p * cw;
        float mn = fmaxf(m, sc);
        float corr = __expf(m - mn);
        float w = __expf(sc - mn);
        m = mn;
        den = den * corr + w;
        a0 = a0 * corr + w * v0.x;
        a1 = a1 * corr + w * v0.y;
        a2 = a2 * corr + w * v0.z;
        a3 = a3 * corr + w * v0.w;
        a4 = a4 * corr + w * v1.x;
        a5 = a5 * corr + w * v1.y;
        a6 = a6 * corr + w * v1.z;
        a7 = a7 * corr + w * v1.w;
    }
    float r = (den > 0.f) ? (1.f / den) : 0.f;
    o[0] = a0 * r; o[1] = a1 * r; o[2] = a2 * r; o[3] = a3 * r;
    o[4] = a4 * r; o[5] = a5 * r; o[6] = a6 * r; o[7] = a7 * r;
}

__global__ __launch_bounds__(256) void agg_paper_k(
    const float* __restrict__ PP, const float* __restrict__ AP,
    const int* __restrict__ offw, const int* __restrict__ pw,
    const int* __restrict__ offc, const int* __restrict__ pc,
    const float* __restrict__ canon, float* __restrict__ OUT, int n)
{
    int gw = (blockIdx.x * blockDim.x + threadIdx.x) >> 5;
    if (gw >= n) return;
    int lane = threadIdx.x & 31;
    int h = lane >> 2;
    int seg = (lane & 3) << 3;
    int hs = h * 32 + seg;
    const float* qp = PP + (size_t)gw * LDA_P + hs;
    float4 q0 = *(const float4*)qp;
    float4 q1 = *(const float4*)(qp + 4);
    const float inv = 0.17677669529663687f;

    float ow[8], oc[8];
    agg_run(q0, q1, __ldg(&canon[h]) * inv, AP, LDA_A, 256 + hs,
            pw, __ldg(&offw[gw]), __ldg(&offw[gw + 1]), ow);
    agg_run(q0, q1, __ldg(&canon[16 + h]) * inv, PP, LDA_P, 768 + hs,
            pc, __ldg(&offc[gw]), __ldg(&offc[gw + 1]), oc);

    float* op = OUT + (size_t)gw * 256 + hs;
    *(float4*)op = make_float4(0.5f * (ow[0] + oc[0]), 0.5f * (ow[1] + oc[1]),
                               0.5f * (ow[2] + oc[2]), 0.5f * (ow[3] + oc[3]));
    *(float4*)(op + 4) = make_float4(0.5f * (ow[4] + oc[4]), 0.5f * (ow[5] + oc[5]),
                                     0.5f * (ow[6] + oc[6]), 0.5f * (ow[7] + oc[7]));
}

__global__ __launch_bounds__(256) void agg_author_k(
    const float* __restrict__ AP, const float* __restrict__ PP,
    const int* __restrict__ offa, const int* __restrict__ pa,
    const float* __restrict__ canon, float* __restrict__ OUT, int n)
{
    int gw = (blockIdx.x * blockDim.x + threadIdx.x) >> 5;
    if (gw >= n) return;
    int lane = threadIdx.x & 31;
    int h = lane >> 2;
    int seg = (lane & 3) << 3;
    int hs = h * 32 + seg;
    const float* qp = AP + (size_t)gw * LDA_A + hs;
    float4 q0 = *(const float4*)qp;
    float4 q1 = *(const float4*)(qp + 4);
    const float inv = 0.17677669529663687f;

    float o[8];
    agg_run(q0, q1, __ldg(&canon[8 + h]) * inv, PP, LDA_P, 256 + hs,
            pa, __ldg(&offa[gw]), __ldg(&offa[gw + 1]), o);

    float* op = OUT + (size_t)gw * 256 + hs;
    *(float4*)op = make_float4(o[0], o[1], o[2], o[3]);
    *(float4*)(op + 4) = make_float4(o[4], o[5], o[6], o[7]);
}

// ---------------- fused layernorm for both node types ----------------
__global__ __launch_bounds__(256) void ln2_k(
    const float* __restrict__ T0, const float* __restrict__ T1,
    const float* __restrict__ lng, const float* __restrict__ lnb,
    float* __restrict__ out)
{
    int gw = (blockIdx.x * blockDim.x + threadIdx.x) >> 5;
    if (gw >= NA_N + NP_N) return;
    int lane = threadIdx.x & 31;
    const float* src;
    const float* g;
    const float* b;
    if (gw < NA_N) { src = T0 + (size_t)gw * 256; g = lng; b = lnb; }
    else { src = T1 + (size_t)(gw - NA_N) * 256; g = lng + 256; b = lnb + 256; }

    int col = lane * 8;
    float4 v0 = *(const float4*)&src[col];
    float4 v1 = *(const float4*)&src[col + 4];
    float s = v0.x + v0.y + v0.z + v0.w + v1.x + v1.y + v1.z + v1.w;
#pragma unroll
    for (int d = 16; d; d >>= 1) s += __shfl_xor_sync(0xffffffffu, s, d);
    float mu = s * (1.f / 256.f);
    float q = (v0.x - mu) * (v0.x - mu) + (v0.y - mu) * (v0.y - mu) +
              (v0.z - mu) * (v0.z - mu) + (v0.w - mu) * (v0.w - mu) +
              (v1.x - mu) * (v1.x - mu) + (v1.y - mu) * (v1.y - mu) +
              (v1.z - mu) * (v1.z - mu) + (v1.w - mu) * (v1.w - mu);
#pragma unroll
    for (int d = 16; d; d >>= 1) q += __shfl_xor_sync(0xffffffffu, q, d);
    float inv = rsqrtf(q * (1.f / 256.f) + 1e-5f);
    float4 g0 = *(const float4*)&g[col];
    float4 g1 = *(const float4*)&g[col + 4];
    float4 b0 = *(const float4*)&b[col];
    float4 b1 = *(const float4*)&b[col + 4];
    float4 r0, r1;
    r0.x = (v0.x - mu) * inv * g0.x + b0.x;
    r0.y = (v0.y - mu) * inv * g0.y + b0.y;
    r0.z = (v0.z - mu) * inv * g0.z + b0.z;
    r0.w = (v0.w - mu) * inv * g0.w + b0.w;
    r1.x = (v1.x - mu) * inv * g1.x + b1.x;
    r1.y = (v1.y - mu) * inv * g1.y + b1.y;
    r1.z = (v1.z - mu) * inv * g1.z + b1.z;
    r1.w = (v1.w - mu) * inv * g1.w + b1.w;
    float* op = out + (size_t)gw * 256 + col;
    *(float4*)op = r0;
    *(float4*)(op + 4) = r1;
}

// ---------------- host orchestration ----------------
extern "C" void kernel_launch(void* const* d_in, const int* in_sizes, int n_in,
                              void* d_out, int out_size)
{
    const float* h_a  = (const float*)d_in[0];
    const float* h_p  = (const float*)d_in[1];
    const int* wsrc   = (const int*)d_in[2];
    const int* wdst   = (const int*)d_in[3];
    const int* wbsrc  = (const int*)d_in[4];
    const int* wbdst  = (const int*)d_in[5];
    const int* csrc   = (const int*)d_in[6];
    const int* cdst   = (const int*)d_in[7];
    const float* Wk   = (const float*)d_in[8];
    const float* bk   = (const float*)d_in[9];
    const float* Wq   = (const float*)d_in[10];
    const float* bq   = (const float*)d_in[11];
    const float* Wv   = (const float*)d_in[12];
    const float* bv   = (const float*)d_in[13];
    const float* Wfc  = (const float*)d_in[14];
    const float* bfc  = (const float*)d_in[15];
    const float* lng  = (const float*)d_in[16];
    const float* lnb  = (const float*)d_in[17];
    const float* attw = (const float*)d_in[18];
    const float* valw = (const float*)d_in[19];
    const float* canon= (const float*)d_in[20];
    const float* res  = (const float*)d_in[21];
    float* out = (float*)d_out;

    float *AP, *PP, *AGA, *AGP, *T0, *T1, *WcA, *WcP, *bcA, *bcP;
    int *cw, *cc, *ca, *ow_, *oc_, *oa_, *uw, *uc, *ua, *pw, *pc, *pa;
    cudaGetSymbolAddress((void**)&AP, g_APROJ);
    cudaGetSymbolAddress((void**)&PP, g_PPROJ);
    cudaGetSymbolAddress((void**)&AGA, g_AGA);
    cudaGetSymbolAddress((void**)&AGP, g_AGP);
    cudaGetSymbolAddress((void**)&T0, g_T0);
    cudaGetSymbolAddress((void**)&T1, g_T1);
    cudaGetSymbolAddress((void**)&WcA, g_WcatA);
    cudaGetSymbolAddress((void**)&WcP, g_WcatP);
    cudaGetSymbolAddress((void**)&bcA, g_bcatA);
    cudaGetSymbolAddress((void**)&bcP, g_bcatP);
    cudaGetSymbolAddress((void**)&cw, g_cnt_w);
    cudaGetSymbolAddress((void**)&cc, g_cnt_c);
    cudaGetSymbolAddress((void**)&ca, g_cnt_a);
    cudaGetSymbolAddress((void**)&ow_, g_off_w);
    cudaGetSymbolAddress((void**)&oc_, g_off_c);
    cudaGetSymbolAddress((void**)&oa_, g_off_a);
    cudaGetSymbolAddress((void**)&uw, g_cur_w);
    cudaGetSymbolAddress((void**)&uc, g_cur_c);
    cudaGetSymbolAddress((void**)&ua, g_cur_a);
    cudaGetSymbolAddress((void**)&pw, g_psrc_w);
    cudaGetSymbolAddress((void**)&pc, g_psrc_c);
    cudaGetSymbolAddress((void**)&pa, g_psrc_a);

    cudaFuncSetAttribute(mma_gemm_k<0>, cudaFuncAttributeMaxDynamicSharedMemorySize, GEMM_SMEM_BYTES);
    cudaFuncSetAttribute(mma_gemm_k<1>, cudaFuncAttributeMaxDynamicSharedMemorySize, GEMM_SMEM_BYTES);

    const int MB = (NA_N + 127) / 128;  // 782 (same for papers)
    const int gwA = (NA_N + 7) / 8, gwP = (NP_N + 7) / 8;
    const dim3 gEdge((E_N + 255) / 256, 3);

    // weight prep (2 launches)
    prep_combine_k<<<dim3(8, 6), 256>>>(Wk, bk, Wv, bv, attw, valw, WcA, WcP, bcA, bcP);
    copyq_k<<<128, 256>>>(Wq, bq, WcA, WcP, bcA, bcP);

    // CSR build for all 3 graphs (4 launches)
    zero3_k<<<(NP_N + 255) / 256, 256>>>(cw, cc, ca);
    hist3_k<<<gEdge, 256>>>(wdst, cdst, wbdst, cw, cc, ca);
    scan3_k<<<3, 1024>>>(cw, cc, ca, ow_, oc_, oa_, uw, uc, ua);
    scatter3_k<<<gEdge, 256>>>(wsrc, wdst, csrc, cdst, wbsrc, wbdst, uw, uc, ua, pw, pc, pa);

    // fused projections
    mma_gemm_k<0><<<dim3(LDA_A / 128, MB), 256, GEMM_SMEM_BYTES>>>(
        h_a, WcA, bcA, nullptr, nullptr, AP, NA_N, LDA_A, 1.f);
    mma_gemm_k<0><<<dim3(LDA_P / 128, MB), 256, GEMM_SMEM_BYTES>>>(
        h_p, WcP, bcP, nullptr, nullptr, PP, NP_N, LDA_P, 1.f);

    // aggregations
    agg_paper_k<<<gwP, 256>>>(PP, AP, ow_, pw, oc_, pc, canon, AGP, NP_N);
    agg_author_k<<<gwA, 256>>>(AP, PP, oa_, pa, canon, AGA, NA_N);

    // fc + residual blend
    mma_gemm_k<1><<<dim3(2, MB), 256, GEMM_SMEM_BYTES>>>(
        AGA, Wfc + 0, bfc + 0, h_a, res + 0, T0, NA_N, 256, 1.f);
    mma_gemm_k<1><<<dim3(2, MB), 256, GEMM_SMEM_BYTES>>>(
        AGP, Wfc + 65536, bfc + 256, h_p, res + 1, T1, NP_N, 256, 1.f);

    // layernorm -> output
    ln2_k<<<(NA_N + NP_N + 7) / 8, 256>>>(T0, T1, lng, lnb, out);
}

// round 4
// speedup vs baseline: 2.6132x; 1.0111x over previous
#include <cuda_runtime.h>
#include <math.h>
#include <stdint.h>

#define NA_N 100000
#define NP_N 100000
#define E_N  400000
#define D_   256
#define H_   8

#define LDA_P 1280   // paper proj row: Q | K1 | V1 | K2 | V2
#define LDA_A 768    // author proj row: Q | K0 | V0

// ---------------- static scratch ----------------
static __device__ float g_APROJ[(size_t)NA_N * LDA_A];
static __device__ float g_PPROJ[(size_t)NP_N * LDA_P];
static __device__ float g_AGA[(size_t)NA_N * D_];
static __device__ float g_AGP[(size_t)NP_N * D_];
static __device__ float g_WcatA[256 * LDA_A];
static __device__ float g_WcatP[256 * LDA_P];
static __device__ float g_bcatA[LDA_A];
static __device__ float g_bcatP[LDA_P];
static __device__ int g_cnt_w[NP_N], g_cnt_c[NP_N], g_cnt_a[NA_N];
static __device__ int g_off_w[NP_N + 1], g_off_c[NP_N + 1], g_off_a[NA_N + 1];
static __device__ int g_cur_w[NP_N], g_cur_c[NP_N], g_cur_a[NA_N];
static __device__ int g_psrc_w[E_N], g_psrc_c[E_N], g_psrc_a[E_N];

// ---------------- helpers ----------------
__device__ __forceinline__ unsigned f2tf32(float x) {
    unsigned y;
    asm("cvt.rna.tf32.f32 %0, %1;" : "=r"(y) : "f"(x));
    return y;
}
__device__ __forceinline__ float4 cvt4(float4 v) {
    float4 w;
    w.x = __uint_as_float(f2tf32(v.x));
    w.y = __uint_as_float(f2tf32(v.y));
    w.z = __uint_as_float(f2tf32(v.z));
    w.w = __uint_as_float(f2tf32(v.w));
    return w;
}
__device__ __forceinline__ void mma_tf32(float& c0, float& c1, float& c2, float& c3,
                                         unsigned a0, unsigned a1, unsigned a2, unsigned a3,
                                         unsigned b0, unsigned b1) {
    asm volatile(
        "mma.sync.aligned.m16n8k8.row.col.f32.tf32.tf32.f32 "
        "{%0,%1,%2,%3}, {%4,%5,%6,%7}, {%8,%9}, {%0,%1,%2,%3};"
        : "+f"(c0), "+f"(c1), "+f"(c2), "+f"(c3)
        : "r"(a0), "r"(a1), "r"(a2), "r"(a3), "r"(b0), "r"(b1));
}

// ---------------- pipelined TF32 GEMM (projections): C[M,N] = A[M,256]@W[256,N] + bias ----------------
// Block tile 128x128, BK=32, 2-stage smem double buffer w/ register prefetch.
#define GEMM_SMEM_BYTES ((2 * 4608 + 2 * 4352) * 4)

__global__ __launch_bounds__(256) void mma_gemm_k(
    const float* __restrict__ A, const float* __restrict__ W,
    const float* __restrict__ bias, float* __restrict__ C,
    int M, int N)
{
    extern __shared__ float sm[];
    float* As = sm;              // [2][128*36]
    float* Bs = sm + 2 * 4608;   // [2][32*136]

    const int tid = threadIdx.x;
    const int bm = blockIdx.y * 128;
    const int bn = blockIdx.x * 128;
    const int lane = tid & 31, wid = tid >> 5;
    const int warp_m = (wid & 3) * 32, warp_n = (wid >> 2) * 64;
    const int qr = lane >> 2, qc = lane & 3;

    float acc[2][8][4];
#pragma unroll
    for (int t = 0; t < 2; t++)
#pragma unroll
        for (int j = 0; j < 8; j++)
#pragma unroll
            for (int c = 0; c < 4; c++) acc[t][j][c] = 0.f;

    const int a_r0 = tid >> 3, a_c4 = (tid & 7) * 4;
    const int b_k0 = tid >> 5, b_n4 = (tid & 31) * 4;

    float4 pa[4], pb[4];

#pragma unroll
    for (int it = 0; it < 4; it++) {
        int grow = bm + a_r0 + it * 32;
        pa[it] = (grow < M) ? *(const float4*)&A[(size_t)grow * 256 + a_c4]
                            : make_float4(0.f, 0.f, 0.f, 0.f);
        pb[it] = *(const float4*)&W[(size_t)(b_k0 + it * 8) * N + bn + b_n4];
    }
#pragma unroll
    for (int it = 0; it < 4; it++) {
        *(float4*)&As[(a_r0 + it * 32) * 36 + a_c4] = cvt4(pa[it]);
        *(float4*)&Bs[(b_k0 + it * 8) * 136 + b_n4] = cvt4(pb[it]);
    }
    __syncthreads();

    int cur = 0;
#pragma unroll
    for (int it8 = 0; it8 < 8; it8++) {
        if (it8 < 7) {
            int k0 = (it8 + 1) * 32;
#pragma unroll
            for (int it = 0; it < 4; it++) {
                int grow = bm + a_r0 + it * 32;
                pa[it] = (grow < M) ? *(const float4*)&A[(size_t)grow * 256 + k0 + a_c4]
                                    : make_float4(0.f, 0.f, 0.f, 0.f);
                pb[it] = *(const float4*)&W[(size_t)(k0 + b_k0 + it * 8) * N + bn + b_n4];
            }
        }

        const float* Ac = As + cur * 4608;
        const float* Bc = Bs + cur * 4352;
#pragma unroll
        for (int ks = 0; ks < 4; ks++) {
            int kc = ks * 8 + qc;
            unsigned af[2][4];
#pragma unroll
            for (int t = 0; t < 2; t++) {
                int r = warp_m + t * 16 + qr;
                af[t][0] = __float_as_uint(Ac[r * 36 + kc]);
                af[t][1] = __float_as_uint(Ac[(r + 8) * 36 + kc]);
                af[t][2] = __float_as_uint(Ac[r * 36 + kc + 4]);
                af[t][3] = __float_as_uint(Ac[(r + 8) * 36 + kc + 4]);
            }
            unsigned bf[8][2];
#pragma unroll
            for (int j = 0; j < 8; j++) {
                int col = warp_n + j * 8 + qr;
                bf[j][0] = __float_as_uint(Bc[kc * 136 + col]);
                bf[j][1] = __float_as_uint(Bc[(kc + 4) * 136 + col]);
            }
#pragma unroll
            for (int t = 0; t < 2; t++)
#pragma unroll
                for (int j = 0; j < 8; j++)
                    mma_tf32(acc[t][j][0], acc[t][j][1], acc[t][j][2], acc[t][j][3],
                             af[t][0], af[t][1], af[t][2], af[t][3],
                             bf[j][0], bf[j][1]);
        }

        if (it8 < 7) {
            int nxt = cur ^ 1;
#pragma unroll
            for (int it = 0; it < 4; it++) {
                *(float4*)&As[nxt * 4608 + (a_r0 + it * 32) * 36 + a_c4] = cvt4(pa[it]);
                *(float4*)&Bs[nxt * 4352 + (b_k0 + it * 8) * 136 + b_n4] = cvt4(pb[it]);
            }
        }
        __syncthreads();
        cur ^= 1;
    }

#pragma unroll
    for (int t = 0; t < 2; t++) {
        int r0 = bm + warp_m + t * 16 + qr;
        int r1 = r0 + 8;
#pragma unroll
        for (int j = 0; j < 8; j++) {
            int col = bn + warp_n + j * 8 + 2 * qc;
            float2 bb = *(const float2*)&bias[col];
            float2 v0, v1;
            v0.x = acc[t][j][0] + bb.x;
            v0.y = acc[t][j][1] + bb.y;
            v1.x = acc[t][j][2] + bb.x;
            v1.y = acc[t][j][3] + bb.y;
            if (r0 < M) *(float2*)&C[(size_t)r0 * N + col] = v0;
            if (r1 < M) *(float2*)&C[(size_t)r1 * N + col] = v1;
        }
    }
}

// ---------------- fused fc + residual-blend + LayerNorm ----------------
// Block tile 64x256 (full row in one block), BK=32, 8 warps (2m x 4n).
// out_row = LN( (A@W + bias)*alpha + Hin*(1-alpha) ) * g + b
#define FC_SMEM_BYTES ((2 * 2304 + 2 * 8448) * 4)

__global__ __launch_bounds__(256) void fc_ln_k(
    const float* __restrict__ A, const float* __restrict__ W,
    const float* __restrict__ bias, const float* __restrict__ Hin,
    const float* __restrict__ resv,
    const float* __restrict__ lng, const float* __restrict__ lnb,
    float* __restrict__ out, int M)
{
    extern __shared__ float sm[];
    float* As = sm;              // [2][64*36]
    float* Bs = sm + 2 * 2304;   // [2][32*264]

    const int tid = threadIdx.x;
    const int bm = blockIdx.y * 64;
    const int lane = tid & 31, wid = tid >> 5;
    const int warp_m = (wid & 1) * 32, warp_n = (wid >> 1) * 64;
    const int wn = wid >> 1;
    const int qr = lane >> 2, qc = lane & 3;

    float acc[2][8][4];
#pragma unroll
    for (int t = 0; t < 2; t++)
#pragma unroll
        for (int j = 0; j < 8; j++)
#pragma unroll
            for (int c = 0; c < 4; c++) acc[t][j][c] = 0.f;

    // A tile 64x32: 512 float4, 2 per thread
    const int a_r0 = tid >> 3, a_c4 = (tid & 7) * 4;
    // B tile 32x256: 2048 float4, 8 per thread
    const int b_k0 = tid >> 6, b_n4 = (tid & 63) * 4;

    float4 pa[2], pb[8];

#pragma unroll
    for (int it = 0; it < 2; it++) {
        int grow = bm + a_r0 + it * 32;
        pa[it] = (grow < M) ? *(const float4*)&A[(size_t)grow * 256 + a_c4]
                            : make_float4(0.f, 0.f, 0.f, 0.f);
    }
#pragma unroll
    for (int it = 0; it < 8; it++)
        pb[it] = *(const float4*)&W[(size_t)(b_k0 + it * 4) * 256 + b_n4];
#pragma unroll
    for (int it = 0; it < 2; it++)
        *(float4*)&As[(a_r0 + it * 32) * 36 + a_c4] = cvt4(pa[it]);
#pragma unroll
    for (int it = 0; it < 8; it++)
        *(float4*)&Bs[(b_k0 + it * 4) * 264 + b_n4] = cvt4(pb[it]);
    __syncthreads();

    int cur = 0;
#pragma unroll
    for (int it8 = 0; it8 < 8; it8++) {
        if (it8 < 7) {
            int k0 = (it8 + 1) * 32;
#pragma unroll
            for (int it = 0; it < 2; it++) {
                int grow = bm + a_r0 + it * 32;
                pa[it] = (grow < M) ? *(const float4*)&A[(size_t)grow * 256 + k0 + a_c4]
                                    : make_float4(0.f, 0.f, 0.f, 0.f);
            }
#pragma unroll
            for (int it = 0; it < 8; it++)
                pb[it] = *(const float4*)&W[(size_t)(k0 + b_k0 + it * 4) * 256 + b_n4];
        }

        const float* Ac = As + cur * 2304;
        const float* Bc = Bs + cur * 8448;
#pragma unroll
        for (int ks = 0; ks < 4; ks++) {
            int kc = ks * 8 + qc;
            unsigned af[2][4];
#pragma unroll
            for (int t = 0; t < 2; t++) {
                int r = warp_m + t * 16 + qr;
                af[t][0] = __float_as_uint(Ac[r * 36 + kc]);
                af[t][1] = __float_as_uint(Ac[(r + 8) * 36 + kc]);
                af[t][2] = __float_as_uint(Ac[r * 36 + kc + 4]);
                af[t][3] = __float_as_uint(Ac[(r + 8) * 36 + kc + 4]);
            }
            unsigned bf[8][2];
#pragma unroll
            for (int j = 0; j < 8; j++) {
                int col = warp_n + j * 8 + qr;
                bf[j][0] = __float_as_uint(Bc[kc * 264 + col]);
                bf[j][1] = __float_as_uint(Bc[(kc + 4) * 264 + col]);
            }
#pragma unroll
            for (int t = 0; t < 2; t++)
#pragma unroll
                for (int j = 0; j < 8; j++)
                    mma_tf32(acc[t][j][0], acc[t][j][1], acc[t][j][2], acc[t][j][3],
                             af[t][0], af[t][1], af[t][2], af[t][3],
                             bf[j][0], bf[j][1]);
        }

        if (it8 < 7) {
            int nxt = cur ^ 1;
#pragma unroll
            for (int it = 0; it < 2; it++)
                *(float4*)&As[nxt * 2304 + (a_r0 + it * 32) * 36 + a_c4] = cvt4(pa[it]);
#pragma unroll
            for (int it = 0; it < 8; it++)
                *(float4*)&Bs[nxt * 8448 + (b_k0 + it * 4) * 264 + b_n4] = cvt4(pb[it]);
        }
        __syncthreads();
        cur ^= 1;
    }

    // ---- epilogue: blend + LN ----
    float rv = __ldg(resv);
    float alpha = 1.f / (1.f + __expf(-rv));
    float beta = 1.f - alpha;

    float s[2][2] = {{0.f, 0.f}, {0.f, 0.f}};
    float sq[2][2] = {{0.f, 0.f}, {0.f, 0.f}};

#pragma unroll
    for (int t = 0; t < 2; t++) {
        int lr0 = warp_m + t * 16 + qr;
        int g0 = bm + lr0, g1 = g0 + 8;
#pragma unroll
        for (int j = 0; j < 8; j++) {
            int col = warp_n + j * 8 + 2 * qc;
            float2 bb = *(const float2*)&bias[col];
            float x0 = acc[t][j][0] + bb.x;
            float y0 = acc[t][j][1] + bb.y;
            float x1 = acc[t][j][2] + bb.x;
            float y1 = acc[t][j][3] + bb.y;
            if (g0 < M) {
                float2 h = *(const float2*)&Hin[(size_t)g0 * 256 + col];
                x0 = x0 * alpha + h.x * beta;
                y0 = y0 * alpha + h.y * beta;
            }
            if (g1 < M) {
                float2 h = *(const float2*)&Hin[(size_t)g1 * 256 + col];
                x1 = x1 * alpha + h.x * beta;
                y1 = y1 * alpha + h.y * beta;
            }
            acc[t][j][0] = x0; acc[t][j][1] = y0;
            acc[t][j][2] = x1; acc[t][j][3] = y1;
            s[t][0] += x0 + y0;
            s[t][1] += x1 + y1;
            sq[t][0] += x0 * x0 + y0 * y0;
            sq[t][1] += x1 * x1 + y1 * y1;
        }
    }

    // reduce across the 4 qc lanes
#pragma unroll
    for (int t = 0; t < 2; t++)
#pragma unroll
        for (int r = 0; r < 2; r++) {
            s[t][r] += __shfl_xor_sync(0xffffffffu, s[t][r], 1);
            s[t][r] += __shfl_xor_sync(0xffffffffu, s[t][r], 2);
            sq[t][r] += __shfl_xor_sync(0xffffffffu, sq[t][r], 1);
            sq[t][r] += __shfl_xor_sync(0xffffffffu, sq[t][r], 2);
        }

    float* red = As;  // reuse: red_s[64][4] at [0..255], red_q[64][4] at [256..511]
    if (qc == 0) {
#pragma unroll
        for (int t = 0; t < 2; t++) {
            int lr0 = warp_m + t * 16 + qr;
            red[lr0 * 4 + wn] = s[t][0];
            red[(lr0 + 8) * 4 + wn] = s[t][1];
            red[256 + lr0 * 4 + wn] = sq[t][0];
            red[256 + (lr0 + 8) * 4 + wn] = sq[t][1];
        }
    }
    __syncthreads();

#pragma unroll
    for (int t = 0; t < 2; t++) {
        int lr0 = warp_m + t * 16 + qr;
        int lr1 = lr0 + 8;
        float ts0 = red[lr0 * 4 + 0] + red[lr0 * 4 + 1] + red[lr0 * 4 + 2] + red[lr0 * 4 + 3];
        float ts1 = red[lr1 * 4 + 0] + red[lr1 * 4 + 1] + red[lr1 * 4 + 2] + red[lr1 * 4 + 3];
        float tq0 = red[256 + lr0 * 4 + 0] + red[256 + lr0 * 4 + 1] +
                    red[256 + lr0 * 4 + 2] + red[256 + lr0 * 4 + 3];
        float tq1 = red[256 + lr1 * 4 + 0] + red[256 + lr1 * 4 + 1] +
                    red[256 + lr1 * 4 + 2] + red[256 + lr1 * 4 + 3];
        float mu0 = ts0 * (1.f / 256.f);
        float mu1 = ts1 * (1.f / 256.f);
        float var0 = fmaxf(tq0 * (1.f / 256.f) - mu0 * mu0, 0.f);
        float var1 = fmaxf(tq1 * (1.f / 256.f) - mu1 * mu1, 0.f);
        float iv0 = rsqrtf(var0 + 1e-5f);
        float iv1 = rsqrtf(var1 + 1e-5f);
        int g0 = bm + lr0, g1 = bm + lr1;
#pragma unroll
        for (int j = 0; j < 8; j++) {
            int col = warp_n + j * 8 + 2 * qc;
            float2 gg = *(const float2*)&lng[col];
            float2 bb = *(const float2*)&lnb[col];
            if (g0 < M) {
                float2 r;
                r.x = (acc[t][j][0] - mu0) * iv0 * gg.x + bb.x;
                r.y = (acc[t][j][1] - mu0) * iv0 * gg.y + bb.y;
                *(float2*)&out[(size_t)g0 * 256 + col] = r;
            }
            if (g1 < M) {
                float2 r;
                r.x = (acc[t][j][2] - mu1) * iv1 * gg.x + bb.x;
                r.y = (acc[t][j][3] - mu1) * iv1 * gg.y + bb.y;
                *(float2*)&out[(size_t)g1 * 256 + col] = r;
            }
        }
    }
}

// ---------------- weight prep ----------------
__global__ __launch_bounds__(256) void prep_combine_k(
    const float* __restrict__ Wk, const float* __restrict__ bk,
    const float* __restrict__ Wv, const float* __restrict__ bv,
    const float* __restrict__ attw, const float* __restrict__ valw,
    float* __restrict__ WcatA, float* __restrict__ WcatP,
    float* __restrict__ bcatA, float* __restrict__ bcatP)
{
    __shared__ float s_hw[32 * 32];
    const int h = blockIdx.x;
    const int slot = blockIdx.y;
    const int tid = threadIdx.x;

    const bool srcA = (slot < 2);
    const bool isV = (slot & 1);
    const int et = (slot < 2) ? 0 : ((slot < 4) ? 1 : 2);

    const float* Wsrc = (isV ? Wv : Wk) + (srcA ? 0 : 65536);
    const float* bsrc = (isV ? bv : bk) + (srcA ? 0 : 256);
    const float* hw = (isV ? valw : attw) + et * 8192 + h * 1024;
    float* Wout = srcA ? WcatA : WcatP;
    float* bout = srcA ? bcatA : bcatP;
    const int ldn = srcA ? LDA_A : LDA_P;
    const int colbase = 256 + (isV ? 256 : 0) + ((slot >= 4) ? 512 : 0);

#pragma unroll
    for (int i = tid; i < 1024; i += 256) s_hw[i] = hw[i];
    __syncthreads();

    const int d = tid;
    float wrow[32];
#pragma unroll
    for (int d2 = 0; d2 < 32; d2++) wrow[d2] = Wsrc[(size_t)d * 256 + h * 32 + d2];
#pragma unroll
    for (int j = 0; j < 32; j++) {
        float acc = 0.f;
#pragma unroll
        for (int d2 = 0; d2 < 32; d2++) acc += wrow[d2] * s_hw[d2 * 32 + j];
        Wout[(size_t)d * ldn + colbase + h * 32 + j] = acc;
    }
    if (tid < 32) {
        float acc = 0.f;
#pragma unroll
        for (int d2 = 0; d2 < 32; d2++) acc += bsrc[h * 32 + d2] * s_hw[d2 * 32 + tid];
        bout[colbase + h * 32 + tid] = acc;
    }
}

__global__ void copyq_k(const float* __restrict__ Wq, const float* __restrict__ bq,
                        float* __restrict__ WcatA, float* __restrict__ WcatP,
                        float* __restrict__ bcatA, float* __restrict__ bcatP)
{
    int gid = blockIdx.x * blockDim.x + threadIdx.x;
    for (int i = gid; i < 65536; i += gridDim.x * blockDim.x) {
        int r = i >> 8, c = i & 255;
        WcatA[(size_t)r * LDA_A + c] = Wq[i];
        WcatP[(size_t)r * LDA_P + c] = Wq[65536 + i];
    }
    if (gid < 256) {
        bcatA[gid] = bq[gid];
        bcatP[gid] = bq[256 + gid];
    }
}

// ---------------- batched CSR build ----------------
__global__ void zero3_k(int* __restrict__ c0, int* __restrict__ c1, int* __restrict__ c2)
{
    int i = blockIdx.x * blockDim.x + threadIdx.x;
    if (i < NP_N) { c0[i] = 0; c1[i] = 0; }
    if (i < NA_N) c2[i] = 0;
}

__global__ void hist3_k(const int* __restrict__ d0, const int* __restrict__ d1,
                        const int* __restrict__ d2,
                        int* __restrict__ c0, int* __restrict__ c1, int* __restrict__ c2)
{
    int g = blockIdx.y;
    int i = blockIdx.x * blockDim.x + threadIdx.x;
    if (i >= E_N) return;
    const int* d = (g == 0) ? d0 : ((g == 1) ? d1 : d2);
    int* c = (g == 0) ? c0 : ((g == 1) ? c1 : c2);
    atomicAdd(&c[d[i]], 1);
}

__global__ __launch_bounds__(1024) void scan3_k(
    const int* __restrict__ cw, const int* __restrict__ cc, const int* __restrict__ ca,
    int* __restrict__ ow, int* __restrict__ oc, int* __restrict__ oa,
    int* __restrict__ uw, int* __restrict__ uc, int* __restrict__ ua)
{
    __shared__ int sh[1024];
    const int* cnt; int* off; int* cur; int n;
    if (blockIdx.x == 0) { cnt = cw; off = ow; cur = uw; n = NP_N; }
    else if (blockIdx.x == 1) { cnt = cc; off = oc; cur = uc; n = NP_N; }
    else { cnt = ca; off = oa; cur = ua; n = NA_N; }

    int t = threadIdx.x;
    int chunk = (n + 1023) >> 10;
    int s0 = t * chunk;
    int s1 = min(s0 + chunk, n);
    int sum = 0;
    for (int i = s0; i < s1; i++) sum += cnt[i];
    sh[t] = sum;
    __syncthreads();
    for (int d = 1; d < 1024; d <<= 1) {
        int v = 0;
        if (t >= d) v = sh[t - d];
        __syncthreads();
        sh[t] += v;
        __syncthreads();
    }
    int run = sh[t] - sum;
    for (int i = s0; i < s1; i++) {
        off[i] = run;
        cur[i] = run;
        run += cnt[i];
    }
    if (t == 1023) off[n] = sh[1023];
}

__global__ void scatter3_k(
    const int* __restrict__ s0, const int* __restrict__ d0,
    const int* __restrict__ s1, const int* __restrict__ d1,
    const int* __restrict__ s2, const int* __restrict__ d2,
    int* __restrict__ u0, int* __restrict__ u1, int* __restrict__ u2,
    int* __restrict__ p0, int* __restrict__ p1, int* __restrict__ p2)
{
    int g = blockIdx.y;
    int i = blockIdx.x * blockDim.x + threadIdx.x;
    if (i >= E_N) return;
    const int* s = (g == 0) ? s0 : ((g == 1) ? s1 : s2);
    const int* d = (g == 0) ? d0 : ((g == 1) ? d1 : d2);
    int* u = (g == 0) ? u0 : ((g == 1) ? u1 : u2);
    int* p = (g == 0) ? p0 : ((g == 1) ? p1 : p2);
    int pos = atomicAdd(&u[d[i]], 1);
    p[pos] = s[i];
}

// ---------------- aggregation (software-pipelined gather) ----------------
// warp layout: head h = lane>>2, 8-dim segment = (lane&3)*8. K at KB[src*ldkv+koff], V at +256.
__device__ __forceinline__ void agg_run(
    float4 q0, float4 q1, float cw,
    const float* __restrict__ KB, int ldkv, int koff,
    const int* __restrict__ psrc, int ebeg, int eend, float* o)
{
    float m = -3.0e38f, den = 0.f;
    float a0 = 0, a1 = 0, a2 = 0, a3 = 0, a4 = 0, a5 = 0, a6 = 0, a7 = 0;

    if (ebeg < eend) {
        int src = __ldg(&psrc[ebeg]);
        const float* kp = KB + (size_t)src * ldkv + koff;
        float4 k0 = *(const float4*)kp;
        float4 k1 = *(const float4*)(kp + 4);
        float4 v0 = *(const float4*)(kp + 256);
        float4 v1 = *(const float4*)(kp + 260);

        for (int i = ebeg; ; ) {
            // prefetch next edge before the serial softmax chain
            bool more = (i + 1 < eend);
            float4 nk0, nk1, nv0, nv1;
            if (more) {
                int nsrc = __ldg(&psrc[i + 1]);
                const float* np = KB + (size_t)nsrc * ldkv + koff;
                nk0 = *(const float4*)np;
                nk1 = *(const float4*)(np + 4);
                nv0 = *(const float4*)(np + 256);
                nv1 = *(const float4*)(np + 260);
            }

            float p = q0.x * k0.x + q0.y * k0.y + q0.z * k0.z + q0.w * k0.w +
                      q1.x * k1.x + q1.y * k1.y + q1.z * k1.z + q1.w * k1.w;
            p += __shfl_xor_sync(0xffffffffu, p, 1);
            p += __shfl_xor_sync(0xffffffffu, p, 2);
            float sc = p * cw;
            float mn = fmaxf(m, sc);
            float corr = __expf(m - mn);
            float w = __expf(sc - mn);
            m = mn;
            den = den * corr + w;
            a0 = a0 * corr + w * v0.x;
            a1 = a1 * corr + w * v0.y;
            a2 = a2 * corr + w * v0.z;
            a3 = a3 * corr + w * v0.w;
            a4 = a4 * corr + w * v1.x;
            a5 = a5 * corr + w * v1.y;
            a6 = a6 * corr + w * v1.z;
            a7 = a7 * corr + w * v1.w;

            if (!more) break;
            k0 = nk0; k1 = nk1; v0 = nv0; v1 = nv1;
            i++;
        }
    }
    float r = (den > 0.f) ? (1.f / den) : 0.f;
    o[0] = a0 * r; o[1] = a1 * r; o[2] = a2 * r; o[3] = a3 * r;
    o[4] = a4 * r; o[5] = a5 * r; o[6] = a6 * r; o[7] = a7 * r;
}

__global__ __launch_bounds__(256) void agg_paper_k(
    const float* __restrict__ PP, const float* __restrict__ AP,
    const int* __restrict__ offw, const int* __restrict__ pw,
    const int* __restrict__ offc, const int* __restrict__ pc,
    const float* __restrict__ canon, float* __restrict__ OUT, int n)
{
    int gw = (blockIdx.x * blockDim.x + threadIdx.x) >> 5;
    if (gw >= n) return;
    int lane = threadIdx.x & 31;
    int h = lane >> 2;
    int seg = (lane & 3) << 3;
    int hs = h * 32 + seg;
    const float* qp = PP + (size_t)gw * LDA_P + hs;
    float4 q0 = *(const float4*)qp;
    float4 q1 = *(const float4*)(qp + 4);
    const float inv = 0.17677669529663687f;

    float ow[8], oc[8];
    agg_run(q0, q1, __ldg(&canon[h]) * inv, AP, LDA_A, 256 + hs,
            pw, __ldg(&offw[gw]), __ldg(&offw[gw + 1]), ow);
    agg_run(q0, q1, __ldg(&canon[16 + h]) * inv, PP, LDA_P, 768 + hs,
            pc, __ldg(&offc[gw]), __ldg(&offc[gw + 1]), oc);

    float* op = OUT + (size_t)gw * 256 + hs;
    *(float4*)op = make_float4(0.5f * (ow[0] + oc[0]), 0.5f * (ow[1] + oc[1]),
                               0.5f * (ow[2] + oc[2]), 0.5f * (ow[3] + oc[3]));
    *(float4*)(op + 4) = make_float4(0.5f * (ow[4] + oc[4]), 0.5f * (ow[5] + oc[5]),
                                     0.5f * (ow[6] + oc[6]), 0.5f * (ow[7] + oc[7]));
}

__global__ __launch_bounds__(256) void agg_author_k(
    const float* __restrict__ AP, const float* __restrict__ PP,
    const int* __restrict__ offa, const int* __restrict__ pa,
    const float* __restrict__ canon, float* __restrict__ OUT, int n)
{
    int gw = (blockIdx.x * blockDim.x + threadIdx.x) >> 5;
    if (gw >= n) return;
    int lane = threadIdx.x & 31;
    int h = lane >> 2;
    int seg = (lane & 3) << 3;
    int hs = h * 32 + seg;
    const float* qp = AP + (size_t)gw * LDA_A + hs;
    float4 q0 = *(const float4*)qp;
    float4 q1 = *(const float4*)(qp + 4);
    const float inv = 0.17677669529663687f;

    float o[8];
    agg_run(q0, q1, __ldg(&canon[8 + h]) * inv, PP, LDA_P, 256 + hs,
            pa, __ldg(&offa[gw]), __ldg(&offa[gw + 1]), o);

    float* op = OUT + (size_t)gw * 256 + hs;
    *(float4*)op = make_float4(o[0], o[1], o[2], o[3]);
    *(float4*)(op + 4) = make_float4(o[4], o[5], o[6], o[7]);
}

// ---------------- host orchestration ----------------
extern "C" void kernel_launch(void* const* d_in, const int* in_sizes, int n_in,
                              void* d_out, int out_size)
{
    const float* h_a  = (const float*)d_in[0];
    const float* h_p  = (const float*)d_in[1];
    const int* wsrc   = (const int*)d_in[2];
    const int* wdst   = (const int*)d_in[3];
    const int* wbsrc  = (const int*)d_in[4];
    const int* wbdst  = (const int*)d_in[5];
    const int* csrc   = (const int*)d_in[6];
    const int* cdst   = (const int*)d_in[7];
    const float* Wk   = (const float*)d_in[8];
    const float* bk   = (const float*)d_in[9];
    const float* Wq   = (const float*)d_in[10];
    const float* bq   = (const float*)d_in[11];
    const float* Wv   = (const float*)d_in[12];
    const float* bv   = (const float*)d_in[13];
    const float* Wfc  = (const float*)d_in[14];
    const float* bfc  = (const float*)d_in[15];
    const float* lng  = (const float*)d_in[16];
    const float* lnb  = (const float*)d_in[17];
    const float* attw = (const float*)d_in[18];
    const float* valw = (const float*)d_in[19];
    const float* canon= (const float*)d_in[20];
    const float* res  = (const float*)d_in[21];
    float* out = (float*)d_out;

    float *AP, *PP, *AGA, *AGP, *WcA, *WcP, *bcA, *bcP;
    int *cw, *cc, *ca, *ow_, *oc_, *oa_, *uw, *uc, *ua, *pw, *pc, *pa;
    cudaGetSymbolAddress((void**)&AP, g_APROJ);
    cudaGetSymbolAddress((void**)&PP, g_PPROJ);
    cudaGetSymbolAddress((void**)&AGA, g_AGA);
    cudaGetSymbolAddress((void**)&AGP, g_AGP);
    cudaGetSymbolAddress((void**)&WcA, g_WcatA);
    cudaGetSymbolAddress((void**)&WcP, g_WcatP);
    cudaGetSymbolAddress((void**)&bcA, g_bcatA);
    cudaGetSymbolAddress((void**)&bcP, g_bcatP);
    cudaGetSymbolAddress((void**)&cw, g_cnt_w);
    cudaGetSymbolAddress((void**)&cc, g_cnt_c);
    cudaGetSymbolAddress((void**)&ca, g_cnt_a);
    cudaGetSymbolAddress((void**)&ow_, g_off_w);
    cudaGetSymbolAddress((void**)&oc_, g_off_c);
    cudaGetSymbolAddress((void**)&oa_, g_off_a);
    cudaGetSymbolAddress((void**)&uw, g_cur_w);
    cudaGetSymbolAddress((void**)&uc, g_cur_c);
    cudaGetSymbolAddress((void**)&ua, g_cur_a);
    cudaGetSymbolAddress((void**)&pw, g_psrc_w);
    cudaGetSymbolAddress((void**)&pc, g_psrc_c);
    cudaGetSymbolAddress((void**)&pa, g_psrc_a);

    cudaFuncSetAttribute(mma_gemm_k, cudaFuncAttributeMaxDynamicSharedMemorySize, GEMM_SMEM_BYTES);
    cudaFuncSetAttribute(fc_ln_k, cudaFuncAttributeMaxDynamicSharedMemorySize, FC_SMEM_BYTES);

    const int MB = (NA_N + 127) / 128;   // 782
    const int MB64 = (NA_N + 63) / 64;   // 1563
    const int gwA = (NA_N + 7) / 8, gwP = (NP_N + 7) / 8;
    const dim3 gEdge((E_N + 255) / 256, 3);

    // weight prep
    prep_combine_k<<<dim3(8, 6), 256>>>(Wk, bk, Wv, bv, attw, valw, WcA, WcP, bcA, bcP);
    copyq_k<<<128, 256>>>(Wq, bq, WcA, WcP, bcA, bcP);

    // CSR build for all 3 graphs
    zero3_k<<<(NP_N + 255) / 256, 256>>>(cw, cc, ca);
    hist3_k<<<gEdge, 256>>>(wdst, cdst, wbdst, cw, cc, ca);
    scan3_k<<<3, 1024>>>(cw, cc, ca, ow_, oc_, oa_, uw, uc, ua);
    scatter3_k<<<gEdge, 256>>>(wsrc, wdst, csrc, cdst, wbsrc, wbdst, uw, uc, ua, pw, pc, pa);

    // fused projections
    mma_gemm_k<<<dim3(LDA_A / 128, MB), 256, GEMM_SMEM_BYTES>>>(h_a, WcA, bcA, AP, NA_N, LDA_A);
    mma_gemm_k<<<dim3(LDA_P / 128, MB), 256, GEMM_SMEM_BYTES>>>(h_p, WcP, bcP, PP, NP_N, LDA_P);

    // aggregations
    agg_paper_k<<<gwP, 256>>>(PP, AP, ow_, pw, oc_, pc, canon, AGP, NP_N);
    agg_author_k<<<gwA, 256>>>(AP, PP, oa_, pa, canon, AGA, NA_N);

    // fc + residual blend + LN, written straight to output
    fc_ln_k<<<dim3(1, MB64), 256, FC_SMEM_BYTES>>>(
        AGA, Wfc + 0, bfc + 0, h_a, res + 0, lng + 0, lnb + 0, out, NA_N);
    fc_ln_k<<<dim3(1, MB64), 256, FC_SMEM_BYTES>>>(
        AGP, Wfc + 65536, bfc + 256, h_p, res + 1, lng + 256, lnb + 256,
        out + (size_t)NA_N * D_, NP_N);
}

// round 10
// speedup vs baseline: 2.7949x; 1.0695x over previous
#include <cuda_runtime.h>
#include <math.h>
#include <stdint.h>

#define NA_N 100000
#define NP_N 100000
#define E_N  400000
#define D_   256
#define H_   8

#define LDA_P 1280   // paper proj row: Q | K1 | V1 | K2 | V2
#define LDA_A 768    // author proj row: Q | K0 | V0

// ---------------- static scratch ----------------
static __device__ float g_APROJ[(size_t)NA_N * LDA_A];
static __device__ float g_PPROJ[(size_t)NP_N * LDA_P];
static __device__ float g_AGA[(size_t)NA_N * D_];
static __device__ float g_AGP[(size_t)NP_N * D_];
static __device__ float g_WcatA[256 * LDA_A];   // [k][n]
static __device__ float g_WcatP[256 * LDA_P];   // [k][n]
static __device__ float g_bcatA[LDA_A];
static __device__ float g_bcatP[LDA_P];
static __device__ int g_cnt_w[NP_N], g_cnt_c[NP_N], g_cnt_a[NA_N];
static __device__ int g_off_w[NP_N + 1], g_off_c[NP_N + 1], g_off_a[NA_N + 1];
static __device__ int g_cur_w[NP_N], g_cur_c[NP_N], g_cur_a[NA_N];
static __device__ int g_psrc_w[E_N], g_psrc_c[E_N], g_psrc_a[E_N];

// ---------------- helpers ----------------
// pack two fp32 into half2 (lo, hi)
__device__ __forceinline__ unsigned f2h2(float lo, float hi) {
    unsigned r;
    asm("cvt.rn.f16x2.f32 %0, %1, %2;" : "=r"(r) : "f"(hi), "f"(lo));
    return r;
}
__device__ __forceinline__ void mma_f16(float& c0, float& c1, float& c2, float& c3,
                                        unsigned a0, unsigned a1, unsigned a2, unsigned a3,
                                        unsigned b0, unsigned b1) {
    asm volatile(
        "mma.sync.aligned.m16n8k16.row.col.f32.f16.f16.f32 "
        "{%0,%1,%2,%3}, {%4,%5,%6,%7}, {%8,%9}, {%0,%1,%2,%3};"
        : "+f"(c0), "+f"(c1), "+f"(c2), "+f"(c3)
        : "r"(a0), "r"(a1), "r"(a2), "r"(a3), "r"(b0), "r"(b1));
}

// ---------------- FP16 tensor GEMM (projections): C[M,N] = A[M,256]@W[256,N] + bias ----------------
// Block tile 128x128, BK=32, 8 warps (4m x 2n), warp tile 32x64, mma m16n8k16.
// SMEM: A as half2 [row][kpair] ld=20; B as half2 k-pair-packed [kpair][n] ld=136.
#define A2_SZ 2560   // 128*20
#define B2_SZ 2176   // 16*136
#define GEMM_SMEM_BYTES (2 * (A2_SZ + B2_SZ) * 4)

__global__ __launch_bounds__(256) void mma_gemm_k(
    const float* __restrict__ A, const float* __restrict__ W,
    const float* __restrict__ bias, float* __restrict__ C,
    int M, int N)
{
    extern __shared__ unsigned smu[];
    unsigned* As2 = smu;              // [2][A2_SZ]
    unsigned* Bs2 = smu + 2 * A2_SZ;  // [2][B2_SZ]

    const int tid = threadIdx.x;
    const int bm = blockIdx.y * 128;
    const int bn = blockIdx.x * 128;
    const int lane = tid & 31, wid = tid >> 5;
    const int warp_m = (wid & 3) * 32, warp_n = (wid >> 2) * 64;
    const int qr = lane >> 2, qc = lane & 3;

    float acc[2][8][4];
#pragma unroll
    for (int t = 0; t < 2; t++)
#pragma unroll
        for (int j = 0; j < 8; j++)
#pragma unroll
            for (int c = 0; c < 4; c++) acc[t][j][c] = 0.f;

    // A loader: 4 iters, row = a_r0 + 32*it, 4 floats at col a_c4
    const int a_r0 = tid >> 3, a_c4 = (tid & 7) * 4;
    // B loader: 2 iters, kpair row kr = b_kr + 8*it, 4 cols at b_n4; reads W rows 2kr, 2kr+1
    const int b_kr = tid >> 5, b_n4 = (tid & 31) * 4;

    float4 pa[4], pb0[2], pb1[2];

    // prologue k0 = 0
#pragma unroll
    for (int it = 0; it < 4; it++) {
        int grow = bm + a_r0 + it * 32;
        pa[it] = (grow < M) ? *(const float4*)&A[(size_t)grow * 256 + a_c4]
                            : make_float4(0.f, 0.f, 0.f, 0.f);
    }
#pragma unroll
    for (int it = 0; it < 2; it++) {
        int kr = b_kr + it * 8;
        pb0[it] = *(const float4*)&W[(size_t)(2 * kr) * N + bn + b_n4];
        pb1[it] = *(const float4*)&W[(size_t)(2 * kr + 1) * N + bn + b_n4];
    }
#pragma unroll
    for (int it = 0; it < 4; it++) {
        uint2 h;
        h.x = f2h2(pa[it].x, pa[it].y);
        h.y = f2h2(pa[it].z, pa[it].w);
        *(uint2*)&As2[(a_r0 + it * 32) * 20 + (a_c4 >> 1)] = h;
    }
#pragma unroll
    for (int it = 0; it < 2; it++) {
        int kr = b_kr + it * 8;
        uint4 h;
        h.x = f2h2(pb0[it].x, pb1[it].x);
        h.y = f2h2(pb0[it].y, pb1[it].y);
        h.z = f2h2(pb0[it].z, pb1[it].z);
        h.w = f2h2(pb0[it].w, pb1[it].w);
        *(uint4*)&Bs2[kr * 136 + b_n4] = h;
    }
    __syncthreads();

    int cur = 0;
#pragma unroll
    for (int it8 = 0; it8 < 8; it8++) {
        if (it8 < 7) {
            int k0 = (it8 + 1) * 32;
#pragma unroll
            for (int it = 0; it < 4; it++) {
                int grow = bm + a_r0 + it * 32;
                pa[it] = (grow < M) ? *(const float4*)&A[(size_t)grow * 256 + k0 + a_c4]
                                    : make_float4(0.f, 0.f, 0.f, 0.f);
            }
#pragma unroll
            for (int it = 0; it < 2; it++) {
                int kr = b_kr + it * 8;
                pb0[it] = *(const float4*)&W[(size_t)(k0 + 2 * kr) * N + bn + b_n4];
                pb1[it] = *(const float4*)&W[(size_t)(k0 + 2 * kr + 1) * N + bn + b_n4];
            }
        }

        const unsigned* Ac = As2 + cur * A2_SZ;
        const unsigned* Bc = Bs2 + cur * B2_SZ;
#pragma unroll
        for (int s = 0; s < 2; s++) {
            const int kb = s * 8;
            unsigned af[2][4];
#pragma unroll
            for (int t = 0; t < 2; t++) {
                int r = warp_m + t * 16 + qr;
                af[t][0] = Ac[r * 20 + kb + qc];
                af[t][1] = Ac[(r + 8) * 20 + kb + qc];
                af[t][2] = Ac[r * 20 + kb + qc + 4];
                af[t][3] = Ac[(r + 8) * 20 + kb + qc + 4];
            }
            unsigned bf[8][2];
#pragma unroll
            for (int j = 0; j < 8; j++) {
                int col = warp_n + j * 8 + qr;
                bf[j][0] = Bc[(kb + qc) * 136 + col];
                bf[j][1] = Bc[(kb + qc + 4) * 136 + col];
            }
#pragma unroll
            for (int t = 0; t < 2; t++)
#pragma unroll
                for (int j = 0; j < 8; j++)
                    mma_f16(acc[t][j][0], acc[t][j][1], acc[t][j][2], acc[t][j][3],
                            af[t][0], af[t][1], af[t][2], af[t][3],
                            bf[j][0], bf[j][1]);
        }

        if (it8 < 7) {
            int nxt = cur ^ 1;
#pragma unroll
            for (int it = 0; it < 4; it++) {
                uint2 h;
                h.x = f2h2(pa[it].x, pa[it].y);
                h.y = f2h2(pa[it].z, pa[it].w);
                *(uint2*)&As2[nxt * A2_SZ + (a_r0 + it * 32) * 20 + (a_c4 >> 1)] = h;
            }
#pragma unroll
            for (int it = 0; it < 2; it++) {
                int kr = b_kr + it * 8;
                uint4 h;
                h.x = f2h2(pb0[it].x, pb1[it].x);
                h.y = f2h2(pb0[it].y, pb1[it].y);
                h.z = f2h2(pb0[it].z, pb1[it].z);
                h.w = f2h2(pb0[it].w, pb1[it].w);
                *(uint4*)&Bs2[nxt * B2_SZ + kr * 136 + b_n4] = h;
            }
        }
        __syncthreads();
        cur ^= 1;
    }

#pragma unroll
    for (int t = 0; t < 2; t++) {
        int r0 = bm + warp_m + t * 16 + qr;
        int r1 = r0 + 8;
#pragma unroll
        for (int j = 0; j < 8; j++) {
            int col = bn + warp_n + j * 8 + 2 * qc;
            float2 bb = *(const float2*)&bias[col];
            float2 v0, v1;
            v0.x = acc[t][j][0] + bb.x;
            v0.y = acc[t][j][1] + bb.y;
            v1.x = acc[t][j][2] + bb.x;
            v1.y = acc[t][j][3] + bb.y;
            if (r0 < M) *(float2*)&C[(size_t)r0 * N + col] = v0;
            if (r1 < M) *(float2*)&C[(size_t)r1 * N + col] = v1;
        }
    }
}

// ---------------- fused fc + residual-blend + LayerNorm (fp16 mma) ----------------
// Block tile 64x256, BK=32, 8 warps (2m x 4n), warp tile 32x64.
#define FA2_SZ 1280  // 64*20
#define FB2_SZ 4224  // 16*264
#define FC_SMEM_BYTES (2 * (FA2_SZ + FB2_SZ) * 4)

__global__ __launch_bounds__(256) void fc_ln_k(
    const float* __restrict__ A, const float* __restrict__ W,
    const float* __restrict__ bias, const float* __restrict__ Hin,
    const float* __restrict__ resv,
    const float* __restrict__ lng, const float* __restrict__ lnb,
    float* __restrict__ out, int M)
{
    extern __shared__ unsigned smu[];
    unsigned* As2 = smu;               // [2][FA2_SZ]
    unsigned* Bs2 = smu + 2 * FA2_SZ;  // [2][FB2_SZ]

    const int tid = threadIdx.x;
    const int bm = blockIdx.y * 64;
    const int lane = tid & 31, wid = tid >> 5;
    const int warp_m = (wid & 1) * 32, warp_n = (wid >> 1) * 64;
    const int wn = wid >> 1;
    const int qr = lane >> 2, qc = lane & 3;

    float acc[2][8][4];
#pragma unroll
    for (int t = 0; t < 2; t++)
#pragma unroll
        for (int j = 0; j < 8; j++)
#pragma unroll
            for (int c = 0; c < 4; c++) acc[t][j][c] = 0.f;

    // A loader: 2 iters, rows 64 (a_r0 + 32*it)
    const int a_r0 = tid >> 3, a_c4 = (tid & 7) * 4;
    // B loader: 4 iters; kr = b_kr0 + it*4 (0..15), n4 = (tid&63)*4
    const int b_kr0 = tid >> 6, b_n4 = (tid & 63) * 4;

    float4 pa[2], pb0[4], pb1[4];

#pragma unroll
    for (int it = 0; it < 2; it++) {
        int grow = bm + a_r0 + it * 32;
        pa[it] = (grow < M) ? *(const float4*)&A[(size_t)grow * 256 + a_c4]
                            : make_float4(0.f, 0.f, 0.f, 0.f);
    }
#pragma unroll
    for (int it = 0; it < 4; it++) {
        int kr = b_kr0 + it * 4;
        pb0[it] = *(const float4*)&W[(size_t)(2 * kr) * 256 + b_n4];
        pb1[it] = *(const float4*)&W[(size_t)(2 * kr + 1) * 256 + b_n4];
    }
#pragma unroll
    for (int it = 0; it < 2; it++) {
        uint2 h;
        h.x = f2h2(pa[it].x, pa[it].y);
        h.y = f2h2(pa[it].z, pa[it].w);
        *(uint2*)&As2[(a_r0 + it * 32) * 20 + (a_c4 >> 1)] = h;
    }
#pragma unroll
    for (int it = 0; it < 4; it++) {
        int kr = b_kr0 + it * 4;
        uint4 h;
        h.x = f2h2(pb0[it].x, pb1[it].x);
        h.y = f2h2(pb0[it].y, pb1[it].y);
        h.z = f2h2(pb0[it].z, pb1[it].z);
        h.w = f2h2(pb0[it].w, pb1[it].w);
        *(uint4*)&Bs2[kr * 264 + b_n4] = h;
    }
    __syncthreads();

    int cur = 0;
#pragma unroll
    for (int it8 = 0; it8 < 8; it8++) {
        if (it8 < 7) {
            int k0 = (it8 + 1) * 32;
#pragma unroll
            for (int it = 0; it < 2; it++) {
                int grow = bm + a_r0 + it * 32;
                pa[it] = (grow < M) ? *(const float4*)&A[(size_t)grow * 256 + k0 + a_c4]
                                    : make_float4(0.f, 0.f, 0.f, 0.f);
            }
#pragma unroll
            for (int it = 0; it < 4; it++) {
                int kr = b_kr0 + it * 4;
                pb0[it] = *(const float4*)&W[(size_t)(k0 + 2 * kr) * 256 + b_n4];
                pb1[it] = *(const float4*)&W[(size_t)(k0 + 2 * kr + 1) * 256 + b_n4];
            }
        }

        const unsigned* Ac = As2 + cur * FA2_SZ;
        const unsigned* Bc = Bs2 + cur * FB2_SZ;
#pragma unroll
        for (int s = 0; s < 2; s++) {
            const int kb = s * 8;
            unsigned af[2][4];
#pragma unroll
            for (int t = 0; t < 2; t++) {
                int r = warp_m + t * 16 + qr;
                af[t][0] = Ac[r * 20 + kb + qc];
                af[t][1] = Ac[(r + 8) * 20 + kb + qc];
                af[t][2] = Ac[r * 20 + kb + qc + 4];
                af[t][3] = Ac[(r + 8) * 20 + kb + qc + 4];
            }
            unsigned bf[8][2];
#pragma unroll
            for (int j = 0; j < 8; j++) {
                int col = warp_n + j * 8 + qr;
                bf[j][0] = Bc[(kb + qc) * 264 + col];
                bf[j][1] = Bc[(kb + qc + 4) * 264 + col];
            }
#pragma unroll
            for (int t = 0; t < 2; t++)
#pragma unroll
                for (int j = 0; j < 8; j++)
                    mma_f16(acc[t][j][0], acc[t][j][1], acc[t][j][2], acc[t][j][3],
                            af[t][0], af[t][1], af[t][2], af[t][3],
                            bf[j][0], bf[j][1]);
        }

        if (it8 < 7) {
            int nxt = cur ^ 1;
#pragma unroll
            for (int it = 0; it < 2; it++) {
                uint2 h;
                h.x = f2h2(pa[it].x, pa[it].y);
                h.y = f2h2(pa[it].z, pa[it].w);
                *(uint2*)&As2[nxt * FA2_SZ + (a_r0 + it * 32) * 20 + (a_c4 >> 1)] = h;
            }
#pragma unroll
            for (int it = 0; it < 4; it++) {
                int kr = b_kr0 + it * 4;
                uint4 h;
                h.x = f2h2(pb0[it].x, pb1[it].x);
                h.y = f2h2(pb0[it].y, pb1[it].y);
                h.z = f2h2(pb0[it].z, pb1[it].z);
                h.w = f2h2(pb0[it].w, pb1[it].w);
                *(uint4*)&Bs2[nxt * FB2_SZ + kr * 264 + b_n4] = h;
            }
        }
        __syncthreads();
        cur ^= 1;
    }

    float rv = __ldg(resv);
    float alpha = 1.f / (1.f + __expf(-rv));
    float beta = 1.f - alpha;

    float s[2][2] = {{0.f, 0.f}, {0.f, 0.f}};
    float sq[2][2] = {{0.f, 0.f}, {0.f, 0.f}};

#pragma unroll
    for (int t = 0; t < 2; t++) {
        int lr0 = warp_m + t * 16 + qr;
        int g0 = bm + lr0, g1 = g0 + 8;
#pragma unroll
        for (int j = 0; j < 8; j++) {
            int col = warp_n + j * 8 + 2 * qc;
            float2 bb = *(const float2*)&bias[col];
            float x0 = acc[t][j][0] + bb.x;
            float y0 = acc[t][j][1] + bb.y;
            float x1 = acc[t][j][2] + bb.x;
            float y1 = acc[t][j][3] + bb.y;
            if (g0 < M) {
                float2 h = *(const float2*)&Hin[(size_t)g0 * 256 + col];
                x0 = x0 * alpha + h.x * beta;
                y0 = y0 * alpha + h.y * beta;
            }
            if (g1 < M) {
                float2 h = *(const float2*)&Hin[(size_t)g1 * 256 + col];
                x1 = x1 * alpha + h.x * beta;
                y1 = y1 * alpha + h.y * beta;
            }
            acc[t][j][0] = x0; acc[t][j][1] = y0;
            acc[t][j][2] = x1; acc[t][j][3] = y1;
            s[t][0] += x0 + y0;
            s[t][1] += x1 + y1;
            sq[t][0] += x0 * x0 + y0 * y0;
            sq[t][1] += x1 * x1 + y1 * y1;
        }
    }

#pragma unroll
    for (int t = 0; t < 2; t++)
#pragma unroll
        for (int r = 0; r < 2; r++) {
            s[t][r] += __shfl_xor_sync(0xffffffffu, s[t][r], 1);
            s[t][r] += __shfl_xor_sync(0xffffffffu, s[t][r], 2);
            sq[t][r] += __shfl_xor_sync(0xffffffffu, sq[t][r], 1);
            sq[t][r] += __shfl_xor_sync(0xffffffffu, sq[t][r], 2);
        }

    float* red = (float*)smu;  // reuse smem: red_s[64][4], red_q at +256
    if (qc == 0) {
#pragma unroll
        for (int t = 0; t < 2; t++) {
            int lr0 = warp_m + t * 16 + qr;
            red[lr0 * 4 + wn] = s[t][0];
            red[(lr0 + 8) * 4 + wn] = s[t][1];
            red[256 + lr0 * 4 + wn] = sq[t][0];
            red[256 + (lr0 + 8) * 4 + wn] = sq[t][1];
        }
    }
    __syncthreads();

#pragma unroll
    for (int t = 0; t < 2; t++) {
        int lr0 = warp_m + t * 16 + qr;
        int lr1 = lr0 + 8;
        float ts0 = red[lr0 * 4 + 0] + red[lr0 * 4 + 1] + red[lr0 * 4 + 2] + red[lr0 * 4 + 3];
        float ts1 = red[lr1 * 4 + 0] + red[lr1 * 4 + 1] + red[lr1 * 4 + 2] + red[lr1 * 4 + 3];
        float tq0 = red[256 + lr0 * 4 + 0] + red[256 + lr0 * 4 + 1] +
                    red[256 + lr0 * 4 + 2] + red[256 + lr0 * 4 + 3];
        float tq1 = red[256 + lr1 * 4 + 0] + red[256 + lr1 * 4 + 1] +
                    red[256 + lr1 * 4 + 2] + red[256 + lr1 * 4 + 3];
        float mu0 = ts0 * (1.f / 256.f);
        float mu1 = ts1 * (1.f / 256.f);
        float var0 = fmaxf(tq0 * (1.f / 256.f) - mu0 * mu0, 0.f);
        float var1 = fmaxf(tq1 * (1.f / 256.f) - mu1 * mu1, 0.f);
        float iv0 = rsqrtf(var0 + 1e-5f);
        float iv1 = rsqrtf(var1 + 1e-5f);
        int g0 = bm + lr0, g1 = bm + lr1;
#pragma unroll
        for (int j = 0; j < 8; j++) {
            int col = warp_n + j * 8 + 2 * qc;
            float2 gg = *(const float2*)&lng[col];
            float2 bb = *(const float2*)&lnb[col];
            if (g0 < M) {
                float2 r;
                r.x = (acc[t][j][0] - mu0) * iv0 * gg.x + bb.x;
                r.y = (acc[t][j][1] - mu0) * iv0 * gg.y + bb.y;
                *(float2*)&out[(size_t)g0 * 256 + col] = r;
            }
            if (g1 < M) {
                float2 r;
                r.x = (acc[t][j][2] - mu1) * iv1 * gg.x + bb.x;
                r.y = (acc[t][j][3] - mu1) * iv1 * gg.y + bb.y;
                *(float2*)&out[(size_t)g1 * 256 + col] = r;
            }
        }
    }
}

// ---------------- weight prep ([k][n] layout) ----------------
__global__ __launch_bounds__(256) void prep_combine_k(
    const float* __restrict__ Wk, const float* __restrict__ bk,
    const float* __restrict__ Wv, const float* __restrict__ bv,
    const float* __restrict__ attw, const float* __restrict__ valw,
    float* __restrict__ WcatA, float* __restrict__ WcatP,
    float* __restrict__ bcatA, float* __restrict__ bcatP)
{
    __shared__ float s_hw[32 * 32];
    const int h = blockIdx.x;
    const int slot = blockIdx.y;
    const int tid = threadIdx.x;

    const bool srcA = (slot < 2);
    const bool isV = (slot & 1);
    const int et = (slot < 2) ? 0 : ((slot < 4) ? 1 : 2);

    const float* Wsrc = (isV ? Wv : Wk) + (srcA ? 0 : 65536);
    const float* bsrc = (isV ? bv : bk) + (srcA ? 0 : 256);
    const float* hw = (isV ? valw : attw) + et * 8192 + h * 1024;
    float* Wout = srcA ? WcatA : WcatP;
    float* bout = srcA ? bcatA : bcatP;
    const int ldn = srcA ? LDA_A : LDA_P;
    const int colbase = 256 + (isV ? 256 : 0) + ((slot >= 4) ? 512 : 0);

#pragma unroll
    for (int i = tid; i < 1024; i += 256) s_hw[i] = hw[i];
    __syncthreads();

    const int d = tid;
    float wrow[32];
#pragma unroll
    for (int d2 = 0; d2 < 32; d2++) wrow[d2] = Wsrc[(size_t)d * 256 + h * 32 + d2];
#pragma unroll
    for (int j = 0; j < 32; j++) {
        float acc = 0.f;
#pragma unroll
        for (int d2 = 0; d2 < 32; d2++) acc += wrow[d2] * s_hw[d2 * 32 + j];
        Wout[(size_t)d * ldn + colbase + h * 32 + j] = acc;
    }
    if (tid < 32) {
        float acc = 0.f;
#pragma unroll
        for (int d2 = 0; d2 < 32; d2++) acc += bsrc[h * 32 + d2] * s_hw[d2 * 32 + tid];
        bout[colbase + h * 32 + tid] = acc;
    }
}

__global__ void copyq_k(const float* __restrict__ Wq, const float* __restrict__ bq,
                        float* __restrict__ WcatA, float* __restrict__ WcatP,
                        float* __restrict__ bcatA, float* __restrict__ bcatP)
{
    int gid = blockIdx.x * blockDim.x + threadIdx.x;
    for (int i = gid; i < 65536; i += gridDim.x * blockDim.x) {
        int r = i >> 8, c = i & 255;
        WcatA[(size_t)r * LDA_A + c] = Wq[i];
        WcatP[(size_t)r * LDA_P + c] = Wq[65536 + i];
    }
    if (gid < 256) {
        bcatA[gid] = bq[gid];
        bcatP[gid] = bq[256 + gid];
    }
}

// ---------------- batched CSR build ----------------
__global__ void zero3_k(int* __restrict__ c0, int* __restrict__ c1, int* __restrict__ c2)
{
    int i = blockIdx.x * blockDim.x + threadIdx.x;
    if (i < NP_N) { c0[i] = 0; c1[i] = 0; }
    if (i < NA_N) c2[i] = 0;
}

__global__ void hist3_k(const int* __restrict__ d0, const int* __restrict__ d1,
                        const int* __restrict__ d2,
                        int* __restrict__ c0, int* __restrict__ c1, int* __restrict__ c2)
{
    int g = blockIdx.y;
    int i = blockIdx.x * blockDim.x + threadIdx.x;
    if (i >= E_N) return;
    const int* d = (g == 0) ? d0 : ((g == 1) ? d1 : d2);
    int* c = (g == 0) ? c0 : ((g == 1) ? c1 : c2);
    atomicAdd(&c[d[i]], 1);
}

__global__ __launch_bounds__(1024) void scan3_k(
    const int* __restrict__ cw, const int* __restrict__ cc, const int* __restrict__ ca,
    int* __restrict__ ow, int* __restrict__ oc, int* __restrict__ oa,
    int* __restrict__ uw, int* __restrict__ uc, int* __restrict__ ua)
{
    __shared__ int sh[1024];
    const int* cnt; int* off; int* cur; int n;
    if (blockIdx.x == 0) { cnt = cw; off = ow; cur = uw; n = NP_N; }
    else if (blockIdx.x == 1) { cnt = cc; off = oc; cur = uc; n = NP_N; }
    else { cnt = ca; off = oa; cur = ua; n = NA_N; }

    int t = threadIdx.x;
    int chunk = (n + 1023) >> 10;
    int s0 = t * chunk;
    int s1 = min(s0 + chunk, n);
    int sum = 0;
    for (int i = s0; i < s1; i++) sum += cnt[i];
    sh[t] = sum;
    __syncthreads();
    for (int d = 1; d < 1024; d <<= 1) {
        int v = 0;
        if (t >= d) v = sh[t - d];
        __syncthreads();
        sh[t] += v;
        __syncthreads();
    }
    int run = sh[t] - sum;
    for (int i = s0; i < s1; i++) {
        off[i] = run;
        cur[i] = run;
        run += cnt[i];
    }
    if (t == 1023) off[n] = sh[1023];
}

__global__ void scatter3_k(
    const int* __restrict__ s0, const int* __restrict__ d0,
    const int* __restrict__ s1, const int* __restrict__ d1,
    const int* __restrict__ s2, const int* __restrict__ d2,
    int* __restrict__ u0, int* __restrict__ u1, int* __restrict__ u2,
    int* __restrict__ p0, int* __restrict__ p1, int* __restrict__ p2)
{
    int g = blockIdx.y;
    int i = blockIdx.x * blockDim.x + threadIdx.x;
    if (i >= E_N) return;
    const int* s = (g == 0) ? s0 : ((g == 1) ? s1 : s2);
    const int* d = (g == 0) ? d0 : ((g == 1) ? d1 : d2);
    int* u = (g == 0) ? u0 : ((g == 1) ? u1 : u2);
    int* p = (g == 0) ? p0 : ((g == 1) ? p1 : p2);
    int pos = atomicAdd(&u[d[i]], 1);
    p[pos] = s[i];
}

// ---------------- aggregation (software-pipelined gather) ----------------
__device__ __forceinline__ void agg_run(
    float4 q0, float4 q1, float cw,
    const float* __restrict__ KB, int ldkv, int koff,
    const int* __restrict__ psrc, int ebeg, int eend, float* o)
{
    float m = -3.0e38f, den = 0.f;
    float a0 = 0, a1 = 0, a2 = 0, a3 = 0, a4 = 0, a5 = 0, a6 = 0, a7 = 0;

    if (ebeg < eend) {
        int src = __ldg(&psrc[ebeg]);
        const float* kp = KB + (size_t)src * ldkv + koff;
        float4 k0 = *(const float4*)kp;
        float4 k1 = *(const float4*)(kp + 4);
        float4 v0 = *(const float4*)(kp + 256);
        float4 v1 = *(const float4*)(kp + 260);

        for (int i = ebeg; ; ) {
            bool more = (i + 1 < eend);
            float4 nk0, nk1, nv0, nv1;
            if (more) {
                int nsrc = __ldg(&psrc[i + 1]);
                const float* np = KB + (size_t)nsrc * ldkv + koff;
                nk0 = *(const float4*)np;
                nk1 = *(const float4*)(np + 4);
                nv0 = *(const float4*)(np + 256);
                nv1 = *(const float4*)(np + 260);
            }

            float p = q0.x * k0.x + q0.y * k0.y + q0.z * k0.z + q0.w * k0.w +
                      q1.x * k1.x + q1.y * k1.y + q1.z * k1.z + q1.w * k1.w;
            p += __shfl_xor_sync(0xffffffffu, p, 1);
            p += __shfl_xor_sync(0xffffffffu, p, 2);
            float sc = p * cw;
            float mn = fmaxf(m, sc);
            float corr = __expf(m - mn);
            float w = __expf(sc - mn);
            m = mn;
            den = den * corr + w;
            a0 = a0 * corr + w * v0.x;
            a1 = a1 * corr + w * v0.y;
            a2 = a2 * corr + w * v0.z;
            a3 = a3 * corr + w * v0.w;
            a4 = a4 * corr + w * v1.x;
            a5 = a5 * corr + w * v1.y;
            a6 = a6 * corr + w * v1.z;
            a7 = a7 * corr + w * v1.w;

            if (!more) break;
            k0 = nk0; k1 = nk1; v0 = nv0; v1 = nv1;
            i++;
        }
    }
    float r = (den > 0.f) ? (1.f / den) : 0.f;
    o[0] = a0 * r; o[1] = a1 * r; o[2] = a2 * r; o[3] = a3 * r;
    o[4] = a4 * r; o[5] = a5 * r; o[6] = a6 * r; o[7] = a7 * r;
}

__global__ __launch_bounds__(256) void agg_paper_k(
    const float* __restrict__ PP, const float* __restrict__ AP,
    const int* __restrict__ offw, const int* __restrict__ pw,
    const int* __restrict__ offc, const int* __restrict__ pc,
    const float* __restrict__ canon, float* __restrict__ OUT, int n)
{
    int gw = (blockIdx.x * blockDim.x + threadIdx.x) >> 5;
    if (gw >= n) return;
    int lane = threadIdx.x & 31;
    int h = lane >> 2;
    int seg = (lane & 3) << 3;
    int hs = h * 32 + seg;
    const float* qp = PP + (size_t)gw * LDA_P + hs;
    float4 q0 = *(const float4*)qp;
    float4 q1 = *(const float4*)(qp + 4);
    const float inv = 0.17677669529663687f;

    float ow[8], oc[8];
    agg_run(q0, q1, __ldg(&canon[h]) * inv, AP, LDA_A, 256 + hs,
            pw, __ldg(&offw[gw]), __ldg(&offw[gw + 1]), ow);
    agg_run(q0, q1, __ldg(&canon[16 + h]) * inv, PP, LDA_P, 768 + hs,
            pc, __ldg(&offc[gw]), __ldg(&offc[gw + 1]), oc);

    float* op = OUT + (size_t)gw * 256 + hs;
    *(float4*)op = make_float4(0.5f * (ow[0] + oc[0]), 0.5f * (ow[1] + oc[1]),
                               0.5f * (ow[2] + oc[2]), 0.5f * (ow[3] + oc[3]));
    *(float4*)(op + 4) = make_float4(0.5f * (ow[4] + oc[4]), 0.5f * (ow[5] + oc[5]),
                                     0.5f * (ow[6] + oc[6]), 0.5f * (ow[7] + oc[7]));
}

__global__ __launch_bounds__(256) void agg_author_k(
    const float* __restrict__ AP, const float* __restrict__ PP,
    const int* __restrict__ offa, const int* __restrict__ pa,
    const float* __restrict__ canon, float* __restrict__ OUT, int n)
{
    int gw = (blockIdx.x * blockDim.x + threadIdx.x) >> 5;
    if (gw >= n) return;
    int lane = threadIdx.x & 31;
    int h = lane >> 2;
    int seg = (lane & 3) << 3;
    int hs = h * 32 + seg;
    const float* qp = AP + (size_t)gw * LDA_A + hs;
    float4 q0 = *(const float4*)qp;
    float4 q1 = *(const float4*)(qp + 4);
    const float inv = 0.17677669529663687f;

    float o[8];
    agg_run(q0, q1, __ldg(&canon[8 + h]) * inv, PP, LDA_P, 256 + hs,
            pa, __ldg(&offa[gw]), __ldg(&offa[gw + 1]), o);

    float* op = OUT + (size_t)gw * 256 + hs;
    *(float4*)op = make_float4(o[0], o[1], o[2], o[3]);
    *(float4*)(op + 4) = make_float4(o[4], o[5], o[6], o[7]);
}

// ---------------- host orchestration ----------------
extern "C" void kernel_launch(void* const* d_in, const int* in_sizes, int n_in,
                              void* d_out, int out_size)
{
    const float* h_a  = (const float*)d_in[0];
    const float* h_p  = (const float*)d_in[1];
    const int* wsrc   = (const int*)d_in[2];
    const int* wdst   = (const int*)d_in[3];
    const int* wbsrc  = (const int*)d_in[4];
    const int* wbdst  = (const int*)d_in[5];
    const int* csrc   = (const int*)d_in[6];
    const int* cdst   = (const int*)d_in[7];
    const float* Wk   = (const float*)d_in[8];
    const float* bk   = (const float*)d_in[9];
    const float* Wq   = (const float*)d_in[10];
    const float* bq   = (const float*)d_in[11];
    const float* Wv   = (const float*)d_in[12];
    const float* bv   = (const float*)d_in[13];
    const float* Wfc  = (const float*)d_in[14];
    const float* bfc  = (const float*)d_in[15];
    const float* lng  = (const float*)d_in[16];
    const float* lnb  = (const float*)d_in[17];
    const float* attw = (const float*)d_in[18];
    const float* valw = (const float*)d_in[19];
    const float* canon= (const float*)d_in[20];
    const float* res  = (const float*)d_in[21];
    float* out = (float*)d_out;

    float *AP, *PP, *AGA, *AGP, *WcA, *WcP, *bcA, *bcP;
    int *cw, *cc, *ca, *ow_, *oc_, *oa_, *uw, *uc, *ua, *pw, *pc, *pa;
    cudaGetSymbolAddress((void**)&AP, g_APROJ);
    cudaGetSymbolAddress((void**)&PP, g_PPROJ);
    cudaGetSymbolAddress((void**)&AGA, g_AGA);
    cudaGetSymbolAddress((void**)&AGP, g_AGP);
    cudaGetSymbolAddress((void**)&WcA, g_WcatA);
    cudaGetSymbolAddress((void**)&WcP, g_WcatP);
    cudaGetSymbolAddress((void**)&bcA, g_bcatA);
    cudaGetSymbolAddress((void**)&bcP, g_bcatP);
    cudaGetSymbolAddress((void**)&cw, g_cnt_w);
    cudaGetSymbolAddress((void**)&cc, g_cnt_c);
    cudaGetSymbolAddress((void**)&ca, g_cnt_a);
    cudaGetSymbolAddress((void**)&ow_, g_off_w);
    cudaGetSymbolAddress((void**)&oc_, g_off_c);
    cudaGetSymbolAddress((void**)&oa_, g_off_a);
    cudaGetSymbolAddress((void**)&uw, g_cur_w);
    cudaGetSymbolAddress((void**)&uc, g_cur_c);
    cudaGetSymbolAddress((void**)&ua, g_cur_a);
    cudaGetSymbolAddress((void**)&pw, g_psrc_w);
    cudaGetSymbolAddress((void**)&pc, g_psrc_c);
    cudaGetSymbolAddress((void**)&pa, g_psrc_a);

    cudaFuncSetAttribute(mma_gemm_k, cudaFuncAttributeMaxDynamicSharedMemorySize, GEMM_SMEM_BYTES);
    cudaFuncSetAttribute(fc_ln_k, cudaFuncAttributeMaxDynamicSharedMemorySize, FC_SMEM_BYTES);

    const int MB = (NA_N + 127) / 128;   // 782
    const int MB64 = (NA_N + 63) / 64;   // 1563
    const int gwA = (NA_N + 7) / 8, gwP = (NP_N + 7) / 8;
    const dim3 gEdge((E_N + 255) / 256, 3);

    // weight prep
    prep_combine_k<<<dim3(8, 6), 256>>>(Wk, bk, Wv, bv, attw, valw, WcA, WcP, bcA, bcP);
    copyq_k<<<128, 256>>>(Wq, bq, WcA, WcP, bcA, bcP);

    // CSR build for all 3 graphs
    zero3_k<<<(NP_N + 255) / 256, 256>>>(cw, cc, ca);
    hist3_k<<<gEdge, 256>>>(wdst, cdst, wbdst, cw, cc, ca);
    scan3_k<<<3, 1024>>>(cw, cc, ca, ow_, oc_, oa_, uw, uc, ua);
    scatter3_k<<<gEdge, 256>>>(wsrc, wdst, csrc, cdst, wbsrc, wbdst, uw, uc, ua, pw, pc, pa);

    // fused projections (fp16 tensor cores)
    mma_gemm_k<<<dim3(LDA_A / 128, MB), 256, GEMM_SMEM_BYTES>>>(h_a, WcA, bcA, AP, NA_N, LDA_A);
    mma_gemm_k<<<dim3(LDA_P / 128, MB), 256, GEMM_SMEM_BYTES>>>(h_p, WcP, bcP, PP, NP_N, LDA_P);

    // aggregations
    agg_paper_k<<<gwP, 256>>>(PP, AP, ow_, pw, oc_, pc, canon, AGP, NP_N);
    agg_author_k<<<gwA, 256>>>(AP, PP, oa_, pa, canon, AGA, NA_N);

    // fc + residual blend + LN -> output
    fc_ln_k<<<dim3(1, MB64), 256, FC_SMEM_BYTES>>>(
        AGA, Wfc + 0, bfc + 0, h_a, res + 0, lng + 0, lnb + 0, out, NA_N);
    fc_ln_k<<<dim3(1, MB64), 256, FC_SMEM_BYTES>>>(
        AGP, Wfc + 65536, bfc + 256, h_p, res + 1, lng + 256, lnb + 256,
        out + (size_t)NA_N * D_, NP_N);
}

// round 15
// speedup vs baseline: 3.2840x; 1.1750x over previous
#include <cuda_runtime.h>
#include <math.h>
#include <stdint.h>

#define NA_N 100000
#define NP_N 100000
#define E_N  400000
#define D_   256
#define H_   8

#define LDA_P 1280   // paper proj row: Q | K1 | V1 | K2 | V2
#define LDA_A 768    // author proj row: Q | K0 | V0

// ---------------- static scratch ----------------
static __device__ float g_APROJ[(size_t)NA_N * LDA_A];
static __device__ float g_PPROJ[(size_t)NP_N * LDA_P];
static __device__ float g_AGA[(size_t)NA_N * D_];
static __device__ float g_AGP[(size_t)NP_N * D_];
static __device__ unsigned g_Ah[(size_t)NA_N * 128];      // h_a as half2 pairs
static __device__ unsigned g_Ph[(size_t)NP_N * 128];      // h_p as half2 pairs
static __device__ unsigned g_WuA[128 * LDA_A];            // weights half2: [kpair][n]
static __device__ unsigned g_WuP[128 * LDA_P];
static __device__ float g_bcatA[LDA_A];
static __device__ float g_bcatP[LDA_P];
static __device__ int g_cnt_w[NP_N], g_cnt_c[NP_N], g_cnt_a[NA_N];
static __device__ int g_off_w[NP_N + 1], g_off_c[NP_N + 1], g_off_a[NA_N + 1];
static __device__ int g_cur_w[NP_N], g_cur_c[NP_N], g_cur_a[NA_N];
static __device__ int g_psrc_w[E_N], g_psrc_c[E_N], g_psrc_a[E_N];

// ---------------- helpers ----------------
__device__ __forceinline__ unsigned f2h2(float lo, float hi) {
    unsigned r;
    asm("cvt.rn.f16x2.f32 %0, %1, %2;" : "=r"(r) : "f"(hi), "f"(lo));
    return r;
}
__device__ __forceinline__ void mma_f16(float& c0, float& c1, float& c2, float& c3,
                                        unsigned a0, unsigned a1, unsigned a2, unsigned a3,
                                        unsigned b0, unsigned b1) {
    asm volatile(
        "mma.sync.aligned.m16n8k16.row.col.f32.f16.f16.f32 "
        "{%0,%1,%2,%3}, {%4,%5,%6,%7}, {%8,%9}, {%0,%1,%2,%3};"
        : "+f"(c0), "+f"(c1), "+f"(c2), "+f"(c3)
        : "r"(a0), "r"(a1), "r"(a2), "r"(a3), "r"(b0), "r"(b1));
}
__device__ __forceinline__ void ldsm_x4(unsigned& r0, unsigned& r1, unsigned& r2, unsigned& r3,
                                        unsigned saddr) {
    asm volatile("ldmatrix.sync.aligned.m8n8.x4.shared.b16 {%0,%1,%2,%3}, [%4];"
                 : "=r"(r0), "=r"(r1), "=r"(r2), "=r"(r3) : "r"(saddr));
}

// ---------------- pre-pass: fp32 -> packed half2 ----------------
__global__ void tohalf_k(const float* __restrict__ a, const float* __restrict__ p,
                         unsigned* __restrict__ ah, unsigned* __restrict__ ph)
{
    const int total = NA_N * 64;  // float4 count per tensor
    for (int i = blockIdx.x * blockDim.x + threadIdx.x; i < total; i += gridDim.x * blockDim.x) {
        float4 va = ((const float4*)a)[i];
        float4 vp = ((const float4*)p)[i];
        uint2 ua, up;
        ua.x = f2h2(va.x, va.y); ua.y = f2h2(va.z, va.w);
        up.x = f2h2(vp.x, vp.y); up.y = f2h2(vp.z, vp.w);
        ((uint2*)ah)[i] = ua;
        ((uint2*)ph)[i] = up;
    }
}

// ---------------- FP16 tensor GEMM (projections): C[M,N] = Ah@Wu + bias ----------------
// Block tile 128x128, BK=32, 8 warps (4m x 2n), warp tile 32x64, mma m16n8k16.
// Ah: [row][kpair] packed half2 (128 uints/row). Wu: [kpair][n] packed half2 (N uints/row).
// SMEM: A [row][kpair] ld=20; B [kpair][n] ld=136. A frags via ldmatrix.x4.
#define A2_SZ 2560   // 128*20
#define B2_SZ 2176   // 16*136
#define GEMM_SMEM_BYTES (2 * (A2_SZ + B2_SZ) * 4)

__global__ __launch_bounds__(256) void mma_gemm_k(
    const unsigned* __restrict__ Ah, const unsigned* __restrict__ Wu,
    const float* __restrict__ bias, float* __restrict__ C,
    int M, int N)
{
    extern __shared__ unsigned smu[];
    unsigned* As2 = smu;              // [2][A2_SZ]
    unsigned* Bs2 = smu + 2 * A2_SZ;  // [2][B2_SZ]

    const int tid = threadIdx.x;
    const int bm = blockIdx.y * 128;
    const int bn = blockIdx.x * 128;
    const int lane = tid & 31, wid = tid >> 5;
    const int warp_m = (wid & 3) * 32, warp_n = (wid >> 2) * 64;
    const int qr = lane >> 2, qc = lane & 3;
    const int lrow = lane & 15;            // ldmatrix address row-within-32
    const int lcol4 = (lane >> 4) * 4;     // ldmatrix address col group
    const unsigned sb_a = (unsigned)__cvta_generic_to_shared(As2);

    float acc[2][8][4];
#pragma unroll
    for (int t = 0; t < 2; t++)
#pragma unroll
        for (int j = 0; j < 8; j++)
#pragma unroll
            for (int c = 0; c < 4; c++) acc[t][j][c] = 0.f;

    // A loader: idx -> row = tid>>2 (0..63 +64), g4 = (tid&3)*4
    const int a_row = tid >> 2, a_g4 = (tid & 3) * 4;
    // B loader: kr = tid>>5 (+8), n4 = (tid&31)*4
    const int b_kr = tid >> 5, b_n4 = (tid & 31) * 4;

    uint4 pa[2], pb[2];
    const uint4 z4 = make_uint4(0, 0, 0, 0);

    // prologue k0 = 0
#pragma unroll
    for (int it = 0; it < 2; it++) {
        int row = a_row + it * 64;
        int grow = bm + row;
        pa[it] = (grow < M) ? *(const uint4*)&Ah[(size_t)grow * 128 + a_g4] : z4;
        int kr = b_kr + it * 8;
        pb[it] = *(const uint4*)&Wu[(size_t)kr * N + bn + b_n4];
    }
#pragma unroll
    for (int it = 0; it < 2; it++) {
        *(uint4*)&As2[(a_row + it * 64) * 20 + a_g4] = pa[it];
        *(uint4*)&Bs2[(b_kr + it * 8) * 136 + b_n4] = pb[it];
    }
    __syncthreads();

    int cur = 0;
#pragma unroll
    for (int it8 = 0; it8 < 8; it8++) {
        if (it8 < 7) {
            int kp0 = (it8 + 1) * 16;  // kpair offset of next chunk
#pragma unroll
            for (int it = 0; it < 2; it++) {
                int row = a_row + it * 64;
                int grow = bm + row;
                pa[it] = (grow < M) ? *(const uint4*)&Ah[(size_t)grow * 128 + kp0 + a_g4] : z4;
                int kr = b_kr + it * 8;
                pb[it] = *(const uint4*)&Wu[(size_t)(kp0 + kr) * N + bn + b_n4];
            }
        }

        const unsigned abase = sb_a + (unsigned)(cur * A2_SZ) * 4u;
        const unsigned* Bc = Bs2 + cur * B2_SZ;
#pragma unroll
        for (int s = 0; s < 2; s++) {
            const int kb = s * 8;
            unsigned af[2][4];
#pragma unroll
            for (int t = 0; t < 2; t++) {
                unsigned addr = abase + (unsigned)((warp_m + t * 16 + lrow) * 20 + kb + lcol4) * 4u;
                ldsm_x4(af[t][0], af[t][1], af[t][2], af[t][3], addr);
            }
            unsigned bf[8][2];
#pragma unroll
            for (int j = 0; j < 8; j++) {
                int col = warp_n + j * 8 + qr;
                bf[j][0] = Bc[(kb + qc) * 136 + col];
                bf[j][1] = Bc[(kb + qc + 4) * 136 + col];
            }
#pragma unroll
            for (int t = 0; t < 2; t++)
#pragma unroll
                for (int j = 0; j < 8; j++)
                    mma_f16(acc[t][j][0], acc[t][j][1], acc[t][j][2], acc[t][j][3],
                            af[t][0], af[t][1], af[t][2], af[t][3],
                            bf[j][0], bf[j][1]);
        }

        if (it8 < 7) {
            int nxt = cur ^ 1;
#pragma unroll
            for (int it = 0; it < 2; it++) {
                *(uint4*)&As2[nxt * A2_SZ + (a_row + it * 64) * 20 + a_g4] = pa[it];
                *(uint4*)&Bs2[nxt * B2_SZ + (b_kr + it * 8) * 136 + b_n4] = pb[it];
            }
        }
        __syncthreads();
        cur ^= 1;
    }

#pragma unroll
    for (int t = 0; t < 2; t++) {
        int r0 = bm + warp_m + t * 16 + qr;
        int r1 = r0 + 8;
#pragma unroll
        for (int j = 0; j < 8; j++) {
            int col = bn + warp_n + j * 8 + 2 * qc;
            float2 bb = *(const float2*)&bias[col];
            float2 v0, v1;
            v0.x = acc[t][j][0] + bb.x;
            v0.y = acc[t][j][1] + bb.y;
            v1.x = acc[t][j][2] + bb.x;
            v1.y = acc[t][j][3] + bb.y;
            if (r0 < M) *(float2*)&C[(size_t)r0 * N + col] = v0;
            if (r1 < M) *(float2*)&C[(size_t)r1 * N + col] = v1;
        }
    }
}

// ---------------- fused fc + residual-blend + LayerNorm (fp16 mma, fp32 inputs) ----------------
// Block tile 64x256, BK=32, 8 warps (2m x 4n), warp tile 32x64.
#define FA2_SZ 1280  // 64*20
#define FB2_SZ 4224  // 16*264
#define FC_SMEM_BYTES (2 * (FA2_SZ + FB2_SZ) * 4)

__global__ __launch_bounds__(256) void fc_ln_k(
    const float* __restrict__ A, const float* __restrict__ W,
    const float* __restrict__ bias, const float* __restrict__ Hin,
    const float* __restrict__ resv,
    const float* __restrict__ lng, const float* __restrict__ lnb,
    float* __restrict__ out, int M)
{
    extern __shared__ unsigned smu[];
    unsigned* As2 = smu;               // [2][FA2_SZ]
    unsigned* Bs2 = smu + 2 * FA2_SZ;  // [2][FB2_SZ]

    const int tid = threadIdx.x;
    const int bm = blockIdx.y * 64;
    const int lane = tid & 31, wid = tid >> 5;
    const int warp_m = (wid & 1) * 32, warp_n = (wid >> 1) * 64;
    const int wn = wid >> 1;
    const int qr = lane >> 2, qc = lane & 3;

    float acc[2][8][4];
#pragma unroll
    for (int t = 0; t < 2; t++)
#pragma unroll
        for (int j = 0; j < 8; j++)
#pragma unroll
            for (int c = 0; c < 4; c++) acc[t][j][c] = 0.f;

    const int a_r0 = tid >> 3, a_c4 = (tid & 7) * 4;
    const int b_kr0 = tid >> 6, b_n4 = (tid & 63) * 4;

    float4 pa[2], pb0[4], pb1[4];

#pragma unroll
    for (int it = 0; it < 2; it++) {
        int grow = bm + a_r0 + it * 32;
        pa[it] = (grow < M) ? *(const float4*)&A[(size_t)grow * 256 + a_c4]
                            : make_float4(0.f, 0.f, 0.f, 0.f);
    }
#pragma unroll
    for (int it = 0; it < 4; it++) {
        int kr = b_kr0 + it * 4;
        pb0[it] = *(const float4*)&W[(size_t)(2 * kr) * 256 + b_n4];
        pb1[it] = *(const float4*)&W[(size_t)(2 * kr + 1) * 256 + b_n4];
    }
#pragma unroll
    for (int it = 0; it < 2; it++) {
        uint2 h;
        h.x = f2h2(pa[it].x, pa[it].y);
        h.y = f2h2(pa[it].z, pa[it].w);
        *(uint2*)&As2[(a_r0 + it * 32) * 20 + (a_c4 >> 1)] = h;
    }
#pragma unroll
    for (int it = 0; it < 4; it++) {
        int kr = b_kr0 + it * 4;
        uint4 h;
        h.x = f2h2(pb0[it].x, pb1[it].x);
        h.y = f2h2(pb0[it].y, pb1[it].y);
        h.z = f2h2(pb0[it].z, pb1[it].z);
        h.w = f2h2(pb0[it].w, pb1[it].w);
        *(uint4*)&Bs2[kr * 264 + b_n4] = h;
    }
    __syncthreads();

    int cur = 0;
#pragma unroll
    for (int it8 = 0; it8 < 8; it8++) {
        if (it8 < 7) {
            int k0 = (it8 + 1) * 32;
#pragma unroll
            for (int it = 0; it < 2; it++) {
                int grow = bm + a_r0 + it * 32;
                pa[it] = (grow < M) ? *(const float4*)&A[(size_t)grow * 256 + k0 + a_c4]
                                    : make_float4(0.f, 0.f, 0.f, 0.f);
            }
#pragma unroll
            for (int it = 0; it < 4; it++) {
                int kr = b_kr0 + it * 4;
                pb0[it] = *(const float4*)&W[(size_t)(k0 + 2 * kr) * 256 + b_n4];
                pb1[it] = *(const float4*)&W[(size_t)(k0 + 2 * kr + 1) * 256 + b_n4];
            }
        }

        const unsigned* Ac = As2 + cur * FA2_SZ;
        const unsigned* Bc = Bs2 + cur * FB2_SZ;
#pragma unroll
        for (int s = 0; s < 2; s++) {
            const int kb = s * 8;
            unsigned af[2][4];
#pragma unroll
            for (int t = 0; t < 2; t++) {
                int r = warp_m + t * 16 + qr;
                af[t][0] = Ac[r * 20 + kb + qc];
                af[t][1] = Ac[(r + 8) * 20 + kb + qc];
                af[t][2] = Ac[r * 20 + kb + qc + 4];
                af[t][3] = Ac[(r + 8) * 20 + kb + qc + 4];
            }
            unsigned bf[8][2];
#pragma unroll
            for (int j = 0; j < 8; j++) {
                int col = warp_n + j * 8 + qr;
                bf[j][0] = Bc[(kb + qc) * 264 + col];
                bf[j][1] = Bc[(kb + qc + 4) * 264 + col];
            }
#pragma unroll
            for (int t = 0; t < 2; t++)
#pragma unroll
                for (int j = 0; j < 8; j++)
                    mma_f16(acc[t][j][0], acc[t][j][1], acc[t][j][2], acc[t][j][3],
                            af[t][0], af[t][1], af[t][2], af[t][3],
                            bf[j][0], bf[j][1]);
        }

        if (it8 < 7) {
            int nxt = cur ^ 1;
#pragma unroll
            for (int it = 0; it < 2; it++) {
                uint2 h;
                h.x = f2h2(pa[it].x, pa[it].y);
                h.y = f2h2(pa[it].z, pa[it].w);
                *(uint2*)&As2[nxt * FA2_SZ + (a_r0 + it * 32) * 20 + (a_c4 >> 1)] = h;
            }
#pragma unroll
            for (int it = 0; it < 4; it++) {
                int kr = b_kr0 + it * 4;
                uint4 h;
                h.x = f2h2(pb0[it].x, pb1[it].x);
                h.y = f2h2(pb0[it].y, pb1[it].y);
                h.z = f2h2(pb0[it].z, pb1[it].z);
                h.w = f2h2(pb0[it].w, pb1[it].w);
                *(uint4*)&Bs2[nxt * FB2_SZ + kr * 264 + b_n4] = h;
            }
        }
        __syncthreads();
        cur ^= 1;
    }

    float rv = __ldg(resv);
    float alpha = 1.f / (1.f + __expf(-rv));
    float beta = 1.f - alpha;

    float s[2][2] = {{0.f, 0.f}, {0.f, 0.f}};
    float sq[2][2] = {{0.f, 0.f}, {0.f, 0.f}};

#pragma unroll
    for (int t = 0; t < 2; t++) {
        int lr0 = warp_m + t * 16 + qr;
        int g0 = bm + lr0, g1 = g0 + 8;
#pragma unroll
        for (int j = 0; j < 8; j++) {
            int col = warp_n + j * 8 + 2 * qc;
            float2 bb = *(const float2*)&bias[col];
            float x0 = acc[t][j][0] + bb.x;
            float y0 = acc[t][j][1] + bb.y;
            float x1 = acc[t][j][2] + bb.x;
            float y1 = acc[t][j][3] + bb.y;
            if (g0 < M) {
                float2 h = *(const float2*)&Hin[(size_t)g0 * 256 + col];
                x0 = x0 * alpha + h.x * beta;
                y0 = y0 * alpha + h.y * beta;
            }
            if (g1 < M) {
                float2 h = *(const float2*)&Hin[(size_t)g1 * 256 + col];
                x1 = x1 * alpha + h.x * beta;
                y1 = y1 * alpha + h.y * beta;
            }
            acc[t][j][0] = x0; acc[t][j][1] = y0;
            acc[t][j][2] = x1; acc[t][j][3] = y1;
            s[t][0] += x0 + y0;
            s[t][1] += x1 + y1;
            sq[t][0] += x0 * x0 + y0 * y0;
            sq[t][1] += x1 * x1 + y1 * y1;
        }
    }

#pragma unroll
    for (int t = 0; t < 2; t++)
#pragma unroll
        for (int r = 0; r < 2; r++) {
            s[t][r] += __shfl_xor_sync(0xffffffffu, s[t][r], 1);
            s[t][r] += __shfl_xor_sync(0xffffffffu, s[t][r], 2);
            sq[t][r] += __shfl_xor_sync(0xffffffffu, sq[t][r], 1);
            sq[t][r] += __shfl_xor_sync(0xffffffffu, sq[t][r], 2);
        }

    float* red = (float*)smu;
    if (qc == 0) {
#pragma unroll
        for (int t = 0; t < 2; t++) {
            int lr0 = warp_m + t * 16 + qr;
            red[lr0 * 4 + wn] = s[t][0];
            red[(lr0 + 8) * 4 + wn] = s[t][1];
            red[256 + lr0 * 4 + wn] = sq[t][0];
            red[256 + (lr0 + 8) * 4 + wn] = sq[t][1];
        }
    }
    __syncthreads();

#pragma unroll
    for (int t = 0; t < 2; t++) {
        int lr0 = warp_m + t * 16 + qr;
        int lr1 = lr0 + 8;
        float ts0 = red[lr0 * 4 + 0] + red[lr0 * 4 + 1] + red[lr0 * 4 + 2] + red[lr0 * 4 + 3];
        float ts1 = red[lr1 * 4 + 0] + red[lr1 * 4 + 1] + red[lr1 * 4 + 2] + red[lr1 * 4 + 3];
        float tq0 = red[256 + lr0 * 4 + 0] + red[256 + lr0 * 4 + 1] +
                    red[256 + lr0 * 4 + 2] + red[256 + lr0 * 4 + 3];
        float tq1 = red[256 + lr1 * 4 + 0] + red[256 + lr1 * 4 + 1] +
                    red[256 + lr1 * 4 + 2] + red[256 + lr1 * 4 + 3];
        float mu0 = ts0 * (1.f / 256.f);
        float mu1 = ts1 * (1.f / 256.f);
        float var0 = fmaxf(tq0 * (1.f / 256.f) - mu0 * mu0, 0.f);
        float var1 = fmaxf(tq1 * (1.f / 256.f) - mu1 * mu1, 0.f);
        float iv0 = rsqrtf(var0 + 1e-5f);
        float iv1 = rsqrtf(var1 + 1e-5f);
        int g0 = bm + lr0, g1 = bm + lr1;
#pragma unroll
        for (int j = 0; j < 8; j++) {
            int col = warp_n + j * 8 + 2 * qc;
            float2 gg = *(const float2*)&lng[col];
            float2 bb = *(const float2*)&lnb[col];
            if (g0 < M) {
                float2 r;
                r.x = (acc[t][j][0] - mu0) * iv0 * gg.x + bb.x;
                r.y = (acc[t][j][1] - mu0) * iv0 * gg.y + bb.y;
                *(float2*)&out[(size_t)g0 * 256 + col] = r;
            }
            if (g1 < M) {
                float2 r;
                r.x = (acc[t][j][2] - mu1) * iv1 * gg.x + bb.x;
                r.y = (acc[t][j][3] - mu1) * iv1 * gg.y + bb.y;
                *(float2*)&out[(size_t)g1 * 256 + col] = r;
            }
        }
    }
}

// ---------------- weight prep (emits packed half2 [kpair][n]) ----------------
__global__ __launch_bounds__(256) void prep_combine_k(
    const float* __restrict__ Wk, const float* __restrict__ bk,
    const float* __restrict__ Wv, const float* __restrict__ bv,
    const float* __restrict__ attw, const float* __restrict__ valw,
    unsigned* __restrict__ WuA, unsigned* __restrict__ WuP,
    float* __restrict__ bcatA, float* __restrict__ bcatP)
{
    __shared__ float s_hw[32 * 32];
    const int h = blockIdx.x;
    const int slot = blockIdx.y;
    const int tid = threadIdx.x;

    const bool srcA = (slot < 2);
    const bool isV = (slot & 1);
    const int et = (slot < 2) ? 0 : ((slot < 4) ? 1 : 2);

    const float* Wsrc = (isV ? Wv : Wk) + (srcA ? 0 : 65536);
    const float* bsrc = (isV ? bv : bk) + (srcA ? 0 : 256);
    const float* hw = (isV ? valw : attw) + et * 8192 + h * 1024;
    unsigned* Wout = srcA ? WuA : WuP;
    float* bout = srcA ? bcatA : bcatP;
    const int ldn = srcA ? LDA_A : LDA_P;
    const int colbase = 256 + (isV ? 256 : 0) + ((slot >= 4) ? 512 : 0);

#pragma unroll
    for (int i = tid; i < 1024; i += 256) s_hw[i] = hw[i];
    __syncthreads();

    const int d = tid;  // input dim k
    float wrow[32];
#pragma unroll
    for (int d2 = 0; d2 < 32; d2++) wrow[d2] = Wsrc[(size_t)d * 256 + h * 32 + d2];
#pragma unroll
    for (int j = 0; j < 32; j++) {
        float acc = 0.f;
#pragma unroll
        for (int d2 = 0; d2 < 32; d2++) acc += wrow[d2] * s_hw[d2 * 32 + j];
        // pair rows (2m, 2m+1) across adjacent lanes; even lane writes half2
        float up = __shfl_down_sync(0xffffffffu, acc, 1);
        if (!(d & 1))
            Wout[(size_t)(d >> 1) * ldn + colbase + h * 32 + j] = f2h2(acc, up);
    }
    if (tid < 32) {
        float acc = 0.f;
#pragma unroll
        for (int d2 = 0; d2 < 32; d2++) acc += bsrc[h * 32 + d2] * s_hw[d2 * 32 + tid];
        bout[colbase + h * 32 + tid] = acc;
    }
}

__global__ void copyq_k(const float* __restrict__ Wq, const float* __restrict__ bq,
                        unsigned* __restrict__ WuA, unsigned* __restrict__ WuP,
                        float* __restrict__ bcatA, float* __restrict__ bcatP)
{
    int gid = blockIdx.x * blockDim.x + threadIdx.x;
    for (int i = gid; i < 32768; i += gridDim.x * blockDim.x) {
        int kp = i >> 8, c = i & 255;
        WuA[(size_t)kp * LDA_A + c] = f2h2(Wq[(2 * kp) * 256 + c], Wq[(2 * kp + 1) * 256 + c]);
        WuP[(size_t)kp * LDA_P + c] = f2h2(Wq[65536 + (2 * kp) * 256 + c],
                                           Wq[65536 + (2 * kp + 1) * 256 + c]);
    }
    if (gid < 256) {
        bcatA[gid] = bq[gid];
        bcatP[gid] = bq[256 + gid];
    }
}

// ---------------- batched CSR build ----------------
__global__ void zero3_k(int* __restrict__ c0, int* __restrict__ c1, int* __restrict__ c2)
{
    int i = blockIdx.x * blockDim.x + threadIdx.x;
    if (i < NP_N) { c0[i] = 0; c1[i] = 0; }
    if (i < NA_N) c2[i] = 0;
}

__global__ void hist3_k(const int* __restrict__ d0, const int* __restrict__ d1,
                        const int* __restrict__ d2,
                        int* __restrict__ c0, int* __restrict__ c1, int* __restrict__ c2)
{
    int g = blockIdx.y;
    int i = blockIdx.x * blockDim.x + threadIdx.x;
    if (i >= E_N) return;
    const int* d = (g == 0) ? d0 : ((g == 1) ? d1 : d2);
    int* c = (g == 0) ? c0 : ((g == 1) ? c1 : c2);
    atomicAdd(&c[d[i]], 1);
}

__global__ __launch_bounds__(1024) void scan3_k(
    const int* __restrict__ cw, const int* __restrict__ cc, const int* __restrict__ ca,
    int* __restrict__ ow, int* __restrict__ oc, int* __restrict__ oa,
    int* __restrict__ uw, int* __restrict__ uc, int* __restrict__ ua)
{
    __shared__ int sh[1024];
    const int* cnt; int* off; int* cur; int n;
    if (blockIdx.x == 0) { cnt = cw; off = ow; cur = uw; n = NP_N; }
    else if (blockIdx.x == 1) { cnt = cc; off = oc; cur = uc; n = NP_N; }
    else { cnt = ca; off = oa; cur = ua; n = NA_N; }

    int t = threadIdx.x;
    int chunk = (n + 1023) >> 10;
    int s0 = t * chunk;
    int s1 = min(s0 + chunk, n);
    int sum = 0;
    for (int i = s0; i < s1; i++) sum += cnt[i];
    sh[t] = sum;
    __syncthreads();
    for (int d = 1; d < 1024; d <<= 1) {
        int v = 0;
        if (t >= d) v = sh[t - d];
        __syncthreads();
        sh[t] += v;
        __syncthreads();
    }
    int run = sh[t] - sum;
    for (int i = s0; i < s1; i++) {
        off[i] = run;
        cur[i] = run;
        run += cnt[i];
    }
    if (t == 1023) off[n] = sh[1023];
}

__global__ void scatter3_k(
    const int* __restrict__ s0, const int* __restrict__ d0,
    const int* __restrict__ s1, const int* __restrict__ d1,
    const int* __restrict__ s2, const int* __restrict__ d2,
    int* __restrict__ u0, int* __restrict__ u1, int* __restrict__ u2,
    int* __restrict__ p0, int* __restrict__ p1, int* __restrict__ p2)
{
    int g = blockIdx.y;
    int i = blockIdx.x * blockDim.x + threadIdx.x;
    if (i >= E_N) return;
    const int* s = (g == 0) ? s0 : ((g == 1) ? s1 : s2);
    const int* d = (g == 0) ? d0 : ((g == 1) ? d1 : d2);
    int* u = (g == 0) ? u0 : ((g == 1) ? u1 : u2);
    int* p = (g == 0) ? p0 : ((g == 1) ? p1 : p2);
    int pos = atomicAdd(&u[d[i]], 1);
    p[pos] = s[i];
}

// ---------------- aggregation (software-pipelined gather) ----------------
__device__ __forceinline__ void agg_run(
    float4 q0, float4 q1, float cw,
    const float* __restrict__ KB, int ldkv, int koff,
    const int* __restrict__ psrc, int ebeg, int eend, float* o)
{
    float m = -3.0e38f, den = 0.f;
    float a0 = 0, a1 = 0, a2 = 0, a3 = 0, a4 = 0, a5 = 0, a6 = 0, a7 = 0;

    if (ebeg < eend) {
        int src = __ldg(&psrc[ebeg]);
        const float* kp = KB + (size_t)src * ldkv + koff;
        float4 k0 = *(const float4*)kp;
        float4 k1 = *(const float4*)(kp + 4);
        float4 v0 = *(const float4*)(kp + 256);
        float4 v1 = *(const float4*)(kp + 260);

        for (int i = ebeg; ; ) {
            bool more = (i + 1 < eend);
            float4 nk0, nk1, nv0, nv1;
            if (more) {
                int nsrc = __ldg(&psrc[i + 1]);
                const float* np = KB + (size_t)nsrc * ldkv + koff;
                nk0 = *(const float4*)np;
                nk1 = *(const float4*)(np + 4);
                nv0 = *(const float4*)(np + 256);
                nv1 = *(const float4*)(np + 260);
            }

            float p = q0.x * k0.x + q0.y * k0.y + q0.z * k0.z + q0.w * k0.w +
                      q1.x * k1.x + q1.y * k1.y + q1.z * k1.z + q1.w * k1.w;
            p += __shfl_xor_sync(0xffffffffu, p, 1);
            p += __shfl_xor_sync(0xffffffffu, p, 2);
            float sc = p * cw;
            float mn = fmaxf(m, sc);
            float corr = __expf(m - mn);
            float w = __expf(sc - mn);
            m = mn;
            den = den * corr + w;
            a0 = a0 * corr + w * v0.x;
            a1 = a1 * corr + w * v0.y;
            a2 = a2 * corr + w * v0.z;
            a3 = a3 * corr + w * v0.w;
            a4 = a4 * corr + w * v1.x;
            a5 = a5 * corr + w * v1.y;
            a6 = a6 * corr + w * v1.z;
            a7 = a7 * corr + w * v1.w;

            if (!more) break;
            k0 = nk0; k1 = nk1; v0 = nv0; v1 = nv1;
            i++;
        }
    }
    float r = (den > 0.f) ? (1.f / den) : 0.f;
    o[0] = a0 * r; o[1] = a1 * r; o[2] = a2 * r; o[3] = a3 * r;
    o[4] = a4 * r; o[5] = a5 * r; o[6] = a6 * r; o[7] = a7 * r;
}

__global__ __launch_bounds__(256) void agg_paper_k(
    const float* __restrict__ PP, const float* __restrict__ AP,
    const int* __restrict__ offw, const int* __restrict__ pw,
    const int* __restrict__ offc, const int* __restrict__ pc,
    const float* __restrict__ canon, float* __restrict__ OUT, int n)
{
    int gw = (blockIdx.x * blockDim.x + threadIdx.x) >> 5;
    if (gw >= n) return;
    int lane = threadIdx.x & 31;
    int h = lane >> 2;
    int seg = (lane & 3) << 3;
    int hs = h * 32 + seg;
    const float* qp = PP + (size_t)gw * LDA_P + hs;
    float4 q0 = *(const float4*)qp;
    float4 q1 = *(const float4*)(qp + 4);
    const float inv = 0.17677669529663687f;

    float ow[8], oc[8];
    agg_run(q0, q1, __ldg(&canon[h]) * inv, AP, LDA_A, 256 + hs,
            pw, __ldg(&offw[gw]), __ldg(&offw[gw + 1]), ow);
    agg_run(q0, q1, __ldg(&canon[16 + h]) * inv, PP, LDA_P, 768 + hs,
            pc, __ldg(&offc[gw]), __ldg(&offc[gw + 1]), oc);

    float* op = OUT + (size_t)gw * 256 + hs;
    *(float4*)op = make_float4(0.5f * (ow[0] + oc[0]), 0.5f * (ow[1] + oc[1]),
                               0.5f * (ow[2] + oc[2]), 0.5f * (ow[3] + oc[3]));
    *(float4*)(op + 4) = make_float4(0.5f * (ow[4] + oc[4]), 0.5f * (ow[5] + oc[5]),
                                     0.5f * (ow[6] + oc[6]), 0.5f * (ow[7] + oc[7]));
}

__global__ __launch_bounds__(256) void agg_author_k(
    const float* __restrict__ AP, const float* __restrict__ PP,
    const int* __restrict__ offa, const int* __restrict__ pa,
    const float* __restrict__ canon, float* __restrict__ OUT, int n)
{
    int gw = (blockIdx.x * blockDim.x + threadIdx.x) >> 5;
    if (gw >= n) return;
    int lane = threadIdx.x & 31;
    int h = lane >> 2;
    int seg = (lane & 3) << 3;
    int hs = h * 32 + seg;
    const float* qp = AP + (size_t)gw * LDA_A + hs;
    float4 q0 = *(const float4*)qp;
    float4 q1 = *(const float4*)(qp + 4);
    const float inv = 0.17677669529663687f;

    float o[8];
    agg_run(q0, q1, __ldg(&canon[8 + h]) * inv, PP, LDA_P, 256 + hs,
            pa, __ldg(&offa[gw]), __ldg(&offa[gw + 1]), o);

    float* op = OUT + (size_t)gw * 256 + hs;
    *(float4*)op = make_float4(o[0], o[1], o[2], o[3]);
    *(float4*)(op + 4) = make_float4(o[4], o[5], o[6], o[7]);
}

// ---------------- host orchestration ----------------
extern "C" void kernel_launch(void* const* d_in, const int* in_sizes, int n_in,
                              void* d_out, int out_size)
{
    const float* h_a  = (const float*)d_in[0];
    const float* h_p  = (const float*)d_in[1];
    const int* wsrc   = (const int*)d_in[2];
    const int* wdst   = (const int*)d_in[3];
    const int* wbsrc  = (const int*)d_in[4];
    const int* wbdst  = (const int*)d_in[5];
    const int* csrc   = (const int*)d_in[6];
    const int* cdst   = (const int*)d_in[7];
    const float* Wk   = (const float*)d_in[8];
    const float* bk   = (const float*)d_in[9];
    const float* Wq   = (const float*)d_in[10];
    const float* bq   = (const float*)d_in[11];
    const float* Wv   = (const float*)d_in[12];
    const float* bv   = (const float*)d_in[13];
    const float* Wfc  = (const float*)d_in[14];
    const float* bfc  = (const float*)d_in[15];
    const float* lng  = (const float*)d_in[16];
    const float* lnb  = (const float*)d_in[17];
    const float* attw = (const float*)d_in[18];
    const float* valw = (const float*)d_in[19];
    const float* canon= (const float*)d_in[20];
    const float* res  = (const float*)d_in[21];
    float* out = (float*)d_out;

    float *AP, *PP, *AGA, *AGP, *bcA, *bcP;
    unsigned *Ah, *Ph, *WuA, *WuP;
    int *cw, *cc, *ca, *ow_, *oc_, *oa_, *uw, *uc, *ua, *pw, *pc, *pa;
    cudaGetSymbolAddress((void**)&AP, g_APROJ);
    cudaGetSymbolAddress((void**)&PP, g_PPROJ);
    cudaGetSymbolAddress((void**)&AGA, g_AGA);
    cudaGetSymbolAddress((void**)&AGP, g_AGP);
    cudaGetSymbolAddress((void**)&Ah, g_Ah);
    cudaGetSymbolAddress((void**)&Ph, g_Ph);
    cudaGetSymbolAddress((void**)&WuA, g_WuA);
    cudaGetSymbolAddress((void**)&WuP, g_WuP);
    cudaGetSymbolAddress((void**)&bcA, g_bcatA);
    cudaGetSymbolAddress((void**)&bcP, g_bcatP);
    cudaGetSymbolAddress((void**)&cw, g_cnt_w);
    cudaGetSymbolAddress((void**)&cc, g_cnt_c);
    cudaGetSymbolAddress((void**)&ca, g_cnt_a);
    cudaGetSymbolAddress((void**)&ow_, g_off_w);
    cudaGetSymbolAddress((void**)&oc_, g_off_c);
    cudaGetSymbolAddress((void**)&oa_, g_off_a);
    cudaGetSymbolAddress((void**)&uw, g_cur_w);
    cudaGetSymbolAddress((void**)&uc, g_cur_c);
    cudaGetSymbolAddress((void**)&ua, g_cur_a);
    cudaGetSymbolAddress((void**)&pw, g_psrc_w);
    cudaGetSymbolAddress((void**)&pc, g_psrc_c);
    cudaGetSymbolAddress((void**)&pa, g_psrc_a);

    cudaFuncSetAttribute(mma_gemm_k, cudaFuncAttributeMaxDynamicSharedMemorySize, GEMM_SMEM_BYTES);
    cudaFuncSetAttribute(fc_ln_k, cudaFuncAttributeMaxDynamicSharedMemorySize, FC_SMEM_BYTES);

    const int MB = (NA_N + 127) / 128;   // 782
    const int MB64 = (NA_N + 63) / 64;   // 1563
    const int gwA = (NA_N + 7) / 8, gwP = (NP_N + 7) / 8;
    const dim3 gEdge((E_N + 255) / 256, 3);

    // 1-3: prep (half-packed weights + inputs)
    prep_combine_k<<<dim3(8, 6), 256>>>(Wk, bk, Wv, bv, attw, valw, WuA, WuP, bcA, bcP);
    copyq_k<<<128, 256>>>(Wq, bq, WuA, WuP, bcA, bcP);
    tohalf_k<<<4096, 256>>>(h_a, h_p, Ah, Ph);

    // 4-5: projections (launch #4 lands in the ncu capture slot)
    mma_gemm_k<<<dim3(LDA_A / 128, MB), 256, GEMM_SMEM_BYTES>>>(Ah, WuA, bcA, AP, NA_N, LDA_A);
    mma_gemm_k<<<dim3(LDA_P / 128, MB), 256, GEMM_SMEM_BYTES>>>(Ph, WuP, bcP, PP, NP_N, LDA_P);

    // 6-9: CSR build
    zero3_k<<<(NP_N + 255) / 256, 256>>>(cw, cc, ca);
    hist3_k<<<gEdge, 256>>>(wdst, cdst, wbdst, cw, cc, ca);
    scan3_k<<<3, 1024>>>(cw, cc, ca, ow_, oc_, oa_, uw, uc, ua);
    scatter3_k<<<gEdge, 256>>>(wsrc, wdst, csrc, cdst, wbsrc, wbdst, uw, uc, ua, pw, pc, pa);

    // 10-11: aggregations
    agg_paper_k<<<gwP, 256>>>(PP, AP, ow_, pw, oc_, pc, canon, AGP, NP_N);
    agg_author_k<<<gwA, 256>>>(AP, PP, oa_, pa, canon, AGA, NA_N);

    // 12-13: fc + residual blend + LN -> output
    fc_ln_k<<<dim3(1, MB64), 256, FC_SMEM_BYTES>>>(
        AGA, Wfc + 0, bfc + 0, h_a, res + 0, lng + 0, lnb + 0, out, NA_N);
    fc_ln_k<<<dim3(1, MB64), 256, FC_SMEM_BYTES>>>(
        AGP, Wfc + 65536, bfc + 256, h_p, res + 1, lng + 256, lnb + 256,
        out + (size_t)NA_N * D_, NP_N);
}

// round 17
// speedup vs baseline: 3.5452x; 1.0795x over previous
#include <cuda_runtime.h>
#include <math.h>
#include <stdint.h>

#define NA_N 100000
#define NP_N 100000
#define E_N  400000
#define D_   256
#define H_   8

#define LDA_P 1280   // paper proj row: Q | K1 | V1 | K2 | V2
#define LDA_A 768    // author proj row: Q | K0 | V0

// ---------------- static scratch ----------------
static __device__ float g_APROJ[(size_t)NA_N * LDA_A];
static __device__ float g_PPROJ[(size_t)NP_N * LDA_P];
static __device__ float g_AGA[(size_t)NA_N * D_];
static __device__ float g_AGP[(size_t)NP_N * D_];
static __device__ unsigned g_Ah[(size_t)NA_N * 128];      // h_a as half2 pairs
static __device__ unsigned g_Ph[(size_t)NP_N * 128];      // h_p as half2 pairs
static __device__ unsigned g_WuA[128 * LDA_A];            // weights half2: [kpair][n]
static __device__ unsigned g_WuP[128 * LDA_P];
static __device__ float g_bcatA[LDA_A];
static __device__ float g_bcatP[LDA_P];
static __device__ int g_cnt_w[NP_N], g_cnt_c[NP_N], g_cnt_a[NA_N];
static __device__ int g_off_w[NP_N + 1], g_off_c[NP_N + 1], g_off_a[NA_N + 1];
static __device__ int g_cur_w[NP_N], g_cur_c[NP_N], g_cur_a[NA_N];
static __device__ int g_psrc_w[E_N], g_psrc_c[E_N], g_psrc_a[E_N];

// ---------------- helpers ----------------
__device__ __forceinline__ unsigned f2h2(float lo, float hi) {
    unsigned r;
    asm("cvt.rn.f16x2.f32 %0, %1, %2;" : "=r"(r) : "f"(hi), "f"(lo));
    return r;
}
__device__ __forceinline__ void mma_f16(float& c0, float& c1, float& c2, float& c3,
                                        unsigned a0, unsigned a1, unsigned a2, unsigned a3,
                                        unsigned b0, unsigned b1) {
    asm volatile(
        "mma.sync.aligned.m16n8k16.row.col.f32.f16.f16.f32 "
        "{%0,%1,%2,%3}, {%4,%5,%6,%7}, {%8,%9}, {%0,%1,%2,%3};"
        : "+f"(c0), "+f"(c1), "+f"(c2), "+f"(c3)
        : "r"(a0), "r"(a1), "r"(a2), "r"(a3), "r"(b0), "r"(b1));
}
__device__ __forceinline__ void ldsm_x4(unsigned& r0, unsigned& r1, unsigned& r2, unsigned& r3,
                                        unsigned saddr) {
    asm volatile("ldmatrix.sync.aligned.m8n8.x4.shared.b16 {%0,%1,%2,%3}, [%4];"
                 : "=r"(r0), "=r"(r1), "=r"(r2), "=r"(r3) : "r"(saddr));
}

// ---------------- pre-pass: fp32 -> packed half2 ----------------
__global__ void tohalf_k(const float* __restrict__ a, const float* __restrict__ p,
                         unsigned* __restrict__ ah, unsigned* __restrict__ ph)
{
    const int total = NA_N * 64;  // float4 count per tensor
    for (int i = blockIdx.x * blockDim.x + threadIdx.x; i < total; i += gridDim.x * blockDim.x) {
        float4 va = ((const float4*)a)[i];
        float4 vp = ((const float4*)p)[i];
        uint2 ua, up;
        ua.x = f2h2(va.x, va.y); ua.y = f2h2(va.z, va.w);
        up.x = f2h2(vp.x, vp.y); up.y = f2h2(vp.z, vp.w);
        ((uint2*)ah)[i] = ua;
        ((uint2*)ph)[i] = up;
    }
}

// ---------------- FP16 tensor GEMM (projections): C[M,N] = Ah@Wu + bias ----------------
// Block tile 128x128, BK=32, 8 warps (4m x 2n), warp tile 32x64, mma m16n8k16.
// 2 CTAs/SM via launch_bounds (reg cap 128) for cross-CTA latency hiding.
#define A2_SZ 2560   // 128*20
#define B2_SZ 2176   // 16*136
#define GEMM_SMEM_BYTES (2 * (A2_SZ + B2_SZ) * 4)

__global__ __launch_bounds__(256, 2) void mma_gemm_k(
    const unsigned* __restrict__ Ah, const unsigned* __restrict__ Wu,
    const float* __restrict__ bias, float* __restrict__ C,
    int M, int N)
{
    extern __shared__ unsigned smu[];
    unsigned* As2 = smu;              // [2][A2_SZ]
    unsigned* Bs2 = smu + 2 * A2_SZ;  // [2][B2_SZ]

    const int tid = threadIdx.x;
    const int bm = blockIdx.y * 128;
    const int bn = blockIdx.x * 128;
    const int lane = tid & 31, wid = tid >> 5;
    const int warp_m = (wid & 3) * 32, warp_n = (wid >> 2) * 64;
    const int qr = lane >> 2, qc = lane & 3;
    const int lrow = lane & 15;            // ldmatrix address row-within-32
    const int lcol4 = (lane >> 4) * 4;     // ldmatrix address col group
    const unsigned sb_a = (unsigned)__cvta_generic_to_shared(As2);

    float acc[2][8][4];
#pragma unroll
    for (int t = 0; t < 2; t++)
#pragma unroll
        for (int j = 0; j < 8; j++)
#pragma unroll
            for (int c = 0; c < 4; c++) acc[t][j][c] = 0.f;

    // A loader: row = tid>>2 (0..63, +64), g4 = (tid&3)*4
    const int a_row = tid >> 2, a_g4 = (tid & 3) * 4;
    // B loader: kr = tid>>5 (+8), n4 = (tid&31)*4
    const int b_kr = tid >> 5, b_n4 = (tid & 31) * 4;

    uint4 pa[2], pb[2];
    const uint4 z4 = make_uint4(0, 0, 0, 0);

    // prologue k0 = 0
#pragma unroll
    for (int it = 0; it < 2; it++) {
        int row = a_row + it * 64;
        int grow = bm + row;
        pa[it] = (grow < M) ? *(const uint4*)&Ah[(size_t)grow * 128 + a_g4] : z4;
        int kr = b_kr + it * 8;
        pb[it] = *(const uint4*)&Wu[(size_t)kr * N + bn + b_n4];
    }
#pragma unroll
    for (int it = 0; it < 2; it++) {
        *(uint4*)&As2[(a_row + it * 64) * 20 + a_g4] = pa[it];
        *(uint4*)&Bs2[(b_kr + it * 8) * 136 + b_n4] = pb[it];
    }
    __syncthreads();

    int cur = 0;
#pragma unroll
    for (int it8 = 0; it8 < 8; it8++) {
        if (it8 < 7) {
            int kp0 = (it8 + 1) * 16;  // kpair offset of next chunk
#pragma unroll
            for (int it = 0; it < 2; it++) {
                int row = a_row + it * 64;
                int grow = bm + row;
                pa[it] = (grow < M) ? *(const uint4*)&Ah[(size_t)grow * 128 + kp0 + a_g4] : z4;
                int kr = b_kr + it * 8;
                pb[it] = *(const uint4*)&Wu[(size_t)(kp0 + kr) * N + bn + b_n4];
            }
        }

        const unsigned abase = sb_a + (unsigned)(cur * A2_SZ) * 4u;
        const unsigned* Bc = Bs2 + cur * B2_SZ;
#pragma unroll
        for (int s = 0; s < 2; s++) {
            const int kb = s * 8;
            unsigned af[2][4];
#pragma unroll
            for (int t = 0; t < 2; t++) {
                unsigned addr = abase + (unsigned)((warp_m + t * 16 + lrow) * 20 + kb + lcol4) * 4u;
                ldsm_x4(af[t][0], af[t][1], af[t][2], af[t][3], addr);
            }
            unsigned bf[8][2];
#pragma unroll
            for (int j = 0; j < 8; j++) {
                int col = warp_n + j * 8 + qr;
                bf[j][0] = Bc[(kb + qc) * 136 + col];
                bf[j][1] = Bc[(kb + qc + 4) * 136 + col];
            }
#pragma unroll
            for (int t = 0; t < 2; t++)
#pragma unroll
                for (int j = 0; j < 8; j++)
                    mma_f16(acc[t][j][0], acc[t][j][1], acc[t][j][2], acc[t][j][3],
                            af[t][0], af[t][1], af[t][2], af[t][3],
                            bf[j][0], bf[j][1]);
        }

        if (it8 < 7) {
            int nxt = cur ^ 1;
#pragma unroll
            for (int it = 0; it < 2; it++) {
                *(uint4*)&As2[nxt * A2_SZ + (a_row + it * 64) * 20 + a_g4] = pa[it];
                *(uint4*)&Bs2[nxt * B2_SZ + (b_kr + it * 8) * 136 + b_n4] = pb[it];
            }
        }
        __syncthreads();
        cur ^= 1;
    }

#pragma unroll
    for (int t = 0; t < 2; t++) {
        int r0 = bm + warp_m + t * 16 + qr;
        int r1 = r0 + 8;
#pragma unroll
        for (int j = 0; j < 8; j++) {
            int col = bn + warp_n + j * 8 + 2 * qc;
            float2 bb = *(const float2*)&bias[col];
            float2 v0, v1;
            v0.x = acc[t][j][0] + bb.x;
            v0.y = acc[t][j][1] + bb.y;
            v1.x = acc[t][j][2] + bb.x;
            v1.y = acc[t][j][3] + bb.y;
            if (r0 < M) *(float2*)&C[(size_t)r0 * N + col] = v0;
            if (r1 < M) *(float2*)&C[(size_t)r1 * N + col] = v1;
        }
    }
}

// ---------------- fused fc + residual-blend + LayerNorm (fp16 mma, fp32 inputs) ----------------
// Block tile 64x256, BK=32, 8 warps (2m x 4n), warp tile 32x64. 2 CTAs/SM.
#define FA2_SZ 1280  // 64*20
#define FB2_SZ 4224  // 16*264
#define FC_SMEM_BYTES (2 * (FA2_SZ + FB2_SZ) * 4)

__global__ __launch_bounds__(256, 2) void fc_ln_k(
    const float* __restrict__ A, const float* __restrict__ W,
    const float* __restrict__ bias, const float* __restrict__ Hin,
    const float* __restrict__ resv,
    const float* __restrict__ lng, const float* __restrict__ lnb,
    float* __restrict__ out, int M)
{
    extern __shared__ unsigned smu[];
    unsigned* As2 = smu;               // [2][FA2_SZ]
    unsigned* Bs2 = smu + 2 * FA2_SZ;  // [2][FB2_SZ]

    const int tid = threadIdx.x;
    const int bm = blockIdx.y * 64;
    const int lane = tid & 31, wid = tid >> 5;
    const int warp_m = (wid & 1) * 32, warp_n = (wid >> 1) * 64;
    const int wn = wid >> 1;
    const int qr = lane >> 2, qc = lane & 3;

    float acc[2][8][4];
#pragma unroll
    for (int t = 0; t < 2; t++)
#pragma unroll
        for (int j = 0; j < 8; j++)
#pragma unroll
            for (int c = 0; c < 4; c++) acc[t][j][c] = 0.f;

    const int a_r0 = tid >> 3, a_c4 = (tid & 7) * 4;
    const int b_kr0 = tid >> 6, b_n4 = (tid & 63) * 4;

    float4 pa[2], pb0[4], pb1[4];

#pragma unroll
    for (int it = 0; it < 2; it++) {
        int grow = bm + a_r0 + it * 32;
        pa[it] = (grow < M) ? *(const float4*)&A[(size_t)grow * 256 + a_c4]
                            : make_float4(0.f, 0.f, 0.f, 0.f);
    }
#pragma unroll
    for (int it = 0; it < 4; it++) {
        int kr = b_kr0 + it * 4;
        pb0[it] = *(const float4*)&W[(size_t)(2 * kr) * 256 + b_n4];
        pb1[it] = *(const float4*)&W[(size_t)(2 * kr + 1) * 256 + b_n4];
    }
#pragma unroll
    for (int it = 0; it < 2; it++) {
        uint2 h;
        h.x = f2h2(pa[it].x, pa[it].y);
        h.y = f2h2(pa[it].z, pa[it].w);
        *(uint2*)&As2[(a_r0 + it * 32) * 20 + (a_c4 >> 1)] = h;
    }
#pragma unroll
    for (int it = 0; it < 4; it++) {
        int kr = b_kr0 + it * 4;
        uint4 h;
        h.x = f2h2(pb0[it].x, pb1[it].x);
        h.y = f2h2(pb0[it].y, pb1[it].y);
        h.z = f2h2(pb0[it].z, pb1[it].z);
        h.w = f2h2(pb0[it].w, pb1[it].w);
        *(uint4*)&Bs2[kr * 264 + b_n4] = h;
    }
    __syncthreads();

    int cur = 0;
#pragma unroll
    for (int it8 = 0; it8 < 8; it8++) {
        if (it8 < 7) {
            int k0 = (it8 + 1) * 32;
#pragma unroll
            for (int it = 0; it < 2; it++) {
                int grow = bm + a_r0 + it * 32;
                pa[it] = (grow < M) ? *(const float4*)&A[(size_t)grow * 256 + k0 + a_c4]
                                    : make_float4(0.f, 0.f, 0.f, 0.f);
            }
#pragma unroll
            for (int it = 0; it < 4; it++) {
                int kr = b_kr0 + it * 4;
                pb0[it] = *(const float4*)&W[(size_t)(k0 + 2 * kr) * 256 + b_n4];
                pb1[it] = *(const float4*)&W[(size_t)(k0 + 2 * kr + 1) * 256 + b_n4];
            }
        }

        const unsigned* Ac = As2 + cur * FA2_SZ;
        const unsigned* Bc = Bs2 + cur * FB2_SZ;
#pragma unroll
        for (int s = 0; s < 2; s++) {
            const int kb = s * 8;
            unsigned af[2][4];
#pragma unroll
            for (int t = 0; t < 2; t++) {
                int r = warp_m + t * 16 + qr;
                af[t][0] = Ac[r * 20 + kb + qc];
                af[t][1] = Ac[(r + 8) * 20 + kb + qc];
                af[t][2] = Ac[r * 20 + kb + qc + 4];
                af[t][3] = Ac[(r + 8) * 20 + kb + qc + 4];
            }
            unsigned bf[8][2];
#pragma unroll
            for (int j = 0; j < 8; j++) {
                int col = warp_n + j * 8 + qr;
                bf[j][0] = Bc[(kb + qc) * 264 + col];
                bf[j][1] = Bc[(kb + qc + 4) * 264 + col];
            }
#pragma unroll
            for (int t = 0; t < 2; t++)
#pragma unroll
                for (int j = 0; j < 8; j++)
                    mma_f16(acc[t][j][0], acc[t][j][1], acc[t][j][2], acc[t][j][3],
                            af[t][0], af[t][1], af[t][2], af[t][3],
                            bf[j][0], bf[j][1]);
        }

        if (it8 < 7) {
            int nxt = cur ^ 1;
#pragma unroll
            for (int it = 0; it < 2; it++) {
                uint2 h;
                h.x = f2h2(pa[it].x, pa[it].y);
                h.y = f2h2(pa[it].z, pa[it].w);
                *(uint2*)&As2[nxt * FA2_SZ + (a_r0 + it * 32) * 20 + (a_c4 >> 1)] = h;
            }
#pragma unroll
            for (int it = 0; it < 4; it++) {
                int kr = b_kr0 + it * 4;
                uint4 h;
                h.x = f2h2(pb0[it].x, pb1[it].x);
                h.y = f2h2(pb0[it].y, pb1[it].y);
                h.z = f2h2(pb0[it].z, pb1[it].z);
                h.w = f2h2(pb0[it].w, pb1[it].w);
                *(uint4*)&Bs2[nxt * FB2_SZ + kr * 264 + b_n4] = h;
            }
        }
        __syncthreads();
        cur ^= 1;
    }

    float rv = __ldg(resv);
    float alpha = 1.f / (1.f + __expf(-rv));
    float beta = 1.f - alpha;

    float s[2][2] = {{0.f, 0.f}, {0.f, 0.f}};
    float sq[2][2] = {{0.f, 0.f}, {0.f, 0.f}};

#pragma unroll
    for (int t = 0; t < 2; t++) {
        int lr0 = warp_m + t * 16 + qr;
        int g0 = bm + lr0, g1 = g0 + 8;
#pragma unroll
        for (int j = 0; j < 8; j++) {
            int col = warp_n + j * 8 + 2 * qc;
            float2 bb = *(const float2*)&bias[col];
            float x0 = acc[t][j][0] + bb.x;
            float y0 = acc[t][j][1] + bb.y;
            float x1 = acc[t][j][2] + bb.x;
            float y1 = acc[t][j][3] + bb.y;
            if (g0 < M) {
                float2 h = *(const float2*)&Hin[(size_t)g0 * 256 + col];
                x0 = x0 * alpha + h.x * beta;
                y0 = y0 * alpha + h.y * beta;
            }
            if (g1 < M) {
                float2 h = *(const float2*)&Hin[(size_t)g1 * 256 + col];
                x1 = x1 * alpha + h.x * beta;
                y1 = y1 * alpha + h.y * beta;
            }
            acc[t][j][0] = x0; acc[t][j][1] = y0;
            acc[t][j][2] = x1; acc[t][j][3] = y1;
            s[t][0] += x0 + y0;
            s[t][1] += x1 + y1;
            sq[t][0] += x0 * x0 + y0 * y0;
            sq[t][1] += x1 * x1 + y1 * y1;
        }
    }

#pragma unroll
    for (int t = 0; t < 2; t++)
#pragma unroll
        for (int r = 0; r < 2; r++) {
            s[t][r] += __shfl_xor_sync(0xffffffffu, s[t][r], 1);
            s[t][r] += __shfl_xor_sync(0xffffffffu, s[t][r], 2);
            sq[t][r] += __shfl_xor_sync(0xffffffffu, sq[t][r], 1);
            sq[t][r] += __shfl_xor_sync(0xffffffffu, sq[t][r], 2);
        }

    float* red = (float*)smu;
    if (qc == 0) {
#pragma unroll
        for (int t = 0; t < 2; t++) {
            int lr0 = warp_m + t * 16 + qr;
            red[lr0 * 4 + wn] = s[t][0];
            red[(lr0 + 8) * 4 + wn] = s[t][1];
            red[256 + lr0 * 4 + wn] = sq[t][0];
            red[256 + (lr0 + 8) * 4 + wn] = sq[t][1];
        }
    }
    __syncthreads();

#pragma unroll
    for (int t = 0; t < 2; t++) {
        int lr0 = warp_m + t * 16 + qr;
        int lr1 = lr0 + 8;
        float ts0 = red[lr0 * 4 + 0] + red[lr0 * 4 + 1] + red[lr0 * 4 + 2] + red[lr0 * 4 + 3];
        float ts1 = red[lr1 * 4 + 0] + red[lr1 * 4 + 1] + red[lr1 * 4 + 2] + red[lr1 * 4 + 3];
        float tq0 = red[256 + lr0 * 4 + 0] + red[256 + lr0 * 4 + 1] +
                    red[256 + lr0 * 4 + 2] + red[256 + lr0 * 4 + 3];
        float tq1 = red[256 + lr1 * 4 + 0] + red[256 + lr1 * 4 + 1] +
                    red[256 + lr1 * 4 + 2] + red[256 + lr1 * 4 + 3];
        float mu0 = ts0 * (1.f / 256.f);
        float mu1 = ts1 * (1.f / 256.f);
        float var0 = fmaxf(tq0 * (1.f / 256.f) - mu0 * mu0, 0.f);
        float var1 = fmaxf(tq1 * (1.f / 256.f) - mu1 * mu1, 0.f);
        float iv0 = rsqrtf(var0 + 1e-5f);
        float iv1 = rsqrtf(var1 + 1e-5f);
        int g0 = bm + lr0, g1 = bm + lr1;
#pragma unroll
        for (int j = 0; j < 8; j++) {
            int col = warp_n + j * 8 + 2 * qc;
            float2 gg = *(const float2*)&lng[col];
            float2 bb = *(const float2*)&lnb[col];
            if (g0 < M) {
                float2 r;
                r.x = (acc[t][j][0] - mu0) * iv0 * gg.x + bb.x;
                r.y = (acc[t][j][1] - mu0) * iv0 * gg.y + bb.y;
                *(float2*)&out[(size_t)g0 * 256 + col] = r;
            }
            if (g1 < M) {
                float2 r;
                r.x = (acc[t][j][2] - mu1) * iv1 * gg.x + bb.x;
                r.y = (acc[t][j][3] - mu1) * iv1 * gg.y + bb.y;
                *(float2*)&out[(size_t)g1 * 256 + col] = r;
            }
        }
    }
}

// ---------------- weight prep (emits packed half2 [kpair][n]) ----------------
__global__ __launch_bounds__(256) void prep_combine_k(
    const float* __restrict__ Wk, const float* __restrict__ bk,
    const float* __restrict__ Wv, const float* __restrict__ bv,
    const float* __restrict__ attw, const float* __restrict__ valw,
    unsigned* __restrict__ WuA, unsigned* __restrict__ WuP,
    float* __restrict__ bcatA, float* __restrict__ bcatP)
{
    __shared__ float s_hw[32 * 32];
    const int h = blockIdx.x;
    const int slot = blockIdx.y;
    const int tid = threadIdx.x;

    const bool srcA = (slot < 2);
    const bool isV = (slot & 1);
    const int et = (slot < 2) ? 0 : ((slot < 4) ? 1 : 2);

    const float* Wsrc = (isV ? Wv : Wk) + (srcA ? 0 : 65536);
    const float* bsrc = (isV ? bv : bk) + (srcA ? 0 : 256);
    const float* hw = (isV ? valw : attw) + et * 8192 + h * 1024;
    unsigned* Wout = srcA ? WuA : WuP;
    float* bout = srcA ? bcatA : bcatP;
    const int ldn = srcA ? LDA_A : LDA_P;
    const int colbase = 256 + (isV ? 256 : 0) + ((slot >= 4) ? 512 : 0);

#pragma unroll
    for (int i = tid; i < 1024; i += 256) s_hw[i] = hw[i];
    __syncthreads();

    const int d = tid;  // input dim k
    float wrow[32];
#pragma unroll
    for (int d2 = 0; d2 < 32; d2++) wrow[d2] = Wsrc[(size_t)d * 256 + h * 32 + d2];
#pragma unroll
    for (int j = 0; j < 32; j++) {
        float acc = 0.f;
#pragma unroll
        for (int d2 = 0; d2 < 32; d2++) acc += wrow[d2] * s_hw[d2 * 32 + j];
        // pair rows (2m, 2m+1) across adjacent lanes; even lane writes half2
        float up = __shfl_down_sync(0xffffffffu, acc, 1);
        if (!(d & 1))
            Wout[(size_t)(d >> 1) * ldn + colbase + h * 32 + j] = f2h2(acc, up);
    }
    if (tid < 32) {
        float acc = 0.f;
#pragma unroll
        for (int d2 = 0; d2 < 32; d2++) acc += bsrc[h * 32 + d2] * s_hw[d2 * 32 + tid];
        bout[colbase + h * 32 + tid] = acc;
    }
}

__global__ void copyq_k(const float* __restrict__ Wq, const float* __restrict__ bq,
                        unsigned* __restrict__ WuA, unsigned* __restrict__ WuP,
                        float* __restrict__ bcatA, float* __restrict__ bcatP)
{
    int gid = blockIdx.x * blockDim.x + threadIdx.x;
    for (int i = gid; i < 32768; i += gridDim.x * blockDim.x) {
        int kp = i >> 8, c = i & 255;
        WuA[(size_t)kp * LDA_A + c] = f2h2(Wq[(2 * kp) * 256 + c], Wq[(2 * kp + 1) * 256 + c]);
        WuP[(size_t)kp * LDA_P + c] = f2h2(Wq[65536 + (2 * kp) * 256 + c],
                                           Wq[65536 + (2 * kp + 1) * 256 + c]);
    }
    if (gid < 256) {
        bcatA[gid] = bq[gid];
        bcatP[gid] = bq[256 + gid];
    }
}

// ---------------- batched CSR build ----------------
__global__ void zero3_k(int* __restrict__ c0, int* __restrict__ c1, int* __restrict__ c2)
{
    int i = blockIdx.x * blockDim.x + threadIdx.x;
    if (i < NP_N) { c0[i] = 0; c1[i] = 0; }
    if (i < NA_N) c2[i] = 0;
}

__global__ void hist3_k(const int* __restrict__ d0, const int* __restrict__ d1,
                        const int* __restrict__ d2,
                        int* __restrict__ c0, int* __restrict__ c1, int* __restrict__ c2)
{
    int g = blockIdx.y;
    int i = blockIdx.x * blockDim.x + threadIdx.x;
    if (i >= E_N) return;
    const int* d = (g == 0) ? d0 : ((g == 1) ? d1 : d2);
    int* c = (g == 0) ? c0 : ((g == 1) ? c1 : c2);
    atomicAdd(&c[d[i]], 1);
}

__global__ __launch_bounds__(1024) void scan3_k(
    const int* __restrict__ cw, const int* __restrict__ cc, const int* __restrict__ ca,
    int* __restrict__ ow, int* __restrict__ oc, int* __restrict__ oa,
    int* __restrict__ uw, int* __restrict__ uc, int* __restrict__ ua)
{
    __shared__ int sh[1024];
    const int* cnt; int* off; int* cur; int n;
    if (blockIdx.x == 0) { cnt = cw; off = ow; cur = uw; n = NP_N; }
    else if (blockIdx.x == 1) { cnt = cc; off = oc; cur = uc; n = NP_N; }
    else { cnt = ca; off = oa; cur = ua; n = NA_N; }

    int t = threadIdx.x;
    int chunk = (n + 1023) >> 10;
    int s0 = t * chunk;
    int s1 = min(s0 + chunk, n);
    int sum = 0;
    for (int i = s0; i < s1; i++) sum += cnt[i];
    sh[t] = sum;
    __syncthreads();
    for (int d = 1; d < 1024; d <<= 1) {
        int v = 0;
        if (t >= d) v = sh[t - d];
        __syncthreads();
        sh[t] += v;
        __syncthreads();
    }
    int run = sh[t] - sum;
    for (int i = s0; i < s1; i++) {
        off[i] = run;
        cur[i] = run;
        run += cnt[i];
    }
    if (t == 1023) off[n] = sh[1023];
}

__global__ void scatter3_k(
    const int* __restrict__ s0, const int* __restrict__ d0,
    const int* __restrict__ s1, const int* __restrict__ d1,
    const int* __restrict__ s2, const int* __restrict__ d2,
    int* __restrict__ u0, int* __restrict__ u1, int* __restrict__ u2,
    int* __restrict__ p0, int* __restrict__ p1, int* __restrict__ p2)
{
    int g = blockIdx.y;
    int i = blockIdx.x * blockDim.x + threadIdx.x;
    if (i >= E_N) return;
    const int* s = (g == 0) ? s0 : ((g == 1) ? s1 : s2);
    const int* d = (g == 0) ? d0 : ((g == 1) ? d1 : d2);
    int* u = (g == 0) ? u0 : ((g == 1) ? u1 : u2);
    int* p = (g == 0) ? p0 : ((g == 1) ? p1 : p2);
    int pos = atomicAdd(&u[d[i]], 1);
    p[pos] = s[i];
}

// ---------------- aggregation (software-pipelined gather) ----------------
__device__ __forceinline__ void agg_run(
    float4 q0, float4 q1, float cw,
    const float* __restrict__ KB, int ldkv, int koff,
    const int* __restrict__ psrc, int ebeg, int eend, float* o)
{
    float m = -3.0e38f, den = 0.f;
    float a0 = 0, a1 = 0, a2 = 0, a3 = 0, a4 = 0, a5 = 0, a6 = 0, a7 = 0;

    if (ebeg < eend) {
        int src = __ldg(&psrc[ebeg]);
        const float* kp = KB + (size_t)src * ldkv + koff;
        float4 k0 = *(const float4*)kp;
        float4 k1 = *(const float4*)(kp + 4);
        float4 v0 = *(const float4*)(kp + 256);
        float4 v1 = *(const float4*)(kp + 260);

        for (int i = ebeg; ; ) {
            bool more = (i + 1 < eend);
            float4 nk0, nk1, nv0, nv1;
            if (more) {
                int nsrc = __ldg(&psrc[i + 1]);
                const float* np = KB + (size_t)nsrc * ldkv + koff;
                nk0 = *(const float4*)np;
                nk1 = *(const float4*)(np + 4);
                nv0 = *(const float4*)(np + 256);
                nv1 = *(const float4*)(np + 260);
            }

            float p = q0.x * k0.x + q0.y * k0.y + q0.z * k0.z + q0.w * k0.w +
                      q1.x * k1.x + q1.y * k1.y + q1.z * k1.z + q1.w * k1.w;
            p += __shfl_xor_sync(0xffffffffu, p, 1);
            p += __shfl_xor_sync(0xffffffffu, p, 2);
            float sc = p * cw;
            float mn = fmaxf(m, sc);
            float corr = __expf(m - mn);
            float w = __expf(sc - mn);
            m = mn;
            den = den * corr + w;
            a0 = a0 * corr + w * v0.x;
            a1 = a1 * corr + w * v0.y;
            a2 = a2 * corr + w * v0.z;
            a3 = a3 * corr + w * v0.w;
            a4 = a4 * corr + w * v1.x;
            a5 = a5 * corr + w * v1.y;
            a6 = a6 * corr + w * v1.z;
            a7 = a7 * corr + w * v1.w;

            if (!more) break;
            k0 = nk0; k1 = nk1; v0 = nv0; v1 = nv1;
            i++;
        }
    }
    float r = (den > 0.f) ? (1.f / den) : 0.f;
    o[0] = a0 * r; o[1] = a1 * r; o[2] = a2 * r; o[3] = a3 * r;
    o[4] = a4 * r; o[5] = a5 * r; o[6] = a6 * r; o[7] = a7 * r;
}

__global__ __launch_bounds__(256) void agg_paper_k(
    const float* __restrict__ PP, const float* __restrict__ AP,
    const int* __restrict__ offw, const int* __restrict__ pw,
    const int* __restrict__ offc, const int* __restrict__ pc,
    const float* __restrict__ canon, float* __restrict__ OUT, int n)
{
    int gw = (blockIdx.x * blockDim.x + threadIdx.x) >> 5;
    if (gw >= n) return;
    int lane = threadIdx.x & 31;
    int h = lane >> 2;
    int seg = (lane & 3) << 3;
    int hs = h * 32 + seg;
    const float* qp = PP + (size_t)gw * LDA_P + hs;
    float4 q0 = *(const float4*)qp;
    float4 q1 = *(const float4*)(qp + 4);
    const float inv = 0.17677669529663687f;

    float ow[8], oc[8];
    agg_run(q0, q1, __ldg(&canon[h]) * inv, AP, LDA_A, 256 + hs,
            pw, __ldg(&offw[gw]), __ldg(&offw[gw + 1]), ow);
    agg_run(q0, q1, __ldg(&canon[16 + h]) * inv, PP, LDA_P, 768 + hs,
            pc, __ldg(&offc[gw]), __ldg(&offc[gw + 1]), oc);

    float* op = OUT + (size_t)gw * 256 + hs;
    *(float4*)op = make_float4(0.5f * (ow[0] + oc[0]), 0.5f * (ow[1] + oc[1]),
                               0.5f * (ow[2] + oc[2]), 0.5f * (ow[3] + oc[3]));
    *(float4*)(op + 4) = make_float4(0.5f * (ow[4] + oc[4]), 0.5f * (ow[5] + oc[5]),
                                     0.5f * (ow[6] + oc[6]), 0.5f * (ow[7] + oc[7]));
}

__global__ __launch_bounds__(256) void agg_author_k(
    const float* __restrict__ AP, const float* __restrict__ PP,
    const int* __restrict__ offa, const int* __restrict__ pa,
    const float* __restrict__ canon, float* __restrict__ OUT, int n)
{
    int gw = (blockIdx.x * blockDim.x + threadIdx.x) >> 5;
    if (gw >= n) return;
    int lane = threadIdx.x & 31;
    int h = lane >> 2;
    int seg = (lane & 3) << 3;
    int hs = h * 32 + seg;
    const float* qp = AP + (size_t)gw * LDA_A + hs;
    float4 q0 = *(const float4*)qp;
    float4 q1 = *(const float4*)(qp + 4);
    const float inv = 0.17677669529663687f;

    float o[8];
    agg_run(q0, q1, __ldg(&canon[8 + h]) * inv, PP, LDA_P, 256 + hs,
            pa, __ldg(&offa[gw]), __ldg(&offa[gw + 1]), o);

    float* op = OUT + (size_t)gw * 256 + hs;
    *(float4*)op = make_float4(o[0], o[1], o[2], o[3]);
    *(float4*)(op + 4) = make_float4(o[4], o[5], o[6], o[7]);
}

// ---------------- host orchestration ----------------
extern "C" void kernel_launch(void* const* d_in, const int* in_sizes, int n_in,
                              void* d_out, int out_size)
{
    const float* h_a  = (const float*)d_in[0];
    const float* h_p  = (const float*)d_in[1];
    const int* wsrc   = (const int*)d_in[2];
    const int* wdst   = (const int*)d_in[3];
    const int* wbsrc  = (const int*)d_in[4];
    const int* wbdst  = (const int*)d_in[5];
    const int* csrc   = (const int*)d_in[6];
    const int* cdst   = (const int*)d_in[7];
    const float* Wk   = (const float*)d_in[8];
    const float* bk   = (const float*)d_in[9];
    const float* Wq   = (const float*)d_in[10];
    const float* bq   = (const float*)d_in[11];
    const float* Wv   = (const float*)d_in[12];
    const float* bv   = (const float*)d_in[13];
    const float* Wfc  = (const float*)d_in[14];
    const float* bfc  = (const float*)d_in[15];
    const float* lng  = (const float*)d_in[16];
    const float* lnb  = (const float*)d_in[17];
    const float* attw = (const float*)d_in[18];
    const float* valw = (const float*)d_in[19];
    const float* canon= (const float*)d_in[20];
    const float* res  = (const float*)d_in[21];
    float* out = (float*)d_out;

    float *AP, *PP, *AGA, *AGP, *bcA, *bcP;
    unsigned *Ah, *Ph, *WuA, *WuP;
    int *cw, *cc, *ca, *ow_, *oc_, *oa_, *uw, *uc, *ua, *pw, *pc, *pa;
    cudaGetSymbolAddress((void**)&AP, g_APROJ);
    cudaGetSymbolAddress((void**)&PP, g_PPROJ);
    cudaGetSymbolAddress((void**)&AGA, g_AGA);
    cudaGetSymbolAddress((void**)&AGP, g_AGP);
    cudaGetSymbolAddress((void**)&Ah, g_Ah);
    cudaGetSymbolAddress((void**)&Ph, g_Ph);
    cudaGetSymbolAddress((void**)&WuA, g_WuA);
    cudaGetSymbolAddress((void**)&WuP, g_WuP);
    cudaGetSymbolAddress((void**)&bcA, g_bcatA);
    cudaGetSymbolAddress((void**)&bcP, g_bcatP);
    cudaGetSymbolAddress((void**)&cw, g_cnt_w);
    cudaGetSymbolAddress((void**)&cc, g_cnt_c);
    cudaGetSymbolAddress((void**)&ca, g_cnt_a);
    cudaGetSymbolAddress((void**)&ow_, g_off_w);
    cudaGetSymbolAddress((void**)&oc_, g_off_c);
    cudaGetSymbolAddress((void**)&oa_, g_off_a);
    cudaGetSymbolAddress((void**)&uw, g_cur_w);
    cudaGetSymbolAddress((void**)&uc, g_cur_c);
    cudaGetSymbolAddress((void**)&ua, g_cur_a);
    cudaGetSymbolAddress((void**)&pw, g_psrc_w);
    cudaGetSymbolAddress((void**)&pc, g_psrc_c);
    cudaGetSymbolAddress((void**)&pa, g_psrc_a);

    cudaFuncSetAttribute(mma_gemm_k, cudaFuncAttributeMaxDynamicSharedMemorySize, GEMM_SMEM_BYTES);
    cudaFuncSetAttribute(fc_ln_k, cudaFuncAttributeMaxDynamicSharedMemorySize, FC_SMEM_BYTES);

    const int MB = (NA_N + 127) / 128;   // 782
    const int MB64 = (NA_N + 63) / 64;   // 1563
    const int gwA = (NA_N + 7) / 8, gwP = (NP_N + 7) / 8;
    const dim3 gEdge((E_N + 255) / 256, 3);

    // 1-3: prep (half-packed weights + inputs)
    prep_combine_k<<<dim3(8, 6), 256>>>(Wk, bk, Wv, bv, attw, valw, WuA, WuP, bcA, bcP);
    copyq_k<<<128, 256>>>(Wq, bq, WuA, WuP, bcA, bcP);
    tohalf_k<<<4096, 256>>>(h_a, h_p, Ah, Ph);

    // 4-5: projections (launch #4 lands in the ncu capture slot)
    mma_gemm_k<<<dim3(LDA_A / 128, MB), 256, GEMM_SMEM_BYTES>>>(Ah, WuA, bcA, AP, NA_N, LDA_A);
    mma_gemm_k<<<dim3(LDA_P / 128, MB), 256, GEMM_SMEM_BYTES>>>(Ph, WuP, bcP, PP, NP_N, LDA_P);

    // 6-9: CSR build
    zero3_k<<<(NP_N + 255) / 256, 256>>>(cw, cc, ca);
    hist3_k<<<gEdge, 256>>>(wdst, cdst, wbdst, cw, cc, ca);
    scan3_k<<<3, 1024>>>(cw, cc, ca, ow_, oc_, oa_, uw, uc, ua);
    scatter3_k<<<gEdge, 256>>>(wsrc, wdst, csrc, cdst, wbsrc, wbdst, uw, uc, ua, pw, pc, pa);

    // 10-11: aggregations
    agg_paper_k<<<gwP, 256>>>(PP, AP, ow_, pw, oc_, pc, canon, AGP, NP_N);
    agg_author_k<<<gwA, 256>>>(AP, PP, oa_, pa, canon, AGA, NA_N);

    // 12-13: fc + residual blend + LN -> output
    fc_ln_k<<<dim3(1, MB64), 256, FC_SMEM_BYTES>>>(
        AGA, Wfc + 0, bfc + 0, h_a, res + 0, lng + 0, lnb + 0, out, NA_N);
    fc_ln_k<<<dim3(1, MB64), 256, FC_SMEM_BYTES>>>(
        AGP, Wfc + 65536, bfc + 256, h_p, res + 1, lng + 256, lnb + 256,
        out + (size_t)NA_N * D_, NP_N);
}